// round 3
// baseline (speedup 1.0000x reference)
#include <cuda_runtime.h>
#include <cuda_bf16.h>
#include <float.h>
#include <stdint.h>

#define NPTS   65536
#define BGRAPH 64
#define PPG    1024

// ---------------- scratch (device globals; no allocation) ----------------
__device__ int   g_knn[NPTS * 8];            // 6 real + 2 pad (dup of nn0)
__device__ float g_ab [NPTS * 128];          // a (+b1 folded) cols 0..63, b cols 64..127
__device__ float g_h1 [NPTS * 64];
__device__ float g_h2 [NPTS * 64];
__device__ __align__(16) __nv_bfloat16 g_w2s[3][2][4096];  // [layer][hi/lo] swizzled W2^T [n][k]

// ---------------- helpers (base-ISA only: ldmatrix + mma.sync, sm_80+) ----------------
__device__ __forceinline__ uint32_t smem_u32(const void* p) {
    uint32_t a;
    asm("{ .reg .u64 t; cvta.to.shared.u64 t, %1; cvt.u32.u64 %0, t; }" : "=r"(a) : "l"(p));
    return a;
}
__device__ __forceinline__ uint32_t sw128(uint32_t off) { return off ^ ((off >> 3) & 0x70); }
__device__ __forceinline__ uint32_t pack_bf(__nv_bfloat16 a, __nv_bfloat16 b) {
    uint16_t ua = __bfloat16_as_ushort(a), ub = __bfloat16_as_ushort(b);
    return (uint32_t)ua | ((uint32_t)ub << 16);
}
__device__ __forceinline__ void ldsm_x4(uint32_t* r, uint32_t addr) {
    asm volatile("ldmatrix.sync.aligned.m8n8.x4.shared.b16 {%0,%1,%2,%3}, [%4];"
                 : "=r"(r[0]), "=r"(r[1]), "=r"(r[2]), "=r"(r[3]) : "r"(addr));
}
__device__ __forceinline__ void ldsm_x2(uint32_t* r, uint32_t addr) {
    asm volatile("ldmatrix.sync.aligned.m8n8.x2.shared.b16 {%0,%1}, [%2];"
                 : "=r"(r[0]), "=r"(r[1]) : "r"(addr));
}
__device__ __forceinline__ void mma_16816(float* d, const uint32_t* a, const uint32_t* b) {
    asm volatile("mma.sync.aligned.m16n8k16.row.col.f32.bf16.bf16.f32 "
                 "{%0,%1,%2,%3}, {%4,%5,%6,%7}, {%8,%9}, {%0,%1,%2,%3};"
                 : "+f"(d[0]), "+f"(d[1]), "+f"(d[2]), "+f"(d[3])
                 : "r"(a[0]), "r"(a[1]), "r"(a[2]), "r"(a[3]), "r"(b[0]), "r"(b[1]));
}

// ---------------- kNN (k=6, matches jax top_k(-d2, 6) incl. ties) ----------------
__global__ __launch_bounds__(256) void knn_kernel(const float* __restrict__ pos)
{
    __shared__ float4 cand[256];
    int graph = blockIdx.x >> 2;
    int q = graph * PPG + ((blockIdx.x & 3) << 8) + threadIdx.x;
    float qx = pos[3*q], qy = pos[3*q+1], qz = pos[3*q+2];
    float qs = qx*qx + qy*qy + qz*qz;
    float bd[6]; int bi[6];
#pragma unroll
    for (int t = 0; t < 6; t++) { bd[t] = FLT_MAX; bi[t] = 0; }
    for (int tile = 0; tile < PPG; tile += 256) {
        int c = graph * PPG + tile + threadIdx.x;
        float cx = pos[3*c], cy = pos[3*c+1], cz = pos[3*c+2];
        cand[threadIdx.x] = make_float4(cx, cy, cz, cx*cx + cy*cy + cz*cz);
        __syncthreads();
#pragma unroll 4
        for (int u = 0; u < 256; u++) {
            float4 p = cand[u];
            float d2 = qs + p.w - 2.0f*(qx*p.x + qy*p.y + qz*p.z);
            if (d2 < bd[5]) {
                bd[5] = d2; bi[5] = graph*PPG + tile + u;
#pragma unroll
                for (int t = 5; t > 0; t--) {
                    if (bd[t] < bd[t-1]) {
                        float td = bd[t]; bd[t] = bd[t-1]; bd[t-1] = td;
                        int   ti = bi[t]; bi[t] = bi[t-1]; bi[t-1] = ti;
                    }
                }
            }
        }
        __syncthreads();
    }
#pragma unroll
    for (int t = 0; t < 6; t++) g_knn[q*8 + t] = bi[t];
    g_knn[q*8 + 6] = bi[0];   // pad rows duplicate nn0: max unaffected
    g_knn[q*8 + 7] = bi[0];
}

// ---------------- W2^T bf16 split into swizzled B tiles (all 3 layers) ----------------
__global__ __launch_bounds__(128) void w2split_kernel(const float* __restrict__ W2a,
                                                      const float* __restrict__ W2b,
                                                      const float* __restrict__ W2c)
{
    int t = blockIdx.x * 128 + threadIdx.x;        // 3*4096 threads
    int l = t >> 12, nk = t & 4095;
    int n = nk >> 6, k = nk & 63;
    const float* W2 = (l == 0) ? W2a : ((l == 1) ? W2b : W2c);
    float v = W2[k*64 + n];                        // B^T[n][k] = W2[k][n]
    __nv_bfloat16 hi = __float2bfloat16(v);
    __nv_bfloat16 lo = __float2bfloat16(v - __bfloat162float(hi));
    uint32_t sw = sw128((uint32_t)(n*128 + k*2));
    g_w2s[l][0][sw >> 1] = hi;
    g_w2s[l][1][sw >> 1] = lo;
}

// ---------------- per-point a/b projections, layer 1 (Cin=3), b1 folded into a ----------------
__global__ __launch_bounds__(256) void ab3_kernel(const float* __restrict__ pos,
                                                  const float* __restrict__ W1,
                                                  const float* __restrict__ b1)
{
    int idx = blockIdx.x * 256 + threadIdx.x;
    int i = idx >> 6, c = idx & 63;
    float x = pos[3*i], y = pos[3*i+1], z = pos[3*i+2];
    g_ab[i*128 + c]      = fmaf(x, W1[c], fmaf(y, W1[64+c], fmaf(z, W1[128+c], b1[c])));
    g_ab[i*128 + 64 + c] = x*W1[192 + c] + y*W1[256 + c] + z*W1[320 + c];
}

// ---------------- per-point a/b projections, layers 2/3 (Cin=64), transposed smem ----------------
#define AB64_SMEM ((64*68 + 64*128) * 4)
__global__ __launch_bounds__(256) void ab64_kernel(const float* __restrict__ h,
                                                   const float* __restrict__ W1,
                                                   const float* __restrict__ b1)
{
    extern __shared__ float sm[];
    float* hs = sm;            // transposed: hs[k*68 + p]
    float* Ws = sm + 64*68;    // [64][128]
    int tx = threadIdx.x;
    int base = blockIdx.x * 64;
    for (int t = tx; t < 4096; t += 256) {
        int p = t >> 6, c = t & 63;
        hs[c*68 + p] = h[(size_t)base*64 + t];
    }
    for (int t = tx; t < 8192; t += 256) {
        int f = t >> 7, cc = t & 127;
        Ws[t] = (cc < 64) ? W1[f*64 + cc] : W1[(64 + f)*64 + (cc - 64)];
    }
    __syncthreads();
    int p0 = (tx & 7) * 8, c0 = (tx >> 3) * 4;
    float acc[8][4];
#pragma unroll
    for (int i = 0; i < 8; i++)
#pragma unroll
        for (int j = 0; j < 4; j++) acc[i][j] = 0.f;
#pragma unroll 4
    for (int kk = 0; kk < 64; kk++) {
        float4 w  = *(const float4*)&Ws[kk*128 + c0];
        float4 hA = *(const float4*)&hs[kk*68 + p0];
        float4 hB = *(const float4*)&hs[kk*68 + p0 + 4];
        float hv[8] = {hA.x, hA.y, hA.z, hA.w, hB.x, hB.y, hB.z, hB.w};
#pragma unroll
        for (int i = 0; i < 8; i++) {
            acc[i][0] = fmaf(hv[i], w.x, acc[i][0]);
            acc[i][1] = fmaf(hv[i], w.y, acc[i][1]);
            acc[i][2] = fmaf(hv[i], w.z, acc[i][2]);
            acc[i][3] = fmaf(hv[i], w.w, acc[i][3]);
        }
    }
    float4 bb = make_float4(0.f, 0.f, 0.f, 0.f);
    if (c0 < 64) bb = *(const float4*)&b1[c0];
#pragma unroll
    for (int i = 0; i < 8; i++) {
        float4 o = make_float4(acc[i][0] + bb.x, acc[i][1] + bb.y, acc[i][2] + bb.z, acc[i][3] + bb.w);
        *(float4*)&g_ab[(size_t)(base + p0 + i)*128 + c0] = o;
    }
}

// ---------------- edge layer: fp32 hidden -> bf16-split -> mma.sync -> max_k -> relu ----------------
// 32 points/block, k padded to 8 (dup nn0) -> 256 edge rows; warp owns 64 rows (4 m16 tiles).
// 3-pass bf16 split GEMM: Ahi*Bhi + Ahi*Blo + Alo*Bhi (residual ~2^-17).
#define EDGE_SMEM (32768*2 + 8192*2 + 256)
template<int K>
__global__ __launch_bounds__(128) void edge_mma_kernel(
    const float* __restrict__ pos,
    const float* __restrict__ W1rel,   // [3][64] rel rows of W1
    const float* __restrict__ b2,
    int layer,
    float* __restrict__ hout)
{
    extern __shared__ char smem_raw[];
    uint32_t su = smem_u32(smem_raw);
    uint32_t abase = (su + 127) & ~127u;
    char* base = smem_raw + (abase - su);
    char* AhiC = base;                   // 256 rows x 128B (bf16 x64)
    char* AloC = base + 32768;
    uint32_t sAhi = abase, sAlo = abase + 32768;
    uint32_t sBhi = abase + 65536, sBlo = abase + 65536 + 8192;

    int tid = threadIdx.x, warp = tid >> 5, lane = tid & 31;

    // stage pre-swizzled B tiles
    {
        const uint4* sh = (const uint4*)g_w2s[layer][0];
        const uint4* sl = (const uint4*)g_w2s[layer][1];
        uint4* dh = (uint4*)(base + 65536);
        uint4* dl = (uint4*)(base + 65536 + 8192);
        for (int t = tid; t < 512; t += 128) { dh[t] = sh[t]; dl[t] = sl[t]; }
    }

    // phase A: hidden rows 2*tid, 2*tid+1 (same point), bf16-split into A tiles
    {
        int r0 = tid * 2;
        int i = blockIdx.x * 32 + (r0 >> 3);
        float pix = pos[3*i], piy = pos[3*i+1], piz = pos[3*i+2];
#pragma unroll
        for (int rr = 0; rr < 2; rr++) {
            int row = r0 + rr;
            int slot = row & 7;
            int j = g_knn[i*8 + (slot < K ? slot : 0)];
            float rx = pos[3*j]   - pix;
            float ry = pos[3*j+1] - piy;
            float rz = pos[3*j+2] - piz;
#pragma unroll
            for (int c4 = 0; c4 < 16; c4++) {
                float4 a  = *(const float4*)&g_ab[(size_t)i*128 + c4*4];
                float4 b  = *(const float4*)&g_ab[(size_t)j*128 + 64 + c4*4];
                float4 u0 = *(const float4*)&W1rel[c4*4];
                float4 u1 = *(const float4*)&W1rel[64 + c4*4];
                float4 u2 = *(const float4*)&W1rel[128 + c4*4];
                float h0 = fmaxf(fmaf(rx, u0.x, fmaf(ry, u1.x, fmaf(rz, u2.x, a.x + b.x))), 0.f);
                float h1 = fmaxf(fmaf(rx, u0.y, fmaf(ry, u1.y, fmaf(rz, u2.y, a.y + b.y))), 0.f);
                float h2 = fmaxf(fmaf(rx, u0.z, fmaf(ry, u1.z, fmaf(rz, u2.z, a.z + b.z))), 0.f);
                float h3 = fmaxf(fmaf(rx, u0.w, fmaf(ry, u1.w, fmaf(rz, u2.w, a.w + b.w))), 0.f);
                __nv_bfloat16 q0 = __float2bfloat16(h0), q1 = __float2bfloat16(h1);
                __nv_bfloat16 q2 = __float2bfloat16(h2), q3 = __float2bfloat16(h3);
                __nv_bfloat16 s0 = __float2bfloat16(h0 - __bfloat162float(q0));
                __nv_bfloat16 s1 = __float2bfloat16(h1 - __bfloat162float(q1));
                __nv_bfloat16 s2 = __float2bfloat16(h2 - __bfloat162float(q2));
                __nv_bfloat16 s3 = __float2bfloat16(h3 - __bfloat162float(q3));
                uint32_t sw = sw128((uint32_t)(row*128 + c4*8));
                *(uint2*)(AhiC + sw) = make_uint2(pack_bf(q0, q1), pack_bf(q2, q3));
                *(uint2*)(AloC + sw) = make_uint2(pack_bf(s0, s1), pack_bf(s2, s3));
            }
        }
    }
    __syncthreads();

    // phase B: per warp, 4 row-tiles of m16 x n64 x k64, 3 passes
    const int rowbase = warp * 64;
    int arow = rowbase + (lane & 15);
    int acolb = (lane >> 4) * 16;
    int brow = (lane & 7) * 128;
    int bcolb = ((lane >> 3) & 1) * 16;

#pragma unroll
    for (int rt = 0; rt < 4; rt++) {
        float d[8][4];
#pragma unroll
        for (int n = 0; n < 8; n++)
#pragma unroll
            for (int q = 0; q < 4; q++) d[n][q] = 0.f;

        uint32_t afr[4][4];
        uint32_t arow_off = (uint32_t)((arow + rt*16) * 128);
#pragma unroll
        for (int k = 0; k < 4; k++)
            ldsm_x4(afr[k], sAhi + sw128(arow_off + k*32 + acolb));

        // pass 1: Ahi x Bhi
#pragma unroll
        for (int n = 0; n < 8; n++)
#pragma unroll
            for (int k = 0; k < 4; k++) {
                uint32_t bf[2];
                ldsm_x2(bf, sBhi + sw128((uint32_t)(n*1024 + brow + k*32 + bcolb)));
                mma_16816(d[n], afr[k], bf);
            }
        // pass 2: Ahi x Blo
#pragma unroll
        for (int n = 0; n < 8; n++)
#pragma unroll
            for (int k = 0; k < 4; k++) {
                uint32_t bf[2];
                ldsm_x2(bf, sBlo + sw128((uint32_t)(n*1024 + brow + k*32 + bcolb)));
                mma_16816(d[n], afr[k], bf);
            }
        // pass 3: Alo x Bhi
#pragma unroll
        for (int k = 0; k < 4; k++)
            ldsm_x4(afr[k], sAlo + sw128(arow_off + k*32 + acolb));
#pragma unroll
        for (int n = 0; n < 8; n++)
#pragma unroll
            for (int k = 0; k < 4; k++) {
                uint32_t bf[2];
                ldsm_x2(bf, sBhi + sw128((uint32_t)(n*1024 + brow + k*32 + bcolb)));
                mma_16816(d[n], afr[k], bf);
            }

        // epilogue: rows 0-7 = point A slots, rows 8-15 = point B slots
        int pA = blockIdx.x*32 + warp*8 + rt*2;
        int pB = pA + 1;
#pragma unroll
        for (int n = 0; n < 8; n++) {
            float m0 = d[n][0], m1 = d[n][1], m2 = d[n][2], m3 = d[n][3];
#pragma unroll
            for (int s = 4; s <= 16; s <<= 1) {
                m0 = fmaxf(m0, __shfl_xor_sync(0xffffffffu, m0, s));
                m1 = fmaxf(m1, __shfl_xor_sync(0xffffffffu, m1, s));
                m2 = fmaxf(m2, __shfl_xor_sync(0xffffffffu, m2, s));
                m3 = fmaxf(m3, __shfl_xor_sync(0xffffffffu, m3, s));
            }
            if (lane < 4) {
                int col = n*8 + lane*2;
                float2 o = make_float2(fmaxf(m0 + b2[col], 0.f), fmaxf(m1 + b2[col+1], 0.f));
                *(float2*)&hout[(size_t)pA*64 + col] = o;
            } else if (lane < 8) {
                int col = n*8 + (lane-4)*2;
                float2 o = make_float2(fmaxf(m2 + b2[col], 0.f), fmaxf(m3 + b2[col+1], 0.f));
                *(float2*)&hout[(size_t)pB*64 + col] = o;
            }
        }
    }
}

// ---------------- global max pool + regression head ----------------
__global__ __launch_bounds__(256) void pool_kernel(const float* __restrict__ h,
                                                   const float* __restrict__ regW,
                                                   const float* __restrict__ regb,
                                                   float* __restrict__ out)
{
    __shared__ float red[4][64];
    int g = blockIdx.x;
    int c = threadIdx.x & 63, s = threadIdx.x >> 6;
    const float* hb = h + (size_t)g * PPG * 64;
    float m = -FLT_MAX;
    for (int p = s; p < PPG; p += 4) m = fmaxf(m, hb[p*64 + c]);
    red[s][c] = m;
    __syncthreads();
    if (threadIdx.x < 64)
        red[0][c] = fmaxf(fmaxf(red[0][c], red[1][c]), fmaxf(red[2][c], red[3][c]));
    __syncthreads();
    if (threadIdx.x < 6) {
        float acc = regb[threadIdx.x];
#pragma unroll
        for (int cc = 0; cc < 64; cc++)
            acc = fmaf(red[0][cc], regW[cc*6 + threadIdx.x], acc);
        out[g*6 + threadIdx.x] = acc;
    }
}

// ---------------- launch ----------------
extern "C" void kernel_launch(void* const* d_in, const int* in_sizes, int n_in,
                              void* d_out, int out_size)
{
    (void)in_sizes; (void)n_in; (void)out_size;
    const float* pos  = (const float*)d_in[1];
    const float* c1W1 = (const float*)d_in[3];
    const float* c1b1 = (const float*)d_in[4];
    const float* c1W2 = (const float*)d_in[5];
    const float* c1b2 = (const float*)d_in[6];
    const float* c2W1 = (const float*)d_in[7];
    const float* c2b1 = (const float*)d_in[8];
    const float* c2W2 = (const float*)d_in[9];
    const float* c2b2 = (const float*)d_in[10];
    const float* c3W1 = (const float*)d_in[11];
    const float* c3b1 = (const float*)d_in[12];
    const float* c3W2 = (const float*)d_in[13];
    const float* c3b2 = (const float*)d_in[14];
    const float* regW = (const float*)d_in[15];
    const float* regb = (const float*)d_in[16];
    float* out = (float*)d_out;

    float *h1, *h2;
    cudaGetSymbolAddress((void**)&h1, g_h1);
    cudaGetSymbolAddress((void**)&h2, g_h2);
    cudaFuncSetAttribute(ab64_kernel, cudaFuncAttributeMaxDynamicSharedMemorySize, AB64_SMEM);
    cudaFuncSetAttribute(edge_mma_kernel<6>, cudaFuncAttributeMaxDynamicSharedMemorySize, EDGE_SMEM);
    cudaFuncSetAttribute(edge_mma_kernel<4>, cudaFuncAttributeMaxDynamicSharedMemorySize, EDGE_SMEM);
    cudaFuncSetAttribute(edge_mma_kernel<3>, cudaFuncAttributeMaxDynamicSharedMemorySize, EDGE_SMEM);

    knn_kernel<<<BGRAPH * 4, 256>>>(pos);
    w2split_kernel<<<96, 128>>>(c1W2, c2W2, c3W2);
    ab3_kernel<<<NPTS * 64 / 256, 256>>>(pos, c1W1, c1b1);
    edge_mma_kernel<6><<<NPTS/32, 128, EDGE_SMEM>>>(pos, c1W1 + 6*64,   c1b2, 0, h1);
    ab64_kernel<<<NPTS/64, 256, AB64_SMEM>>>(h1, c2W1, c2b1);
    edge_mma_kernel<4><<<NPTS/32, 128, EDGE_SMEM>>>(pos, c2W1 + 128*64, c2b2, 1, h2);
    ab64_kernel<<<NPTS/64, 256, AB64_SMEM>>>(h2, c3W1, c3b1);
    edge_mma_kernel<3><<<NPTS/32, 128, EDGE_SMEM>>>(pos, c3W1 + 128*64, c3b2, 2, h1);
    pool_kernel<<<BGRAPH, 256>>>(h1, regW, regb, out);
}

// round 5
// speedup vs baseline: 1.3995x; 1.3995x over previous
#include <cuda_runtime.h>
#include <cuda_bf16.h>
#include <float.h>
#include <stdint.h>

#define NPTS   65536
#define BGRAPH 64
#define PPG    1024

// ---------------- scratch (device globals; no allocation) ----------------
__device__ int   g_knn[NPTS * 8];            // 6 real + 2 pad (dup of nn0)
__device__ float g_ab [NPTS * 128];          // a (+b1 folded) cols 0..63, b cols 64..127
__device__ float g_h1 [NPTS * 64];
__device__ float g_h2 [NPTS * 64];
__device__ __align__(16) __nv_bfloat16 g_w2s[3][2][4096];  // [layer][hi/lo] swizzled W2^T [n][k]

// ---------------- helpers (base-ISA: ldmatrix + mma.sync, sm_80+) ----------------
__device__ __forceinline__ uint32_t smem_u32(const void* p) {
    uint32_t a;
    asm("{ .reg .u64 t; cvta.to.shared.u64 t, %1; cvt.u32.u64 %0, t; }" : "=r"(a) : "l"(p));
    return a;
}
__device__ __forceinline__ uint32_t sw128(uint32_t off) { return off ^ ((off >> 3) & 0x70); }
__device__ __forceinline__ uint32_t pack_bf(__nv_bfloat16 a, __nv_bfloat16 b) {
    uint16_t ua = __bfloat16_as_ushort(a), ub = __bfloat16_as_ushort(b);
    return (uint32_t)ua | ((uint32_t)ub << 16);
}
__device__ __forceinline__ void ldsm_x4(uint32_t* r, uint32_t addr) {
    asm volatile("ldmatrix.sync.aligned.m8n8.x4.shared.b16 {%0,%1,%2,%3}, [%4];"
                 : "=r"(r[0]), "=r"(r[1]), "=r"(r[2]), "=r"(r[3]) : "r"(addr));
}
__device__ __forceinline__ void ldsm_x2(uint32_t* r, uint32_t addr) {
    asm volatile("ldmatrix.sync.aligned.m8n8.x2.shared.b16 {%0,%1}, [%2];"
                 : "=r"(r[0]), "=r"(r[1]) : "r"(addr));
}
__device__ __forceinline__ void mma_16816(float* d, const uint32_t* a, const uint32_t* b) {
    asm volatile("mma.sync.aligned.m16n8k16.row.col.f32.bf16.bf16.f32 "
                 "{%0,%1,%2,%3}, {%4,%5,%6,%7}, {%8,%9}, {%0,%1,%2,%3};"
                 : "+f"(d[0]), "+f"(d[1]), "+f"(d[2]), "+f"(d[3])
                 : "r"(a[0]), "r"(a[1]), "r"(a[2]), "r"(a[3]), "r"(b[0]), "r"(b[1]));
}

// ---------------- kNN (k=6, matches jax top_k(-d2, 6) incl. ties) ----------------
__global__ __launch_bounds__(256) void knn_kernel(const float* __restrict__ pos)
{
    __shared__ float4 cand[256];
    int graph = blockIdx.x >> 2;
    int q = graph * PPG + ((blockIdx.x & 3) << 8) + threadIdx.x;
    float qx = pos[3*q], qy = pos[3*q+1], qz = pos[3*q+2];
    float qs = qx*qx + qy*qy + qz*qz;
    float bd[6]; int bi[6];
#pragma unroll
    for (int t = 0; t < 6; t++) { bd[t] = FLT_MAX; bi[t] = 0; }
    for (int tile = 0; tile < PPG; tile += 256) {
        int c = graph * PPG + tile + threadIdx.x;
        float cx = pos[3*c], cy = pos[3*c+1], cz = pos[3*c+2];
        cand[threadIdx.x] = make_float4(cx, cy, cz, cx*cx + cy*cy + cz*cz);
        __syncthreads();
#pragma unroll 4
        for (int u = 0; u < 256; u++) {
            float4 p = cand[u];
            float d2 = qs + p.w - 2.0f*(qx*p.x + qy*p.y + qz*p.z);
            if (d2 < bd[5]) {
                bd[5] = d2; bi[5] = graph*PPG + tile + u;
#pragma unroll
                for (int t = 5; t > 0; t--) {
                    if (bd[t] < bd[t-1]) {
                        float td = bd[t]; bd[t] = bd[t-1]; bd[t-1] = td;
                        int   ti = bi[t]; bi[t] = bi[t-1]; bi[t-1] = ti;
                    }
                }
            }
        }
        __syncthreads();
    }
#pragma unroll
    for (int t = 0; t < 6; t++) g_knn[q*8 + t] = bi[t];
    g_knn[q*8 + 6] = bi[0];
    g_knn[q*8 + 7] = bi[0];
}

// ---------------- W2^T bf16 split into swizzled B tiles (all 3 layers) ----------------
__global__ __launch_bounds__(128) void w2split_kernel(const float* __restrict__ W2a,
                                                      const float* __restrict__ W2b,
                                                      const float* __restrict__ W2c)
{
    int t = blockIdx.x * 128 + threadIdx.x;        // 3*4096 threads
    int l = t >> 12, nk = t & 4095;
    int n = nk >> 6, k = nk & 63;
    const float* W2 = (l == 0) ? W2a : ((l == 1) ? W2b : W2c);
    float v = W2[k*64 + n];                        // B^T[n][k] = W2[k][n]
    __nv_bfloat16 hi = __float2bfloat16(v);
    __nv_bfloat16 lo = __float2bfloat16(v - __bfloat162float(hi));
    uint32_t sw = sw128((uint32_t)(n*128 + k*2));
    g_w2s[l][0][sw >> 1] = hi;
    g_w2s[l][1][sw >> 1] = lo;
}

// ---------------- per-point a/b projections, layer 1 (Cin=3), b1 folded into a ----------------
__global__ __launch_bounds__(256) void ab3_kernel(const float* __restrict__ pos,
                                                  const float* __restrict__ W1,
                                                  const float* __restrict__ b1)
{
    int idx = blockIdx.x * 256 + threadIdx.x;
    int i = idx >> 6, c = idx & 63;
    float x = pos[3*i], y = pos[3*i+1], z = pos[3*i+2];
    g_ab[i*128 + c]      = fmaf(x, W1[c], fmaf(y, W1[64+c], fmaf(z, W1[128+c], b1[c])));
    g_ab[i*128 + 64 + c] = x*W1[192 + c] + y*W1[256 + c] + z*W1[320 + c];
}

// ---------------- per-point a/b projections, layers 2/3 (Cin=64), transposed smem ----------------
#define AB64_SMEM ((64*68 + 64*128) * 4)
__global__ __launch_bounds__(256) void ab64_kernel(const float* __restrict__ h,
                                                   const float* __restrict__ W1,
                                                   const float* __restrict__ b1)
{
    extern __shared__ float sm[];
    float* hs = sm;            // transposed: hs[k*68 + p]
    float* Ws = sm + 64*68;    // [64][128]
    int tx = threadIdx.x;
    int base = blockIdx.x * 64;
    for (int t = tx; t < 4096; t += 256) {
        int p = t >> 6, c = t & 63;
        hs[c*68 + p] = h[(size_t)base*64 + t];
    }
    for (int t = tx; t < 8192; t += 256) {
        int f = t >> 7, cc = t & 127;
        Ws[t] = (cc < 64) ? W1[f*64 + cc] : W1[(64 + f)*64 + (cc - 64)];
    }
    __syncthreads();
    int p0 = (tx & 7) * 8, c0 = (tx >> 3) * 4;
    float acc[8][4];
#pragma unroll
    for (int i = 0; i < 8; i++)
#pragma unroll
        for (int j = 0; j < 4; j++) acc[i][j] = 0.f;
#pragma unroll 4
    for (int kk = 0; kk < 64; kk++) {
        float4 w  = *(const float4*)&Ws[kk*128 + c0];
        float4 hA = *(const float4*)&hs[kk*68 + p0];
        float4 hB = *(const float4*)&hs[kk*68 + p0 + 4];
        float hv[8] = {hA.x, hA.y, hA.z, hA.w, hB.x, hB.y, hB.z, hB.w};
#pragma unroll
        for (int i = 0; i < 8; i++) {
            acc[i][0] = fmaf(hv[i], w.x, acc[i][0]);
            acc[i][1] = fmaf(hv[i], w.y, acc[i][1]);
            acc[i][2] = fmaf(hv[i], w.z, acc[i][2]);
            acc[i][3] = fmaf(hv[i], w.w, acc[i][3]);
        }
    }
    // b1 folds into the a-half (cols 0..63) ONLY; b-half (cols 64..127) must stay bias-free
    float4 bb = make_float4(0.f, 0.f, 0.f, 0.f);
    if (c0 < 64) bb = *(const float4*)&b1[c0];
#pragma unroll
    for (int i = 0; i < 8; i++) {
        float4 o = make_float4(acc[i][0] + bb.x, acc[i][1] + bb.y, acc[i][2] + bb.z, acc[i][3] + bb.w);
        *(float4*)&g_ab[(size_t)(base + p0 + i)*128 + c0] = o;
    }
}

// ---------------- edge layer: fp32 hidden -> bf16-split -> mma.sync -> max_slots -> relu ----------------
// 256 threads, 256 edge rows/block (SLOTS rows per point). Warp tile = 64 rows x 32 cols.
// Bhi kept in registers (reused pass 1 & 3); Blo streamed. 3-pass split: AhiBhi + AhiBlo + AloBhi.
#define EDGE_SMEM (65536 + 16384 + 256)
template<int K, int SLOTS>
__global__ __launch_bounds__(256, 2) void edge_mma_kernel(
    const float* __restrict__ pos,
    const float* __restrict__ W1rel,   // [3][64] rel rows of W1
    const float* __restrict__ b2,
    int layer,
    float* __restrict__ hout)
{
    constexpr int PTS = 256 / SLOTS;
    extern __shared__ char smem_raw[];
    uint32_t su = smem_u32(smem_raw);
    uint32_t abase = (su + 127) & ~127u;
    char* base = smem_raw + (abase - su);
    char* AhiC = base;                       // 256 x 128B
    char* AloC = base + 32768;
    uint32_t sAhi = abase, sAlo = abase + 32768;
    uint32_t sBhi = abase + 65536, sBlo = abase + 65536 + 8192;

    int tid = threadIdx.x, warp = tid >> 5, lane = tid & 31;

    // stage pre-swizzled B tiles (16KB)
    {
        const uint4* sh = (const uint4*)g_w2s[layer][0];
        const uint4* sl = (const uint4*)g_w2s[layer][1];
        uint4* dh = (uint4*)(base + 65536);
        uint4* dl = (uint4*)(base + 65536 + 8192);
        for (int t = tid; t < 512; t += 256) { dh[t] = sh[t]; dl[t] = sl[t]; }
    }

    // phase A: one edge row per thread, bf16-split into A tiles
    {
        int row  = tid;
        int i    = blockIdx.x * PTS + row / SLOTS;
        int slot = row % SLOTS;
        int j = g_knn[i*8 + (slot < K ? slot : 0)];
        float rx = pos[3*j]   - pos[3*i];
        float ry = pos[3*j+1] - pos[3*i+1];
        float rz = pos[3*j+2] - pos[3*i+2];
#pragma unroll
        for (int c4 = 0; c4 < 16; c4++) {
            float4 a  = *(const float4*)&g_ab[(size_t)i*128 + c4*4];
            float4 b  = *(const float4*)&g_ab[(size_t)j*128 + 64 + c4*4];
            float4 u0 = *(const float4*)&W1rel[c4*4];
            float4 u1 = *(const float4*)&W1rel[64 + c4*4];
            float4 u2 = *(const float4*)&W1rel[128 + c4*4];
            float h0 = fmaxf(fmaf(rx, u0.x, fmaf(ry, u1.x, fmaf(rz, u2.x, a.x + b.x))), 0.f);
            float h1 = fmaxf(fmaf(rx, u0.y, fmaf(ry, u1.y, fmaf(rz, u2.y, a.y + b.y))), 0.f);
            float h2 = fmaxf(fmaf(rx, u0.z, fmaf(ry, u1.z, fmaf(rz, u2.z, a.z + b.z))), 0.f);
            float h3 = fmaxf(fmaf(rx, u0.w, fmaf(ry, u1.w, fmaf(rz, u2.w, a.w + b.w))), 0.f);
            __nv_bfloat16 q0 = __float2bfloat16(h0), q1 = __float2bfloat16(h1);
            __nv_bfloat16 q2 = __float2bfloat16(h2), q3 = __float2bfloat16(h3);
            __nv_bfloat16 s0 = __float2bfloat16(h0 - __bfloat162float(q0));
            __nv_bfloat16 s1 = __float2bfloat16(h1 - __bfloat162float(q1));
            __nv_bfloat16 s2 = __float2bfloat16(h2 - __bfloat162float(q2));
            __nv_bfloat16 s3 = __float2bfloat16(h3 - __bfloat162float(q3));
            uint32_t sw = sw128((uint32_t)(row*128 + c4*8));
            *(uint2*)(AhiC + sw) = make_uint2(pack_bf(q0, q1), pack_bf(q2, q3));
            *(uint2*)(AloC + sw) = make_uint2(pack_bf(s0, s1), pack_bf(s2, s3));
        }
    }
    __syncthreads();

    // phase B: warp tile = rows [(w>>1)*64, +64) x cols [(w&1)*32, +32)
    const int rb = (warp >> 1) * 64;
    const int ch = (warp & 1) * 32;         // col half base
    const int gn0 = (warp & 1) * 4;         // first global n-tile
    int acolb = (lane >> 4) * 16;
    int brow  = (lane & 7) * 128;
    int bcolb = ((lane >> 3) & 1) * 16;

    // Bhi fragments in registers (reused in passes 1 and 3)
    uint32_t bh[4][4][2];
#pragma unroll
    for (int nt = 0; nt < 4; nt++)
#pragma unroll
        for (int k = 0; k < 4; k++)
            ldsm_x2(bh[nt][k], sBhi + sw128((uint32_t)((gn0 + nt)*1024 + brow + k*32 + bcolb)));

#pragma unroll
    for (int rt = 0; rt < 4; rt++) {
        float d[4][4];
#pragma unroll
        for (int nt = 0; nt < 4; nt++)
#pragma unroll
            for (int q = 0; q < 4; q++) d[nt][q] = 0.f;

        uint32_t afr[4][4];
        uint32_t arow_off = (uint32_t)((rb + rt*16 + (lane & 15)) * 128);
#pragma unroll
        for (int k = 0; k < 4; k++)
            ldsm_x4(afr[k], sAhi + sw128(arow_off + k*32 + acolb));

        // pass 1: Ahi x Bhi (regs)
#pragma unroll
        for (int nt = 0; nt < 4; nt++)
#pragma unroll
            for (int k = 0; k < 4; k++) mma_16816(d[nt], afr[k], bh[nt][k]);
        // pass 2: Ahi x Blo (streamed)
#pragma unroll
        for (int nt = 0; nt < 4; nt++)
#pragma unroll
            for (int k = 0; k < 4; k++) {
                uint32_t bl[2];
                ldsm_x2(bl, sBlo + sw128((uint32_t)((gn0 + nt)*1024 + brow + k*32 + bcolb)));
                mma_16816(d[nt], afr[k], bl);
            }
        // pass 3: Alo x Bhi (regs)
#pragma unroll
        for (int k = 0; k < 4; k++)
            ldsm_x4(afr[k], sAlo + sw128(arow_off + k*32 + acolb));
#pragma unroll
        for (int nt = 0; nt < 4; nt++)
#pragma unroll
            for (int k = 0; k < 4; k++) mma_16816(d[nt], afr[k], bh[nt][k]);

        // epilogue: max over SLOTS rows, +b2, relu, store
        if (SLOTS == 8) {
            int pA = blockIdx.x * PTS + (warp >> 1) * 8 + rt * 2;
#pragma unroll
            for (int nt = 0; nt < 4; nt++) {
                float m0 = d[nt][0], m1 = d[nt][1], m2 = d[nt][2], m3 = d[nt][3];
#pragma unroll
                for (int s = 4; s <= 16; s <<= 1) {
                    m0 = fmaxf(m0, __shfl_xor_sync(0xffffffffu, m0, s));
                    m1 = fmaxf(m1, __shfl_xor_sync(0xffffffffu, m1, s));
                    m2 = fmaxf(m2, __shfl_xor_sync(0xffffffffu, m2, s));
                    m3 = fmaxf(m3, __shfl_xor_sync(0xffffffffu, m3, s));
                }
                int col = ch + nt*8 + (lane & 3)*2;
                if (lane < 4) {
                    float2 o = make_float2(fmaxf(m0 + b2[col], 0.f), fmaxf(m1 + b2[col+1], 0.f));
                    *(float2*)&hout[(size_t)pA*64 + col] = o;
                } else if (lane < 8) {
                    float2 o = make_float2(fmaxf(m2 + b2[col], 0.f), fmaxf(m3 + b2[col+1], 0.f));
                    *(float2*)&hout[(size_t)(pA + 1)*64 + col] = o;
                }
            }
        } else {  // SLOTS == 4: 4 points per m16 tile
            int pBse = blockIdx.x * PTS + (warp >> 1) * 16 + rt * 4;
#pragma unroll
            for (int nt = 0; nt < 4; nt++) {
                float m0 = d[nt][0], m1 = d[nt][1], m2 = d[nt][2], m3 = d[nt][3];
#pragma unroll
                for (int s = 4; s <= 8; s <<= 1) {
                    m0 = fmaxf(m0, __shfl_xor_sync(0xffffffffu, m0, s));
                    m1 = fmaxf(m1, __shfl_xor_sync(0xffffffffu, m1, s));
                    m2 = fmaxf(m2, __shfl_xor_sync(0xffffffffu, m2, s));
                    m3 = fmaxf(m3, __shfl_xor_sync(0xffffffffu, m3, s));
                }
                int col = ch + nt*8 + (lane & 3)*2;
                if ((lane & 15) < 4) {
                    int g = lane >> 4;   // 0 or 1
                    float2 o0 = make_float2(fmaxf(m0 + b2[col], 0.f), fmaxf(m1 + b2[col+1], 0.f));
                    float2 o1 = make_float2(fmaxf(m2 + b2[col], 0.f), fmaxf(m3 + b2[col+1], 0.f));
                    *(float2*)&hout[(size_t)(pBse + g)*64 + col]     = o0;
                    *(float2*)&hout[(size_t)(pBse + 2 + g)*64 + col] = o1;
                }
            }
        }
    }
}

// ---------------- global max pool + regression head ----------------
__global__ __launch_bounds__(256) void pool_kernel(const float* __restrict__ h,
                                                   const float* __restrict__ regW,
                                                   const float* __restrict__ regb,
                                                   float* __restrict__ out)
{
    __shared__ float red[4][64];
    int g = blockIdx.x;
    int c = threadIdx.x & 63, s = threadIdx.x >> 6;
    const float* hb = h + (size_t)g * PPG * 64;
    float m = -FLT_MAX;
    for (int p = s; p < PPG; p += 4) m = fmaxf(m, hb[p*64 + c]);
    red[s][c] = m;
    __syncthreads();
    if (threadIdx.x < 64)
        red[0][c] = fmaxf(fmaxf(red[0][c], red[1][c]), fmaxf(red[2][c], red[3][c]));
    __syncthreads();
    if (threadIdx.x < 6) {
        float acc = regb[threadIdx.x];
#pragma unroll
        for (int cc = 0; cc < 64; cc++)
            acc = fmaf(red[0][cc], regW[cc*6 + threadIdx.x], acc);
        out[g*6 + threadIdx.x] = acc;
    }
}

// ---------------- launch ----------------
extern "C" void kernel_launch(void* const* d_in, const int* in_sizes, int n_in,
                              void* d_out, int out_size)
{
    (void)in_sizes; (void)n_in; (void)out_size;
    const float* pos  = (const float*)d_in[1];
    const float* c1W1 = (const float*)d_in[3];
    const float* c1b1 = (const float*)d_in[4];
    const float* c1W2 = (const float*)d_in[5];
    const float* c1b2 = (const float*)d_in[6];
    const float* c2W1 = (const float*)d_in[7];
    const float* c2b1 = (const float*)d_in[8];
    const float* c2W2 = (const float*)d_in[9];
    const float* c2b2 = (const float*)d_in[10];
    const float* c3W1 = (const float*)d_in[11];
    const float* c3b1 = (const float*)d_in[12];
    const float* c3W2 = (const float*)d_in[13];
    const float* c3b2 = (const float*)d_in[14];
    const float* regW = (const float*)d_in[15];
    const float* regb = (const float*)d_in[16];
    float* out = (float*)d_out;

    float *h1, *h2;
    cudaGetSymbolAddress((void**)&h1, g_h1);
    cudaGetSymbolAddress((void**)&h2, g_h2);
    cudaFuncSetAttribute(ab64_kernel, cudaFuncAttributeMaxDynamicSharedMemorySize, AB64_SMEM);
    cudaFuncSetAttribute((const void*)edge_mma_kernel<6,8>, cudaFuncAttributeMaxDynamicSharedMemorySize, EDGE_SMEM);
    cudaFuncSetAttribute((const void*)edge_mma_kernel<4,4>, cudaFuncAttributeMaxDynamicSharedMemorySize, EDGE_SMEM);
    cudaFuncSetAttribute((const void*)edge_mma_kernel<3,4>, cudaFuncAttributeMaxDynamicSharedMemorySize, EDGE_SMEM);

    knn_kernel<<<BGRAPH * 4, 256>>>(pos);
    w2split_kernel<<<96, 128>>>(c1W2, c2W2, c3W2);
    ab3_kernel<<<NPTS * 64 / 256, 256>>>(pos, c1W1, c1b1);
    edge_mma_kernel<6,8><<<NPTS/32, 256, EDGE_SMEM>>>(pos, c1W1 + 6*64,   c1b2, 0, h1);
    ab64_kernel<<<NPTS/64, 256, AB64_SMEM>>>(h1, c2W1, c2b1);
    edge_mma_kernel<4,4><<<NPTS/64, 256, EDGE_SMEM>>>(pos, c2W1 + 128*64, c2b2, 1, h2);
    ab64_kernel<<<NPTS/64, 256, AB64_SMEM>>>(h2, c3W1, c3b1);
    edge_mma_kernel<3,4><<<NPTS/64, 256, EDGE_SMEM>>>(pos, c3W1 + 128*64, c3b2, 2, h1);
    pool_kernel<<<BGRAPH, 256>>>(h1, regW, regb, out);
}

// round 6
// speedup vs baseline: 1.4561x; 1.0404x over previous
#include <cuda_runtime.h>
#include <cuda_bf16.h>
#include <float.h>
#include <stdint.h>

#define NPTS   65536
#define BGRAPH 64
#define PPG    1024

// ---------------- scratch (device globals; no allocation) ----------------
__device__ int   g_knn[NPTS * 8];            // 6 real + 2 pad (dup of nn0)
__device__ float g_ab [NPTS * 128];          // a (+b1 folded) cols 0..63, b cols 64..127
__device__ float g_h1 [NPTS * 64];
__device__ float g_h2 [NPTS * 64];
__device__ __align__(16) __nv_bfloat16 g_w2s[3][2][4096];  // [layer][hi/lo] swizzled W2^T [n][k]

// ---------------- helpers (base-ISA: ldmatrix + mma.sync, sm_80+) ----------------
__device__ __forceinline__ uint32_t smem_u32(const void* p) {
    uint32_t a;
    asm("{ .reg .u64 t; cvta.to.shared.u64 t, %1; cvt.u32.u64 %0, t; }" : "=r"(a) : "l"(p));
    return a;
}
__device__ __forceinline__ uint32_t sw128(uint32_t off) { return off ^ ((off >> 3) & 0x70); }
__device__ __forceinline__ uint32_t pack_bf(__nv_bfloat16 a, __nv_bfloat16 b) {
    uint16_t ua = __bfloat16_as_ushort(a), ub = __bfloat16_as_ushort(b);
    return (uint32_t)ua | ((uint32_t)ub << 16);
}
__device__ __forceinline__ void ldsm_x4(uint32_t* r, uint32_t addr) {
    asm volatile("ldmatrix.sync.aligned.m8n8.x4.shared.b16 {%0,%1,%2,%3}, [%4];"
                 : "=r"(r[0]), "=r"(r[1]), "=r"(r[2]), "=r"(r[3]) : "r"(addr));
}
__device__ __forceinline__ void ldsm_x2(uint32_t* r, uint32_t addr) {
    asm volatile("ldmatrix.sync.aligned.m8n8.x2.shared.b16 {%0,%1}, [%2];"
                 : "=r"(r[0]), "=r"(r[1]) : "r"(addr));
}
__device__ __forceinline__ void mma_16816(float* d, const uint32_t* a, const uint32_t* b) {
    asm volatile("mma.sync.aligned.m16n8k16.row.col.f32.bf16.bf16.f32 "
                 "{%0,%1,%2,%3}, {%4,%5,%6,%7}, {%8,%9}, {%0,%1,%2,%3};"
                 : "+f"(d[0]), "+f"(d[1]), "+f"(d[2]), "+f"(d[3])
                 : "r"(a[0]), "r"(a[1]), "r"(a[2]), "r"(a[3]), "r"(b[0]), "r"(b[1]));
}

// ---------------- kNN (k=6, matches jax top_k(-d2, 6) incl. ties) ----------------
__global__ __launch_bounds__(256) void knn_kernel(const float* __restrict__ pos)
{
    __shared__ float4 cand[256];
    int graph = blockIdx.x >> 2;
    int q = graph * PPG + ((blockIdx.x & 3) << 8) + threadIdx.x;
    float qx = pos[3*q], qy = pos[3*q+1], qz = pos[3*q+2];
    float qs = qx*qx + qy*qy + qz*qz;
    float bd[6]; int bi[6];
#pragma unroll
    for (int t = 0; t < 6; t++) { bd[t] = FLT_MAX; bi[t] = 0; }
    for (int tile = 0; tile < PPG; tile += 256) {
        int c = graph * PPG + tile + threadIdx.x;
        float cx = pos[3*c], cy = pos[3*c+1], cz = pos[3*c+2];
        cand[threadIdx.x] = make_float4(cx, cy, cz, cx*cx + cy*cy + cz*cz);
        __syncthreads();
#pragma unroll 4
        for (int u = 0; u < 256; u++) {
            float4 p = cand[u];
            float d2 = qs + p.w - 2.0f*(qx*p.x + qy*p.y + qz*p.z);
            if (d2 < bd[5]) {
                bd[5] = d2; bi[5] = graph*PPG + tile + u;
#pragma unroll
                for (int t = 5; t > 0; t--) {
                    if (bd[t] < bd[t-1]) {
                        float td = bd[t]; bd[t] = bd[t-1]; bd[t-1] = td;
                        int   ti = bi[t]; bi[t] = bi[t-1]; bi[t-1] = ti;
                    }
                }
            }
        }
        __syncthreads();
    }
#pragma unroll
    for (int t = 0; t < 6; t++) g_knn[q*8 + t] = bi[t];
    g_knn[q*8 + 6] = bi[0];
    g_knn[q*8 + 7] = bi[0];
}

// ---------------- W2^T bf16 split into swizzled B tiles (all 3 layers) ----------------
__global__ __launch_bounds__(128) void w2split_kernel(const float* __restrict__ W2a,
                                                      const float* __restrict__ W2b,
                                                      const float* __restrict__ W2c)
{
    int t = blockIdx.x * 128 + threadIdx.x;        // 3*4096 threads
    int l = t >> 12, nk = t & 4095;
    int n = nk >> 6, k = nk & 63;
    const float* W2 = (l == 0) ? W2a : ((l == 1) ? W2b : W2c);
    float v = W2[k*64 + n];                        // B^T[n][k] = W2[k][n]
    __nv_bfloat16 hi = __float2bfloat16(v);
    __nv_bfloat16 lo = __float2bfloat16(v - __bfloat162float(hi));
    uint32_t sw = sw128((uint32_t)(n*128 + k*2));
    g_w2s[l][0][sw >> 1] = hi;
    g_w2s[l][1][sw >> 1] = lo;
}

// ---------------- per-point a/b projections, layer 1 (Cin=3), b1 folded into a ----------------
__global__ __launch_bounds__(256) void ab3_kernel(const float* __restrict__ pos,
                                                  const float* __restrict__ W1,
                                                  const float* __restrict__ b1)
{
    int idx = blockIdx.x * 256 + threadIdx.x;
    int i = idx >> 6, c = idx & 63;
    float x = pos[3*i], y = pos[3*i+1], z = pos[3*i+2];
    g_ab[i*128 + c]      = fmaf(x, W1[c], fmaf(y, W1[64+c], fmaf(z, W1[128+c], b1[c])));
    g_ab[i*128 + 64 + c] = x*W1[192 + c] + y*W1[256 + c] + z*W1[320 + c];
}

// ---------------- per-point a/b projections, layers 2/3 (Cin=64), transposed smem ----------------
#define AB64_SMEM ((64*68 + 64*128) * 4)
__global__ __launch_bounds__(256) void ab64_kernel(const float* __restrict__ h,
                                                   const float* __restrict__ W1,
                                                   const float* __restrict__ b1)
{
    extern __shared__ float sm[];
    float* hs = sm;            // transposed: hs[k*68 + p]
    float* Ws = sm + 64*68;    // [64][128]
    int tx = threadIdx.x;
    int base = blockIdx.x * 64;
    for (int t = tx; t < 4096; t += 256) {
        int p = t >> 6, c = t & 63;
        hs[c*68 + p] = h[(size_t)base*64 + t];
    }
    for (int t = tx; t < 8192; t += 256) {
        int f = t >> 7, cc = t & 127;
        Ws[t] = (cc < 64) ? W1[f*64 + cc] : W1[(64 + f)*64 + (cc - 64)];
    }
    __syncthreads();
    int p0 = (tx & 7) * 8, c0 = (tx >> 3) * 4;
    float acc[8][4];
#pragma unroll
    for (int i = 0; i < 8; i++)
#pragma unroll
        for (int j = 0; j < 4; j++) acc[i][j] = 0.f;
#pragma unroll 4
    for (int kk = 0; kk < 64; kk++) {
        float4 w  = *(const float4*)&Ws[kk*128 + c0];
        float4 hA = *(const float4*)&hs[kk*68 + p0];
        float4 hB = *(const float4*)&hs[kk*68 + p0 + 4];
        float hv[8] = {hA.x, hA.y, hA.z, hA.w, hB.x, hB.y, hB.z, hB.w};
#pragma unroll
        for (int i = 0; i < 8; i++) {
            acc[i][0] = fmaf(hv[i], w.x, acc[i][0]);
            acc[i][1] = fmaf(hv[i], w.y, acc[i][1]);
            acc[i][2] = fmaf(hv[i], w.z, acc[i][2]);
            acc[i][3] = fmaf(hv[i], w.w, acc[i][3]);
        }
    }
    // b1 folds into the a-half (cols 0..63) ONLY; b-half (cols 64..127) must stay bias-free
    float4 bb = make_float4(0.f, 0.f, 0.f, 0.f);
    if (c0 < 64) bb = *(const float4*)&b1[c0];
#pragma unroll
    for (int i = 0; i < 8; i++) {
        float4 o = make_float4(acc[i][0] + bb.x, acc[i][1] + bb.y, acc[i][2] + bb.z, acc[i][3] + bb.w);
        *(float4*)&g_ab[(size_t)(base + p0 + i)*128 + c0] = o;
    }
}

// ---------------- edge layer: fp32 hidden -> bf16-split -> mma.sync -> max_slots -> relu ----------------
// 256 threads, 256 edge rows/block (SLOTS rows per point). Warp tile = 64 rows x 32 cols.
// BOTH Bhi and Blo held in registers (zero streamed B traffic). STS.128 A stores.
#define EDGE_SMEM (65536 + 16384 + 256)
template<int K, int SLOTS>
__global__ __launch_bounds__(256, 2) void edge_mma_kernel(
    const float* __restrict__ pos,
    const float* __restrict__ W1rel,   // [3][64] rel rows of W1
    const float* __restrict__ b2,
    int layer,
    float* __restrict__ hout)
{
    constexpr int PTS = 256 / SLOTS;
    extern __shared__ char smem_raw[];
    uint32_t su = smem_u32(smem_raw);
    uint32_t abase = (su + 127) & ~127u;
    char* base = smem_raw + (abase - su);
    char* AhiC = base;                       // 256 x 128B
    char* AloC = base + 32768;
    uint32_t sAhi = abase, sAlo = abase + 32768;
    uint32_t sBhi = abase + 65536, sBlo = abase + 65536 + 8192;

    int tid = threadIdx.x, warp = tid >> 5, lane = tid & 31;

    // stage pre-swizzled B tiles (16KB)
    {
        const uint4* sh = (const uint4*)g_w2s[layer][0];
        const uint4* sl = (const uint4*)g_w2s[layer][1];
        uint4* dh = (uint4*)(base + 65536);
        uint4* dl = (uint4*)(base + 65536 + 8192);
        for (int t = tid; t < 512; t += 256) { dh[t] = sh[t]; dl[t] = sl[t]; }
    }

    // phase A: one edge row per thread, bf16-split into A tiles (STS.128, 16B-merged)
    {
        int row  = tid;
        int i    = blockIdx.x * PTS + row / SLOTS;
        int slot = row % SLOTS;
        int j = g_knn[i*8 + (slot < K ? slot : 0)];
        float rx = pos[3*j]   - pos[3*i];
        float ry = pos[3*j+1] - pos[3*i+1];
        float rz = pos[3*j+2] - pos[3*i+2];
#pragma unroll
        for (int c8 = 0; c8 < 8; c8++) {       // 8 channels per iter -> one uint4 store
            uint32_t hi4[4], lo4[4];
#pragma unroll
            for (int hh = 0; hh < 2; hh++) {   // two float4 sub-groups
                int cb = c8*8 + hh*4;
                float4 a  = *(const float4*)&g_ab[(size_t)i*128 + cb];
                float4 b  = *(const float4*)&g_ab[(size_t)j*128 + 64 + cb];
                float4 u0 = *(const float4*)&W1rel[cb];
                float4 u1 = *(const float4*)&W1rel[64 + cb];
                float4 u2 = *(const float4*)&W1rel[128 + cb];
                float h0 = fmaxf(fmaf(rx, u0.x, fmaf(ry, u1.x, fmaf(rz, u2.x, a.x + b.x))), 0.f);
                float h1 = fmaxf(fmaf(rx, u0.y, fmaf(ry, u1.y, fmaf(rz, u2.y, a.y + b.y))), 0.f);
                float h2 = fmaxf(fmaf(rx, u0.z, fmaf(ry, u1.z, fmaf(rz, u2.z, a.z + b.z))), 0.f);
                float h3 = fmaxf(fmaf(rx, u0.w, fmaf(ry, u1.w, fmaf(rz, u2.w, a.w + b.w))), 0.f);
                __nv_bfloat16 q0 = __float2bfloat16(h0), q1 = __float2bfloat16(h1);
                __nv_bfloat16 q2 = __float2bfloat16(h2), q3 = __float2bfloat16(h3);
                __nv_bfloat16 s0 = __float2bfloat16(h0 - __bfloat162float(q0));
                __nv_bfloat16 s1 = __float2bfloat16(h1 - __bfloat162float(q1));
                __nv_bfloat16 s2 = __float2bfloat16(h2 - __bfloat162float(q2));
                __nv_bfloat16 s3 = __float2bfloat16(h3 - __bfloat162float(q3));
                hi4[hh*2]   = pack_bf(q0, q1); hi4[hh*2+1] = pack_bf(q2, q3);
                lo4[hh*2]   = pack_bf(s0, s1); lo4[hh*2+1] = pack_bf(s2, s3);
            }
            uint32_t sw = sw128((uint32_t)(row*128 + c8*16));
            *(uint4*)(AhiC + sw) = make_uint4(hi4[0], hi4[1], hi4[2], hi4[3]);
            *(uint4*)(AloC + sw) = make_uint4(lo4[0], lo4[1], lo4[2], lo4[3]);
        }
    }
    __syncthreads();

    // phase B: warp tile = rows [(w>>1)*64, +64) x cols [(w&1)*32, +32)
    const int rb = (warp >> 1) * 64;
    const int ch = (warp & 1) * 32;         // col half base
    const int gn0 = (warp & 1) * 4;         // first global n-tile
    int acolb = (lane >> 4) * 16;
    int brow  = (lane & 7) * 128;
    int bcolb = ((lane >> 3) & 1) * 16;

    // Bhi AND Blo fragments in registers (no streamed B traffic in the rt loop)
    uint32_t bh[4][4][2], bl[4][4][2];
#pragma unroll
    for (int nt = 0; nt < 4; nt++)
#pragma unroll
        for (int k = 0; k < 4; k++) {
            uint32_t boff = (uint32_t)((gn0 + nt)*1024 + brow + k*32 + bcolb);
            ldsm_x2(bh[nt][k], sBhi + sw128(boff));
            ldsm_x2(bl[nt][k], sBlo + sw128(boff));
        }

#pragma unroll
    for (int rt = 0; rt < 4; rt++) {
        float d[4][4];
#pragma unroll
        for (int nt = 0; nt < 4; nt++)
#pragma unroll
            for (int q = 0; q < 4; q++) d[nt][q] = 0.f;

        uint32_t afr[4][4];
        uint32_t arow_off = (uint32_t)((rb + rt*16 + (lane & 15)) * 128);
#pragma unroll
        for (int k = 0; k < 4; k++)
            ldsm_x4(afr[k], sAhi + sw128(arow_off + k*32 + acolb));

        // pass 1: Ahi x Bhi
#pragma unroll
        for (int nt = 0; nt < 4; nt++)
#pragma unroll
            for (int k = 0; k < 4; k++) mma_16816(d[nt], afr[k], bh[nt][k]);
        // pass 2: Ahi x Blo
#pragma unroll
        for (int nt = 0; nt < 4; nt++)
#pragma unroll
            for (int k = 0; k < 4; k++) mma_16816(d[nt], afr[k], bl[nt][k]);
        // pass 3: Alo x Bhi
#pragma unroll
        for (int k = 0; k < 4; k++)
            ldsm_x4(afr[k], sAlo + sw128(arow_off + k*32 + acolb));
#pragma unroll
        for (int nt = 0; nt < 4; nt++)
#pragma unroll
            for (int k = 0; k < 4; k++) mma_16816(d[nt], afr[k], bh[nt][k]);

        // epilogue: max over SLOTS rows, +b2, relu, store
        if (SLOTS == 8) {
            int pA = blockIdx.x * PTS + (warp >> 1) * 8 + rt * 2;
#pragma unroll
            for (int nt = 0; nt < 4; nt++) {
                float m0 = d[nt][0], m1 = d[nt][1], m2 = d[nt][2], m3 = d[nt][3];
#pragma unroll
                for (int s = 4; s <= 16; s <<= 1) {
                    m0 = fmaxf(m0, __shfl_xor_sync(0xffffffffu, m0, s));
                    m1 = fmaxf(m1, __shfl_xor_sync(0xffffffffu, m1, s));
                    m2 = fmaxf(m2, __shfl_xor_sync(0xffffffffu, m2, s));
                    m3 = fmaxf(m3, __shfl_xor_sync(0xffffffffu, m3, s));
                }
                int col = ch + nt*8 + (lane & 3)*2;
                if (lane < 4) {
                    float2 o = make_float2(fmaxf(m0 + b2[col], 0.f), fmaxf(m1 + b2[col+1], 0.f));
                    *(float2*)&hout[(size_t)pA*64 + col] = o;
                } else if (lane < 8) {
                    float2 o = make_float2(fmaxf(m2 + b2[col], 0.f), fmaxf(m3 + b2[col+1], 0.f));
                    *(float2*)&hout[(size_t)(pA + 1)*64 + col] = o;
                }
            }
        } else {  // SLOTS == 4: 4 points per m16 tile
            int pBse = blockIdx.x * PTS + (warp >> 1) * 16 + rt * 4;
#pragma unroll
            for (int nt = 0; nt < 4; nt++) {
                float m0 = d[nt][0], m1 = d[nt][1], m2 = d[nt][2], m3 = d[nt][3];
#pragma unroll
                for (int s = 4; s <= 8; s <<= 1) {
                    m0 = fmaxf(m0, __shfl_xor_sync(0xffffffffu, m0, s));
                    m1 = fmaxf(m1, __shfl_xor_sync(0xffffffffu, m1, s));
                    m2 = fmaxf(m2, __shfl_xor_sync(0xffffffffu, m2, s));
                    m3 = fmaxf(m3, __shfl_xor_sync(0xffffffffu, m3, s));
                }
                int col = ch + nt*8 + (lane & 3)*2;
                if ((lane & 15) < 4) {
                    int g = lane >> 4;   // 0 or 1
                    float2 o0 = make_float2(fmaxf(m0 + b2[col], 0.f), fmaxf(m1 + b2[col+1], 0.f));
                    float2 o1 = make_float2(fmaxf(m2 + b2[col], 0.f), fmaxf(m3 + b2[col+1], 0.f));
                    *(float2*)&hout[(size_t)(pBse + g)*64 + col]     = o0;
                    *(float2*)&hout[(size_t)(pBse + 2 + g)*64 + col] = o1;
                }
            }
        }
    }
}

// ---------------- global max pool + regression head ----------------
__global__ __launch_bounds__(256) void pool_kernel(const float* __restrict__ h,
                                                   const float* __restrict__ regW,
                                                   const float* __restrict__ regb,
                                                   float* __restrict__ out)
{
    __shared__ float red[4][64];
    int g = blockIdx.x;
    int c = threadIdx.x & 63, s = threadIdx.x >> 6;
    const float* hb = h + (size_t)g * PPG * 64;
    float m = -FLT_MAX;
    for (int p = s; p < PPG; p += 4) m = fmaxf(m, hb[p*64 + c]);
    red[s][c] = m;
    __syncthreads();
    if (threadIdx.x < 64)
        red[0][c] = fmaxf(fmaxf(red[0][c], red[1][c]), fmaxf(red[2][c], red[3][c]));
    __syncthreads();
    if (threadIdx.x < 6) {
        float acc = regb[threadIdx.x];
#pragma unroll
        for (int cc = 0; cc < 64; cc++)
            acc = fmaf(red[0][cc], regW[cc*6 + threadIdx.x], acc);
        out[g*6 + threadIdx.x] = acc;
    }
}

// ---------------- launch ----------------
extern "C" void kernel_launch(void* const* d_in, const int* in_sizes, int n_in,
                              void* d_out, int out_size)
{
    (void)in_sizes; (void)n_in; (void)out_size;
    const float* pos  = (const float*)d_in[1];
    const float* c1W1 = (const float*)d_in[3];
    const float* c1b1 = (const float*)d_in[4];
    const float* c1W2 = (const float*)d_in[5];
    const float* c1b2 = (const float*)d_in[6];
    const float* c2W1 = (const float*)d_in[7];
    const float* c2b1 = (const float*)d_in[8];
    const float* c2W2 = (const float*)d_in[9];
    const float* c2b2 = (const float*)d_in[10];
    const float* c3W1 = (const float*)d_in[11];
    const float* c3b1 = (const float*)d_in[12];
    const float* c3W2 = (const float*)d_in[13];
    const float* c3b2 = (const float*)d_in[14];
    const float* regW = (const float*)d_in[15];
    const float* regb = (const float*)d_in[16];
    float* out = (float*)d_out;

    float *h1, *h2;
    cudaGetSymbolAddress((void**)&h1, g_h1);
    cudaGetSymbolAddress((void**)&h2, g_h2);
    cudaFuncSetAttribute(ab64_kernel, cudaFuncAttributeMaxDynamicSharedMemorySize, AB64_SMEM);
    cudaFuncSetAttribute((const void*)edge_mma_kernel<6,8>, cudaFuncAttributeMaxDynamicSharedMemorySize, EDGE_SMEM);
    cudaFuncSetAttribute((const void*)edge_mma_kernel<4,4>, cudaFuncAttributeMaxDynamicSharedMemorySize, EDGE_SMEM);
    cudaFuncSetAttribute((const void*)edge_mma_kernel<3,4>, cudaFuncAttributeMaxDynamicSharedMemorySize, EDGE_SMEM);

    knn_kernel<<<BGRAPH * 4, 256>>>(pos);
    w2split_kernel<<<96, 128>>>(c1W2, c2W2, c3W2);
    ab3_kernel<<<NPTS * 64 / 256, 256>>>(pos, c1W1, c1b1);
    edge_mma_kernel<6,8><<<NPTS/32, 256, EDGE_SMEM>>>(pos, c1W1 + 6*64,   c1b2, 0, h1);
    ab64_kernel<<<NPTS/64, 256, AB64_SMEM>>>(h1, c2W1, c2b1);
    edge_mma_kernel<4,4><<<NPTS/64, 256, EDGE_SMEM>>>(pos, c2W1 + 128*64, c2b2, 1, h2);
    ab64_kernel<<<NPTS/64, 256, AB64_SMEM>>>(h2, c3W1, c3b1);
    edge_mma_kernel<3,4><<<NPTS/64, 256, EDGE_SMEM>>>(pos, c3W1 + 128*64, c3b2, 2, h1);
    pool_kernel<<<BGRAPH, 256>>>(h1, regW, regb, out);
}

// round 7
// speedup vs baseline: 1.5136x; 1.0395x over previous
#include <cuda_runtime.h>
#include <cuda_bf16.h>
#include <float.h>
#include <stdint.h>

#define NPTS   65536
#define BGRAPH 64
#define PPG    1024

// ---------------- scratch (device globals; no allocation) ----------------
__device__ int    g_knn[NPTS * 8];            // 6 real + 2 pad (dup of nn0)
__device__ float  g_ab [NPTS * 128];          // a (+b1 folded) cols 0..63, b cols 64..127
__device__ float  g_h1 [NPTS * 64];
__device__ float  g_h2 [NPTS * 64];
__device__ float4 g_pos4[NPTS];               // packed positions (x,y,z,0)
__device__ __align__(16) __nv_bfloat16 g_w2s[3][2][4096];  // [layer][hi/lo] swizzled W2^T [n][k]

// ---------------- helpers (base-ISA: ldmatrix + mma.sync, sm_80+) ----------------
__device__ __forceinline__ uint32_t smem_u32(const void* p) {
    uint32_t a;
    asm("{ .reg .u64 t; cvta.to.shared.u64 t, %1; cvt.u32.u64 %0, t; }" : "=r"(a) : "l"(p));
    return a;
}
__device__ __forceinline__ uint32_t sw128(uint32_t off) { return off ^ ((off >> 3) & 0x70); }
__device__ __forceinline__ uint32_t pack_bf(__nv_bfloat16 a, __nv_bfloat16 b) {
    uint16_t ua = __bfloat16_as_ushort(a), ub = __bfloat16_as_ushort(b);
    return (uint32_t)ua | ((uint32_t)ub << 16);
}
__device__ __forceinline__ void ldsm_x4(uint32_t* r, uint32_t addr) {
    asm volatile("ldmatrix.sync.aligned.m8n8.x4.shared.b16 {%0,%1,%2,%3}, [%4];"
                 : "=r"(r[0]), "=r"(r[1]), "=r"(r[2]), "=r"(r[3]) : "r"(addr));
}
__device__ __forceinline__ void mma_16816(float* d, const uint32_t* a, const uint32_t* b) {
    asm volatile("mma.sync.aligned.m16n8k16.row.col.f32.bf16.bf16.f32 "
                 "{%0,%1,%2,%3}, {%4,%5,%6,%7}, {%8,%9}, {%0,%1,%2,%3};"
                 : "+f"(d[0]), "+f"(d[1]), "+f"(d[2]), "+f"(d[3])
                 : "r"(a[0]), "r"(a[1]), "r"(a[2]), "r"(a[3]), "r"(b[0]), "r"(b[1]));
}

// ---------------- kNN (k=6, 2 queries/thread; matches jax top_k ties) ----------------
__global__ __launch_bounds__(256) void knn_kernel(const float* __restrict__ pos)
{
    __shared__ float4 cand[256];
    int graph = blockIdx.x >> 1;
    int q0 = graph * PPG + ((blockIdx.x & 1) << 9) + threadIdx.x;
    int q1 = q0 + 256;
    float ax = pos[3*q0], ay = pos[3*q0+1], az = pos[3*q0+2];
    float bx = pos[3*q1], by = pos[3*q1+1], bz = pos[3*q1+2];
    float as = ax*ax + ay*ay + az*az;
    float bs = bx*bx + by*by + bz*bz;
    g_pos4[q0] = make_float4(ax, ay, az, 0.f);
    g_pos4[q1] = make_float4(bx, by, bz, 0.f);
    float ad[6], bd[6]; int ai[6], bi[6];
#pragma unroll
    for (int t = 0; t < 6; t++) { ad[t] = FLT_MAX; ai[t] = 0; bd[t] = FLT_MAX; bi[t] = 0; }
    for (int tile = 0; tile < PPG; tile += 256) {
        int c = graph * PPG + tile + threadIdx.x;
        float cx = pos[3*c], cy = pos[3*c+1], cz = pos[3*c+2];
        cand[threadIdx.x] = make_float4(cx, cy, cz, cx*cx + cy*cy + cz*cz);
        __syncthreads();
#pragma unroll 4
        for (int u = 0; u < 256; u++) {
            float4 p = cand[u];
            int cidx = graph*PPG + tile + u;
            float d2a = as + p.w - 2.0f*(ax*p.x + ay*p.y + az*p.z);
            float d2b = bs + p.w - 2.0f*(bx*p.x + by*p.y + bz*p.z);
            if (d2a < ad[5]) {
                ad[5] = d2a; ai[5] = cidx;
#pragma unroll
                for (int t = 5; t > 0; t--)
                    if (ad[t] < ad[t-1]) {
                        float td = ad[t]; ad[t] = ad[t-1]; ad[t-1] = td;
                        int   ti = ai[t]; ai[t] = ai[t-1]; ai[t-1] = ti;
                    }
            }
            if (d2b < bd[5]) {
                bd[5] = d2b; bi[5] = cidx;
#pragma unroll
                for (int t = 5; t > 0; t--)
                    if (bd[t] < bd[t-1]) {
                        float td = bd[t]; bd[t] = bd[t-1]; bd[t-1] = td;
                        int   ti = bi[t]; bi[t] = bi[t-1]; bi[t-1] = ti;
                    }
            }
        }
        __syncthreads();
    }
#pragma unroll
    for (int t = 0; t < 6; t++) { g_knn[q0*8 + t] = ai[t]; g_knn[q1*8 + t] = bi[t]; }
    g_knn[q0*8 + 6] = ai[0]; g_knn[q0*8 + 7] = ai[0];
    g_knn[q1*8 + 6] = bi[0]; g_knn[q1*8 + 7] = bi[0];
}

// ---------------- W2^T bf16 split into swizzled B tiles (all 3 layers) ----------------
__global__ __launch_bounds__(128) void w2split_kernel(const float* __restrict__ W2a,
                                                      const float* __restrict__ W2b,
                                                      const float* __restrict__ W2c)
{
    int t = blockIdx.x * 128 + threadIdx.x;        // 3*4096 threads
    int l = t >> 12, nk = t & 4095;
    int n = nk >> 6, k = nk & 63;
    const float* W2 = (l == 0) ? W2a : ((l == 1) ? W2b : W2c);
    float v = W2[k*64 + n];                        // B^T[n][k] = W2[k][n]
    __nv_bfloat16 hi = __float2bfloat16(v);
    __nv_bfloat16 lo = __float2bfloat16(v - __bfloat162float(hi));
    uint32_t sw = sw128((uint32_t)(n*128 + k*2));
    g_w2s[l][0][sw >> 1] = hi;
    g_w2s[l][1][sw >> 1] = lo;
}

// ---------------- per-point a/b projections, layer 1 (Cin=3), b1 folded into a ----------------
__global__ __launch_bounds__(256) void ab3_kernel(const float* __restrict__ pos,
                                                  const float* __restrict__ W1,
                                                  const float* __restrict__ b1)
{
    int idx = blockIdx.x * 256 + threadIdx.x;
    int i = idx >> 6, c = idx & 63;
    float x = pos[3*i], y = pos[3*i+1], z = pos[3*i+2];
    g_ab[i*128 + c]      = fmaf(x, W1[c], fmaf(y, W1[64+c], fmaf(z, W1[128+c], b1[c])));
    g_ab[i*128 + 64 + c] = x*W1[192 + c] + y*W1[256 + c] + z*W1[320 + c];
}

// ---------------- per-point a/b projections, layers 2/3 (Cin=64), transposed smem ----------------
#define AB64_SMEM ((64*68 + 64*128) * 4)
__global__ __launch_bounds__(256) void ab64_kernel(const float* __restrict__ h,
                                                   const float* __restrict__ W1,
                                                   const float* __restrict__ b1)
{
    extern __shared__ float sm[];
    float* hs = sm;            // transposed: hs[k*68 + p]
    float* Ws = sm + 64*68;    // [64][128]
    int tx = threadIdx.x;
    int base = blockIdx.x * 64;
    for (int t = tx; t < 4096; t += 256) {
        int p = t >> 6, c = t & 63;
        hs[c*68 + p] = h[(size_t)base*64 + t];
    }
    for (int t = tx; t < 8192; t += 256) {
        int f = t >> 7, cc = t & 127;
        Ws[t] = (cc < 64) ? W1[f*64 + cc] : W1[(64 + f)*64 + (cc - 64)];
    }
    __syncthreads();
    int p0 = (tx & 7) * 8, c0 = (tx >> 3) * 4;
    float acc[8][4];
#pragma unroll
    for (int i = 0; i < 8; i++)
#pragma unroll
        for (int j = 0; j < 4; j++) acc[i][j] = 0.f;
#pragma unroll 4
    for (int kk = 0; kk < 64; kk++) {
        float4 w  = *(const float4*)&Ws[kk*128 + c0];
        float4 hA = *(const float4*)&hs[kk*68 + p0];
        float4 hB = *(const float4*)&hs[kk*68 + p0 + 4];
        float hv[8] = {hA.x, hA.y, hA.z, hA.w, hB.x, hB.y, hB.z, hB.w};
#pragma unroll
        for (int i = 0; i < 8; i++) {
            acc[i][0] = fmaf(hv[i], w.x, acc[i][0]);
            acc[i][1] = fmaf(hv[i], w.y, acc[i][1]);
            acc[i][2] = fmaf(hv[i], w.z, acc[i][2]);
            acc[i][3] = fmaf(hv[i], w.w, acc[i][3]);
        }
    }
    // b1 folds into the a-half (cols 0..63) ONLY
    float4 bb = make_float4(0.f, 0.f, 0.f, 0.f);
    if (c0 < 64) bb = *(const float4*)&b1[c0];
#pragma unroll
    for (int i = 0; i < 8; i++) {
        float4 o = make_float4(acc[i][0] + bb.x, acc[i][1] + bb.y, acc[i][2] + bb.z, acc[i][3] + bb.w);
        *(float4*)&g_ab[(size_t)(base + p0 + i)*128 + c0] = o;
    }
}

// ---------------- edge layer: channel-major hidden -> bf16-split -> mma.sync -> max -> relu ----------------
// 256 threads, 256 edge rows/block (SLOTS rows per point). Warp tile = 64 rows x 32 cols.
// Phase A: lane owns channels (2*lane, 2*lane+1); W1rel in regs; coalesced gathers.
#define EDGE_SMEM (65536 + 16384 + 256)
template<int K, int SLOTS>
__global__ __launch_bounds__(256, 2) void edge_mma_kernel(
    const float* __restrict__ pos,
    const float* __restrict__ W1rel,   // [3][64] rel rows of W1
    const float* __restrict__ b2,
    int layer,
    float* __restrict__ hout)
{
    constexpr int PTS = 256 / SLOTS;
    constexpr int PPW = PTS / 8;        // points per warp in phase A
    extern __shared__ char smem_raw[];
    uint32_t su = smem_u32(smem_raw);
    uint32_t abase = (su + 127) & ~127u;
    char* base = smem_raw + (abase - su);
    char* AhiC = base;                       // 256 x 128B
    char* AloC = base + 32768;
    uint32_t sAhi = abase, sAlo = abase + 32768;
    uint32_t sBhi = abase + 65536, sBlo = abase + 65536 + 8192;

    int tid = threadIdx.x, warp = tid >> 5, lane = tid & 31;

    // stage pre-swizzled B tiles (16KB)
    {
        const uint4* sh = (const uint4*)g_w2s[layer][0];
        const uint4* sl = (const uint4*)g_w2s[layer][1];
        uint4* dh = (uint4*)(base + 65536);
        uint4* dl = (uint4*)(base + 65536 + 8192);
        for (int t = tid; t < 512; t += 256) { dh[t] = sh[t]; dl[t] = sl[t]; }
    }

    // phase A: channel-major. lane -> channels (2*lane, 2*lane+1); warp -> PPW points x SLOTS rows
    {
        int lane2 = lane * 2;
        float u0x = W1rel[lane2],       u0y = W1rel[lane2 + 1];
        float u1x = W1rel[64 + lane2],  u1y = W1rel[64 + lane2 + 1];
        float u2x = W1rel[128 + lane2], u2y = W1rel[128 + lane2 + 1];
#pragma unroll
        for (int pp = 0; pp < PPW; pp++) {
            int lp = warp * PPW + pp;
            int i = blockIdx.x * PTS + lp;
            float2 a = *(const float2*)&g_ab[(size_t)i*128 + lane2];
            float4 pi = g_pos4[i];
            int rowbase = lp * SLOTS;
#pragma unroll
            for (int slot = 0; slot < SLOTS; slot++) {
                int j = g_knn[i*8 + (slot < K ? slot : 0)];
                float4 pj = g_pos4[j];
                float2 b = *(const float2*)&g_ab[(size_t)j*128 + 64 + lane2];
                float rx = pj.x - pi.x, ry = pj.y - pi.y, rz = pj.z - pi.z;
                float h0 = fmaxf(fmaf(rx, u0x, fmaf(ry, u1x, fmaf(rz, u2x, a.x + b.x))), 0.f);
                float h1 = fmaxf(fmaf(rx, u0y, fmaf(ry, u1y, fmaf(rz, u2y, a.y + b.y))), 0.f);
                __nv_bfloat16 q0 = __float2bfloat16(h0), q1 = __float2bfloat16(h1);
                __nv_bfloat16 s0 = __float2bfloat16(h0 - __bfloat162float(q0));
                __nv_bfloat16 s1 = __float2bfloat16(h1 - __bfloat162float(q1));
                uint32_t sw = sw128((uint32_t)((rowbase + slot)*128 + lane2*2));
                *(uint32_t*)(AhiC + sw) = pack_bf(q0, q1);
                *(uint32_t*)(AloC + sw) = pack_bf(s0, s1);
            }
        }
    }
    __syncthreads();

    // phase B: warp tile = rows [(w>>1)*64, +64) x cols [(w&1)*32, +32)
    const int rb = (warp >> 1) * 64;
    const int ch = (warp & 1) * 32;
    const int gn0 = (warp & 1) * 4;
    int acolb = (lane >> 4) * 16;

    // B fragments (hi+lo) in registers, loaded via ldsm_x4 (2 k-chunks per instr)
    uint32_t bh[4][4][2], bl[4][4][2];
    {
        uint32_t laddr = (uint32_t)((lane & 7)*128 + ((lane >> 4) & 1)*32 + ((lane >> 3) & 1)*16);
#pragma unroll
        for (int nt = 0; nt < 4; nt++)
#pragma unroll
            for (int kp = 0; kp < 4; kp += 2) {
                uint32_t boff = sw128((uint32_t)((gn0 + nt)*1024 + kp*32) + laddr);
                uint32_t r[4];
                ldsm_x4(r, sBhi + boff);
                bh[nt][kp][0] = r[0]; bh[nt][kp][1] = r[1];
                bh[nt][kp+1][0] = r[2]; bh[nt][kp+1][1] = r[3];
                ldsm_x4(r, sBlo + boff);
                bl[nt][kp][0] = r[0]; bl[nt][kp][1] = r[1];
                bl[nt][kp+1][0] = r[2]; bl[nt][kp+1][1] = r[3];
            }
    }

#pragma unroll
    for (int rt = 0; rt < 4; rt++) {
        float d[4][4];
#pragma unroll
        for (int nt = 0; nt < 4; nt++)
#pragma unroll
            for (int q = 0; q < 4; q++) d[nt][q] = 0.f;

        uint32_t afr[4][4];
        uint32_t arow_off = (uint32_t)((rb + rt*16 + (lane & 15)) * 128);
#pragma unroll
        for (int k = 0; k < 4; k++)
            ldsm_x4(afr[k], sAhi + sw128(arow_off + k*32 + acolb));

#pragma unroll
        for (int nt = 0; nt < 4; nt++)
#pragma unroll
            for (int k = 0; k < 4; k++) mma_16816(d[nt], afr[k], bh[nt][k]);
#pragma unroll
        for (int nt = 0; nt < 4; nt++)
#pragma unroll
            for (int k = 0; k < 4; k++) mma_16816(d[nt], afr[k], bl[nt][k]);
#pragma unroll
        for (int k = 0; k < 4; k++)
            ldsm_x4(afr[k], sAlo + sw128(arow_off + k*32 + acolb));
#pragma unroll
        for (int nt = 0; nt < 4; nt++)
#pragma unroll
            for (int k = 0; k < 4; k++) mma_16816(d[nt], afr[k], bh[nt][k]);

        // epilogue: max over SLOTS rows, +b2, relu, store
        if (SLOTS == 8) {
            int pA = blockIdx.x * PTS + (warp >> 1) * 8 + rt * 2;
#pragma unroll
            for (int nt = 0; nt < 4; nt++) {
                float m0 = d[nt][0], m1 = d[nt][1], m2 = d[nt][2], m3 = d[nt][3];
#pragma unroll
                for (int s = 4; s <= 16; s <<= 1) {
                    m0 = fmaxf(m0, __shfl_xor_sync(0xffffffffu, m0, s));
                    m1 = fmaxf(m1, __shfl_xor_sync(0xffffffffu, m1, s));
                    m2 = fmaxf(m2, __shfl_xor_sync(0xffffffffu, m2, s));
                    m3 = fmaxf(m3, __shfl_xor_sync(0xffffffffu, m3, s));
                }
                int col = ch + nt*8 + (lane & 3)*2;
                if (lane < 4) {
                    float2 o = make_float2(fmaxf(m0 + b2[col], 0.f), fmaxf(m1 + b2[col+1], 0.f));
                    *(float2*)&hout[(size_t)pA*64 + col] = o;
                } else if (lane < 8) {
                    float2 o = make_float2(fmaxf(m2 + b2[col], 0.f), fmaxf(m3 + b2[col+1], 0.f));
                    *(float2*)&hout[(size_t)(pA + 1)*64 + col] = o;
                }
            }
        } else {  // SLOTS == 4
            int pBse = blockIdx.x * PTS + (warp >> 1) * 16 + rt * 4;
#pragma unroll
            for (int nt = 0; nt < 4; nt++) {
                float m0 = d[nt][0], m1 = d[nt][1], m2 = d[nt][2], m3 = d[nt][3];
#pragma unroll
                for (int s = 4; s <= 8; s <<= 1) {
                    m0 = fmaxf(m0, __shfl_xor_sync(0xffffffffu, m0, s));
                    m1 = fmaxf(m1, __shfl_xor_sync(0xffffffffu, m1, s));
                    m2 = fmaxf(m2, __shfl_xor_sync(0xffffffffu, m2, s));
                    m3 = fmaxf(m3, __shfl_xor_sync(0xffffffffu, m3, s));
                }
                int col = ch + nt*8 + (lane & 3)*2;
                if ((lane & 15) < 4) {
                    int g = lane >> 4;
                    float2 o0 = make_float2(fmaxf(m0 + b2[col], 0.f), fmaxf(m1 + b2[col+1], 0.f));
                    float2 o1 = make_float2(fmaxf(m2 + b2[col], 0.f), fmaxf(m3 + b2[col+1], 0.f));
                    *(float2*)&hout[(size_t)(pBse + g)*64 + col]     = o0;
                    *(float2*)&hout[(size_t)(pBse + 2 + g)*64 + col] = o1;
                }
            }
        }
    }
}

// ---------------- global max pool + regression head ----------------
__global__ __launch_bounds__(256) void pool_kernel(const float* __restrict__ h,
                                                   const float* __restrict__ regW,
                                                   const float* __restrict__ regb,
                                                   float* __restrict__ out)
{
    __shared__ float red[4][64];
    int g = blockIdx.x;
    int c = threadIdx.x & 63, s = threadIdx.x >> 6;
    const float* hb = h + (size_t)g * PPG * 64;
    float m = -FLT_MAX;
    for (int p = s; p < PPG; p += 4) m = fmaxf(m, hb[p*64 + c]);
    red[s][c] = m;
    __syncthreads();
    if (threadIdx.x < 64)
        red[0][c] = fmaxf(fmaxf(red[0][c], red[1][c]), fmaxf(red[2][c], red[3][c]));
    __syncthreads();
    if (threadIdx.x < 6) {
        float acc = regb[threadIdx.x];
#pragma unroll
        for (int cc = 0; cc < 64; cc++)
            acc = fmaf(red[0][cc], regW[cc*6 + threadIdx.x], acc);
        out[g*6 + threadIdx.x] = acc;
    }
}

// ---------------- launch ----------------
extern "C" void kernel_launch(void* const* d_in, const int* in_sizes, int n_in,
                              void* d_out, int out_size)
{
    (void)in_sizes; (void)n_in; (void)out_size;
    const float* pos  = (const float*)d_in[1];
    const float* c1W1 = (const float*)d_in[3];
    const float* c1b1 = (const float*)d_in[4];
    const float* c1W2 = (const float*)d_in[5];
    const float* c1b2 = (const float*)d_in[6];
    const float* c2W1 = (const float*)d_in[7];
    const float* c2b1 = (const float*)d_in[8];
    const float* c2W2 = (const float*)d_in[9];
    const float* c2b2 = (const float*)d_in[10];
    const float* c3W1 = (const float*)d_in[11];
    const float* c3b1 = (const float*)d_in[12];
    const float* c3W2 = (const float*)d_in[13];
    const float* c3b2 = (const float*)d_in[14];
    const float* regW = (const float*)d_in[15];
    const float* regb = (const float*)d_in[16];
    float* out = (float*)d_out;

    float *h1, *h2;
    cudaGetSymbolAddress((void**)&h1, g_h1);
    cudaGetSymbolAddress((void**)&h2, g_h2);
    cudaFuncSetAttribute(ab64_kernel, cudaFuncAttributeMaxDynamicSharedMemorySize, AB64_SMEM);
    cudaFuncSetAttribute((const void*)edge_mma_kernel<6,8>, cudaFuncAttributeMaxDynamicSharedMemorySize, EDGE_SMEM);
    cudaFuncSetAttribute((const void*)edge_mma_kernel<4,4>, cudaFuncAttributeMaxDynamicSharedMemorySize, EDGE_SMEM);
    cudaFuncSetAttribute((const void*)edge_mma_kernel<3,4>, cudaFuncAttributeMaxDynamicSharedMemorySize, EDGE_SMEM);

    knn_kernel<<<BGRAPH * 2, 256>>>(pos);
    w2split_kernel<<<96, 128>>>(c1W2, c2W2, c3W2);
    ab3_kernel<<<NPTS * 64 / 256, 256>>>(pos, c1W1, c1b1);
    edge_mma_kernel<6,8><<<NPTS/32, 256, EDGE_SMEM>>>(pos, c1W1 + 6*64,   c1b2, 0, h1);
    ab64_kernel<<<NPTS/64, 256, AB64_SMEM>>>(h1, c2W1, c2b1);
    edge_mma_kernel<4,4><<<NPTS/64, 256, EDGE_SMEM>>>(pos, c2W1 + 128*64, c2b2, 1, h2);
    ab64_kernel<<<NPTS/64, 256, AB64_SMEM>>>(h2, c3W1, c3b1);
    edge_mma_kernel<3,4><<<NPTS/64, 256, EDGE_SMEM>>>(pos, c3W1 + 128*64, c3b2, 2, h1);
    pool_kernel<<<BGRAPH, 256>>>(h1, regW, regb, out);
}

// round 8
// speedup vs baseline: 1.7158x; 1.1336x over previous
#include <cuda_runtime.h>
#include <cuda_bf16.h>
#include <float.h>
#include <stdint.h>

#define NPTS   65536
#define BGRAPH 64
#define PPG    1024

// ---------------- scratch (device globals; no allocation) ----------------
__device__ int    g_knn[NPTS * 8];            // 6 real + 2 pad (dup of nn0)
__device__ float  g_ab [NPTS * 128];          // a (+b1 folded) cols 0..63, b cols 64..127
__device__ float  g_h1 [NPTS * 64];
__device__ float  g_h2 [NPTS * 64];
__device__ float4 g_pos4[NPTS];               // packed positions (x,y,z,0)
__device__ __align__(16) __nv_bfloat16 g_w2s[3][2][4096];  // [layer][hi/lo] swizzled W2^T [n=64][k=64]
__device__ __align__(16) __nv_bfloat16 g_w1s[2][2][8192];  // [layer][hi/lo] swizzled W1ab^T [n=128][k=64]

// ---------------- helpers (base-ISA: ldmatrix + mma.sync, sm_80+) ----------------
__device__ __forceinline__ uint32_t smem_u32(const void* p) {
    uint32_t a;
    asm("{ .reg .u64 t; cvta.to.shared.u64 t, %1; cvt.u32.u64 %0, t; }" : "=r"(a) : "l"(p));
    return a;
}
__device__ __forceinline__ uint32_t sw128(uint32_t off) { return off ^ ((off >> 3) & 0x70); }
__device__ __forceinline__ uint32_t pack_bf(__nv_bfloat16 a, __nv_bfloat16 b) {
    uint16_t ua = __bfloat16_as_ushort(a), ub = __bfloat16_as_ushort(b);
    return (uint32_t)ua | ((uint32_t)ub << 16);
}
__device__ __forceinline__ void ldsm_x4(uint32_t* r, uint32_t addr) {
    asm volatile("ldmatrix.sync.aligned.m8n8.x4.shared.b16 {%0,%1,%2,%3}, [%4];"
                 : "=r"(r[0]), "=r"(r[1]), "=r"(r[2]), "=r"(r[3]) : "r"(addr));
}
__device__ __forceinline__ void mma_16816(float* d, const uint32_t* a, const uint32_t* b) {
    asm volatile("mma.sync.aligned.m16n8k16.row.col.f32.bf16.bf16.f32 "
                 "{%0,%1,%2,%3}, {%4,%5,%6,%7}, {%8,%9}, {%0,%1,%2,%3};"
                 : "+f"(d[0]), "+f"(d[1]), "+f"(d[2]), "+f"(d[3])
                 : "r"(a[0]), "r"(a[1]), "r"(a[2]), "r"(a[3]), "r"(b[0]), "r"(b[1]));
}
__device__ __forceinline__ void split_store(char* hiC, char* loC, uint32_t sw,
                                            float4 v0, float4 v1) {
    __nv_bfloat16 q0 = __float2bfloat16(v0.x), q1 = __float2bfloat16(v0.y);
    __nv_bfloat16 q2 = __float2bfloat16(v0.z), q3 = __float2bfloat16(v0.w);
    __nv_bfloat16 q4 = __float2bfloat16(v1.x), q5 = __float2bfloat16(v1.y);
    __nv_bfloat16 q6 = __float2bfloat16(v1.z), q7 = __float2bfloat16(v1.w);
    __nv_bfloat16 s0 = __float2bfloat16(v0.x - __bfloat162float(q0));
    __nv_bfloat16 s1 = __float2bfloat16(v0.y - __bfloat162float(q1));
    __nv_bfloat16 s2 = __float2bfloat16(v0.z - __bfloat162float(q2));
    __nv_bfloat16 s3 = __float2bfloat16(v0.w - __bfloat162float(q3));
    __nv_bfloat16 s4 = __float2bfloat16(v1.x - __bfloat162float(q4));
    __nv_bfloat16 s5 = __float2bfloat16(v1.y - __bfloat162float(q5));
    __nv_bfloat16 s6 = __float2bfloat16(v1.z - __bfloat162float(q6));
    __nv_bfloat16 s7 = __float2bfloat16(v1.w - __bfloat162float(q7));
    *(uint4*)(hiC + sw) = make_uint4(pack_bf(q0,q1), pack_bf(q2,q3), pack_bf(q4,q5), pack_bf(q6,q7));
    *(uint4*)(loC + sw) = make_uint4(pack_bf(s0,s1), pack_bf(s2,s3), pack_bf(s4,s5), pack_bf(s6,s7));
}

// ---------------- kNN (k=6, 2 queries/thread, 4 blocks/graph; matches jax top_k ties) ----------------
__global__ __launch_bounds__(128) void knn_kernel(const float* __restrict__ pos)
{
    __shared__ float4 cand[128];
    int graph = blockIdx.x >> 2;
    int q0 = graph * PPG + ((blockIdx.x & 3) << 8) + threadIdx.x;
    int q1 = q0 + 128;
    float ax = pos[3*q0], ay = pos[3*q0+1], az = pos[3*q0+2];
    float bx = pos[3*q1], by = pos[3*q1+1], bz = pos[3*q1+2];
    float as = ax*ax + ay*ay + az*az;
    float bs = bx*bx + by*by + bz*bz;
    g_pos4[q0] = make_float4(ax, ay, az, 0.f);
    g_pos4[q1] = make_float4(bx, by, bz, 0.f);
    float ad[6], bd[6]; int ai[6], bi[6];
#pragma unroll
    for (int t = 0; t < 6; t++) { ad[t] = FLT_MAX; ai[t] = 0; bd[t] = FLT_MAX; bi[t] = 0; }
    for (int tile = 0; tile < PPG; tile += 128) {
        int c = graph * PPG + tile + threadIdx.x;
        float cx = pos[3*c], cy = pos[3*c+1], cz = pos[3*c+2];
        cand[threadIdx.x] = make_float4(cx, cy, cz, cx*cx + cy*cy + cz*cz);
        __syncthreads();
#pragma unroll 4
        for (int u = 0; u < 128; u++) {
            float4 p = cand[u];
            int cidx = graph*PPG + tile + u;
            float d2a = as + p.w - 2.0f*(ax*p.x + ay*p.y + az*p.z);
            float d2b = bs + p.w - 2.0f*(bx*p.x + by*p.y + bz*p.z);
            if (d2a < ad[5]) {
                ad[5] = d2a; ai[5] = cidx;
#pragma unroll
                for (int t = 5; t > 0; t--)
                    if (ad[t] < ad[t-1]) {
                        float td = ad[t]; ad[t] = ad[t-1]; ad[t-1] = td;
                        int   ti = ai[t]; ai[t] = ai[t-1]; ai[t-1] = ti;
                    }
            }
            if (d2b < bd[5]) {
                bd[5] = d2b; bi[5] = cidx;
#pragma unroll
                for (int t = 5; t > 0; t--)
                    if (bd[t] < bd[t-1]) {
                        float td = bd[t]; bd[t] = bd[t-1]; bd[t-1] = td;
                        int   ti = bi[t]; bi[t] = bi[t-1]; bi[t-1] = ti;
                    }
            }
        }
        __syncthreads();
    }
#pragma unroll
    for (int t = 0; t < 6; t++) { g_knn[q0*8 + t] = ai[t]; g_knn[q1*8 + t] = bi[t]; }
    g_knn[q0*8 + 6] = ai[0]; g_knn[q0*8 + 7] = ai[0];
    g_knn[q1*8 + 6] = bi[0]; g_knn[q1*8 + 7] = bi[0];
}

// ---------------- W2^T bf16 split into swizzled B tiles (all 3 layers) ----------------
__global__ __launch_bounds__(128) void w2split_kernel(const float* __restrict__ W2a,
                                                      const float* __restrict__ W2b,
                                                      const float* __restrict__ W2c)
{
    int t = blockIdx.x * 128 + threadIdx.x;        // 3*4096 threads
    int l = t >> 12, nk = t & 4095;
    int n = nk >> 6, k = nk & 63;
    const float* W2 = (l == 0) ? W2a : ((l == 1) ? W2b : W2c);
    float v = W2[k*64 + n];                        // B^T[n][k] = W2[k][n]
    __nv_bfloat16 hi = __float2bfloat16(v);
    __nv_bfloat16 lo = __float2bfloat16(v - __bfloat162float(hi));
    uint32_t sw = sw128((uint32_t)(n*128 + k*2));
    g_w2s[l][0][sw >> 1] = hi;
    g_w2s[l][1][sw >> 1] = lo;
}

// ---------------- W1ab^T bf16 split, layers 2/3 (n=128 out cols, k=64 in ch) ----------------
__global__ __launch_bounds__(128) void w1split_kernel(const float* __restrict__ W1b,
                                                      const float* __restrict__ W1c)
{
    int t = blockIdx.x * 128 + threadIdx.x;        // 2*8192 threads
    int l = t >> 13, nk = t & 8191;
    int n = nk >> 6, k = nk & 63;
    const float* W1 = l ? W1c : W1b;
    float v = (n < 64) ? W1[k*64 + n] : W1[(64 + k)*64 + (n - 64)];
    __nv_bfloat16 hi = __float2bfloat16(v);
    __nv_bfloat16 lo = __float2bfloat16(v - __bfloat162float(hi));
    uint32_t sw = sw128((uint32_t)(n*128 + k*2));
    g_w1s[l][0][sw >> 1] = hi;
    g_w1s[l][1][sw >> 1] = lo;
}

// ---------------- per-point a/b projections, layer 1 (Cin=3), b1 folded into a ----------------
__global__ __launch_bounds__(256) void ab3_kernel(const float* __restrict__ pos,
                                                  const float* __restrict__ W1,
                                                  const float* __restrict__ b1)
{
    int idx = blockIdx.x * 256 + threadIdx.x;
    int i = idx >> 6, c = idx & 63;
    float x = pos[3*i], y = pos[3*i+1], z = pos[3*i+2];
    g_ab[i*128 + c]      = fmaf(x, W1[c], fmaf(y, W1[64+c], fmaf(z, W1[128+c], b1[c])));
    g_ab[i*128 + 64 + c] = x*W1[192 + c] + y*W1[256 + c] + z*W1[320 + c];
}

// ---------------- ab projections, layers 2/3: MMA GEMM 128pts x 128cols x 64ch ----------------
// 8 warps; warp tile = 32 rows x 64 cols. bf16 3-pass split. b1 added to cols 0..63 only.
#define ABM_SMEM (65536 + 256)
__global__ __launch_bounds__(256, 2) void ab64_mma_kernel(const float* __restrict__ h,
                                                          const float* __restrict__ b1,
                                                          int layer,
                                                          float* __restrict__ abot)
{
    extern __shared__ char smem_raw[];
    uint32_t su = smem_u32(smem_raw);
    uint32_t abase = (su + 127) & ~127u;
    char* base = smem_raw + (abase - su);
    char* AhiC = base;                        // 128 rows x 128B = 16KB
    char* AloC = base + 16384;
    uint32_t sAhi = abase, sAlo = abase + 16384;
    uint32_t sBhi = abase + 32768, sBlo = abase + 32768 + 16384;

    int tid = threadIdx.x, warp = tid >> 5, lane = tid & 31;
    int pbase = blockIdx.x * 128;

    // stage B tiles (16KB hi + 16KB lo)
    {
        const uint4* sh = (const uint4*)g_w1s[layer][0];
        const uint4* sl = (const uint4*)g_w1s[layer][1];
        uint4* dh = (uint4*)(base + 32768);
        uint4* dl = (uint4*)(base + 32768 + 16384);
        for (int t = tid; t < 1024; t += 256) { dh[t] = sh[t]; dl[t] = sl[t]; }
    }

    // load + split A: thread -> row tid>>1, channel half (tid&1)*32
    {
        int row = tid >> 1, chb = (tid & 1) * 32;
        const float* hr = h + (size_t)(pbase + row) * 64 + chb;
#pragma unroll
        for (int g = 0; g < 4; g++) {      // 8 channels per iter -> one uint4 per tile
            float4 v0 = *(const float4*)(hr + g*8);
            float4 v1 = *(const float4*)(hr + g*8 + 4);
            uint32_t sw = sw128((uint32_t)(row*128 + (chb + g*8)*2));
            split_store(AhiC, AloC, sw, v0, v1);
        }
    }
    __syncthreads();

    const int rb = (warp >> 1) * 32;       // 4 row-groups of 32
    const int ch = (warp & 1) * 64;        // 2 col halves of 64
    const int gn0 = (warp & 1) * 8;        // first n-tile
    int acolb = (lane >> 4) * 16;
    uint32_t laddr = (uint32_t)((lane & 7)*128 + ((lane >> 4) & 1)*32 + ((lane >> 3) & 1)*16);

    uint32_t afr[2][4][4];
#pragma unroll
    for (int rt = 0; rt < 2; rt++) {
        uint32_t arow = (uint32_t)((rb + rt*16 + (lane & 15)) * 128);
#pragma unroll
        for (int k = 0; k < 4; k++)
            ldsm_x4(afr[rt][k], sAhi + sw128(arow + k*32 + acolb));
    }

    float d[2][8][4];
#pragma unroll
    for (int rt = 0; rt < 2; rt++)
#pragma unroll
        for (int nt = 0; nt < 8; nt++)
#pragma unroll
            for (int q = 0; q < 4; q++) d[rt][nt][q] = 0.f;

    // passes 1 (Ahi*Bhi) + 2 (Ahi*Blo), B streamed per n-tile
#pragma unroll
    for (int nt = 0; nt < 8; nt++) {
        uint32_t bh[4][2], bl[4][2];
#pragma unroll
        for (int kp = 0; kp < 4; kp += 2) {
            uint32_t bo = sw128((uint32_t)((gn0 + nt)*1024 + kp*32) + laddr);
            uint32_t r[4];
            ldsm_x4(r, sBhi + bo);
            bh[kp][0] = r[0]; bh[kp][1] = r[1]; bh[kp+1][0] = r[2]; bh[kp+1][1] = r[3];
            ldsm_x4(r, sBlo + bo);
            bl[kp][0] = r[0]; bl[kp][1] = r[1]; bl[kp+1][0] = r[2]; bl[kp+1][1] = r[3];
        }
#pragma unroll
        for (int rt = 0; rt < 2; rt++)
#pragma unroll
            for (int k = 0; k < 4; k++) mma_16816(d[rt][nt], afr[rt][k], bh[k]);
#pragma unroll
        for (int rt = 0; rt < 2; rt++)
#pragma unroll
            for (int k = 0; k < 4; k++) mma_16816(d[rt][nt], afr[rt][k], bl[k]);
    }
    // pass 3 (Alo*Bhi): overwrite A frags with lo
#pragma unroll
    for (int rt = 0; rt < 2; rt++) {
        uint32_t arow = (uint32_t)((rb + rt*16 + (lane & 15)) * 128);
#pragma unroll
        for (int k = 0; k < 4; k++)
            ldsm_x4(afr[rt][k], sAlo + sw128(arow + k*32 + acolb));
    }
#pragma unroll
    for (int nt = 0; nt < 8; nt++) {
        uint32_t bh[4][2];
#pragma unroll
        for (int kp = 0; kp < 4; kp += 2) {
            uint32_t bo = sw128((uint32_t)((gn0 + nt)*1024 + kp*32) + laddr);
            uint32_t r[4];
            ldsm_x4(r, sBhi + bo);
            bh[kp][0] = r[0]; bh[kp][1] = r[1]; bh[kp+1][0] = r[2]; bh[kp+1][1] = r[3];
        }
#pragma unroll
        for (int rt = 0; rt < 2; rt++)
#pragma unroll
            for (int k = 0; k < 4; k++) mma_16816(d[rt][nt], afr[rt][k], bh[k]);
    }

    // epilogue: +b1 on cols 0..63 only, store fp32
#pragma unroll
    for (int rt = 0; rt < 2; rt++) {
        int r0 = rb + rt*16 + (lane >> 2);
#pragma unroll
        for (int nt = 0; nt < 8; nt++) {
            int col = ch + nt*8 + (lane & 3)*2;
            float bx = 0.f, by = 0.f;
            if (col < 64) { bx = b1[col]; by = b1[col + 1]; }
            *(float2*)&abot[(size_t)(pbase + r0)*128 + col] =
                make_float2(d[rt][nt][0] + bx, d[rt][nt][1] + by);
            *(float2*)&abot[(size_t)(pbase + r0 + 8)*128 + col] =
                make_float2(d[rt][nt][2] + bx, d[rt][nt][3] + by);
        }
    }
}

// ---------------- edge layer: channel-major hidden -> bf16-split -> mma.sync -> max -> relu ----------------
#define EDGE_SMEM (65536 + 16384 + 256)
template<int K, int SLOTS>
__global__ __launch_bounds__(256, 2) void edge_mma_kernel(
    const float* __restrict__ pos,
    const float* __restrict__ W1rel,   // [3][64] rel rows of W1
    const float* __restrict__ b2,
    int layer,
    float* __restrict__ hout)
{
    constexpr int PTS = 256 / SLOTS;
    constexpr int PPW = PTS / 8;
    extern __shared__ char smem_raw[];
    uint32_t su = smem_u32(smem_raw);
    uint32_t abase = (su + 127) & ~127u;
    char* base = smem_raw + (abase - su);
    char* AhiC = base;
    char* AloC = base + 32768;
    uint32_t sAhi = abase, sAlo = abase + 32768;
    uint32_t sBhi = abase + 65536, sBlo = abase + 65536 + 8192;

    int tid = threadIdx.x, warp = tid >> 5, lane = tid & 31;

    {
        const uint4* sh = (const uint4*)g_w2s[layer][0];
        const uint4* sl = (const uint4*)g_w2s[layer][1];
        uint4* dh = (uint4*)(base + 65536);
        uint4* dl = (uint4*)(base + 65536 + 8192);
        for (int t = tid; t < 512; t += 256) { dh[t] = sh[t]; dl[t] = sl[t]; }
    }

    // phase A: channel-major; lane -> channels (2*lane, 2*lane+1)
    {
        int lane2 = lane * 2;
        float u0x = W1rel[lane2],       u0y = W1rel[lane2 + 1];
        float u1x = W1rel[64 + lane2],  u1y = W1rel[64 + lane2 + 1];
        float u2x = W1rel[128 + lane2], u2y = W1rel[128 + lane2 + 1];
#pragma unroll
        for (int pp = 0; pp < PPW; pp++) {
            int lp = warp * PPW + pp;
            int i = blockIdx.x * PTS + lp;
            float2 a = *(const float2*)&g_ab[(size_t)i*128 + lane2];
            float4 pi = g_pos4[i];
            int rowbase = lp * SLOTS;
#pragma unroll
            for (int slot = 0; slot < SLOTS; slot++) {
                int j = g_knn[i*8 + (slot < K ? slot : 0)];
                float4 pj = g_pos4[j];
                float2 b = *(const float2*)&g_ab[(size_t)j*128 + 64 + lane2];
                float rx = pj.x - pi.x, ry = pj.y - pi.y, rz = pj.z - pi.z;
                float h0 = fmaxf(fmaf(rx, u0x, fmaf(ry, u1x, fmaf(rz, u2x, a.x + b.x))), 0.f);
                float h1 = fmaxf(fmaf(rx, u0y, fmaf(ry, u1y, fmaf(rz, u2y, a.y + b.y))), 0.f);
                __nv_bfloat16 q0 = __float2bfloat16(h0), q1 = __float2bfloat16(h1);
                __nv_bfloat16 s0 = __float2bfloat16(h0 - __bfloat162float(q0));
                __nv_bfloat16 s1 = __float2bfloat16(h1 - __bfloat162float(q1));
                uint32_t sw = sw128((uint32_t)((rowbase + slot)*128 + lane2*2));
                *(uint32_t*)(AhiC + sw) = pack_bf(q0, q1);
                *(uint32_t*)(AloC + sw) = pack_bf(s0, s1);
            }
        }
    }
    __syncthreads();

    const int rb = (warp >> 1) * 64;
    const int ch = (warp & 1) * 32;
    const int gn0 = (warp & 1) * 4;
    int acolb = (lane >> 4) * 16;

    uint32_t bh[4][4][2], bl[4][4][2];
    {
        uint32_t laddr = (uint32_t)((lane & 7)*128 + ((lane >> 4) & 1)*32 + ((lane >> 3) & 1)*16);
#pragma unroll
        for (int nt = 0; nt < 4; nt++)
#pragma unroll
            for (int kp = 0; kp < 4; kp += 2) {
                uint32_t boff = sw128((uint32_t)((gn0 + nt)*1024 + kp*32) + laddr);
                uint32_t r[4];
                ldsm_x4(r, sBhi + boff);
                bh[nt][kp][0] = r[0]; bh[nt][kp][1] = r[1];
                bh[nt][kp+1][0] = r[2]; bh[nt][kp+1][1] = r[3];
                ldsm_x4(r, sBlo + boff);
                bl[nt][kp][0] = r[0]; bl[nt][kp][1] = r[1];
                bl[nt][kp+1][0] = r[2]; bl[nt][kp+1][1] = r[3];
            }
    }

#pragma unroll
    for (int rt = 0; rt < 4; rt++) {
        float d[4][4];
#pragma unroll
        for (int nt = 0; nt < 4; nt++)
#pragma unroll
            for (int q = 0; q < 4; q++) d[nt][q] = 0.f;

        uint32_t afr[4][4];
        uint32_t arow_off = (uint32_t)((rb + rt*16 + (lane & 15)) * 128);
#pragma unroll
        for (int k = 0; k < 4; k++)
            ldsm_x4(afr[k], sAhi + sw128(arow_off + k*32 + acolb));

#pragma unroll
        for (int nt = 0; nt < 4; nt++)
#pragma unroll
            for (int k = 0; k < 4; k++) mma_16816(d[nt], afr[k], bh[nt][k]);
#pragma unroll
        for (int nt = 0; nt < 4; nt++)
#pragma unroll
            for (int k = 0; k < 4; k++) mma_16816(d[nt], afr[k], bl[nt][k]);
#pragma unroll
        for (int k = 0; k < 4; k++)
            ldsm_x4(afr[k], sAlo + sw128(arow_off + k*32 + acolb));
#pragma unroll
        for (int nt = 0; nt < 4; nt++)
#pragma unroll
            for (int k = 0; k < 4; k++) mma_16816(d[nt], afr[k], bh[nt][k]);

        if (SLOTS == 8) {
            int pA = blockIdx.x * PTS + (warp >> 1) * 8 + rt * 2;
#pragma unroll
            for (int nt = 0; nt < 4; nt++) {
                float m0 = d[nt][0], m1 = d[nt][1], m2 = d[nt][2], m3 = d[nt][3];
#pragma unroll
                for (int s = 4; s <= 16; s <<= 1) {
                    m0 = fmaxf(m0, __shfl_xor_sync(0xffffffffu, m0, s));
                    m1 = fmaxf(m1, __shfl_xor_sync(0xffffffffu, m1, s));
                    m2 = fmaxf(m2, __shfl_xor_sync(0xffffffffu, m2, s));
                    m3 = fmaxf(m3, __shfl_xor_sync(0xffffffffu, m3, s));
                }
                int col = ch + nt*8 + (lane & 3)*2;
                if (lane < 4) {
                    float2 o = make_float2(fmaxf(m0 + b2[col], 0.f), fmaxf(m1 + b2[col+1], 0.f));
                    *(float2*)&hout[(size_t)pA*64 + col] = o;
                } else if (lane < 8) {
                    float2 o = make_float2(fmaxf(m2 + b2[col], 0.f), fmaxf(m3 + b2[col+1], 0.f));
                    *(float2*)&hout[(size_t)(pA + 1)*64 + col] = o;
                }
            }
        } else {  // SLOTS == 4
            int pBse = blockIdx.x * PTS + (warp >> 1) * 16 + rt * 4;
#pragma unroll
            for (int nt = 0; nt < 4; nt++) {
                float m0 = d[nt][0], m1 = d[nt][1], m2 = d[nt][2], m3 = d[nt][3];
#pragma unroll
                for (int s = 4; s <= 8; s <<= 1) {
                    m0 = fmaxf(m0, __shfl_xor_sync(0xffffffffu, m0, s));
                    m1 = fmaxf(m1, __shfl_xor_sync(0xffffffffu, m1, s));
                    m2 = fmaxf(m2, __shfl_xor_sync(0xffffffffu, m2, s));
                    m3 = fmaxf(m3, __shfl_xor_sync(0xffffffffu, m3, s));
                }
                int col = ch + nt*8 + (lane & 3)*2;
                if ((lane & 15) < 4) {
                    int g = lane >> 4;
                    float2 o0 = make_float2(fmaxf(m0 + b2[col], 0.f), fmaxf(m1 + b2[col+1], 0.f));
                    float2 o1 = make_float2(fmaxf(m2 + b2[col], 0.f), fmaxf(m3 + b2[col+1], 0.f));
                    *(float2*)&hout[(size_t)(pBse + g)*64 + col]     = o0;
                    *(float2*)&hout[(size_t)(pBse + 2 + g)*64 + col] = o1;
                }
            }
        }
    }
}

// ---------------- global max pool + regression head ----------------
__global__ __launch_bounds__(256) void pool_kernel(const float* __restrict__ h,
                                                   const float* __restrict__ regW,
                                                   const float* __restrict__ regb,
                                                   float* __restrict__ out)
{
    __shared__ float red[4][64];
    int g = blockIdx.x;
    int c = threadIdx.x & 63, s = threadIdx.x >> 6;
    const float* hb = h + (size_t)g * PPG * 64;
    float m = -FLT_MAX;
    for (int p = s; p < PPG; p += 4) m = fmaxf(m, hb[p*64 + c]);
    red[s][c] = m;
    __syncthreads();
    if (threadIdx.x < 64)
        red[0][c] = fmaxf(fmaxf(red[0][c], red[1][c]), fmaxf(red[2][c], red[3][c]));
    __syncthreads();
    if (threadIdx.x < 6) {
        float acc = regb[threadIdx.x];
#pragma unroll
        for (int cc = 0; cc < 64; cc++)
            acc = fmaf(red[0][cc], regW[cc*6 + threadIdx.x], acc);
        out[g*6 + threadIdx.x] = acc;
    }
}

// ---------------- launch ----------------
extern "C" void kernel_launch(void* const* d_in, const int* in_sizes, int n_in,
                              void* d_out, int out_size)
{
    (void)in_sizes; (void)n_in; (void)out_size;
    const float* pos  = (const float*)d_in[1];
    const float* c1W1 = (const float*)d_in[3];
    const float* c1b1 = (const float*)d_in[4];
    const float* c1W2 = (const float*)d_in[5];
    const float* c1b2 = (const float*)d_in[6];
    const float* c2W1 = (const float*)d_in[7];
    const float* c2b1 = (const float*)d_in[8];
    const float* c2W2 = (const float*)d_in[9];
    const float* c2b2 = (const float*)d_in[10];
    const float* c3W1 = (const float*)d_in[11];
    const float* c3b1 = (const float*)d_in[12];
    const float* c3W2 = (const float*)d_in[13];
    const float* c3b2 = (const float*)d_in[14];
    const float* regW = (const float*)d_in[15];
    const float* regb = (const float*)d_in[16];
    float* out = (float*)d_out;

    float *h1, *h2, *ab;
    cudaGetSymbolAddress((void**)&h1, g_h1);
    cudaGetSymbolAddress((void**)&h2, g_h2);
    cudaGetSymbolAddress((void**)&ab, g_ab);
    cudaFuncSetAttribute((const void*)ab64_mma_kernel, cudaFuncAttributeMaxDynamicSharedMemorySize, ABM_SMEM);
    cudaFuncSetAttribute((const void*)edge_mma_kernel<6,8>, cudaFuncAttributeMaxDynamicSharedMemorySize, EDGE_SMEM);
    cudaFuncSetAttribute((const void*)edge_mma_kernel<4,4>, cudaFuncAttributeMaxDynamicSharedMemorySize, EDGE_SMEM);
    cudaFuncSetAttribute((const void*)edge_mma_kernel<3,4>, cudaFuncAttributeMaxDynamicSharedMemorySize, EDGE_SMEM);

    knn_kernel<<<BGRAPH * 4, 128>>>(pos);
    w2split_kernel<<<96, 128>>>(c1W2, c2W2, c3W2);
    w1split_kernel<<<128, 128>>>(c2W1, c3W1);
    ab3_kernel<<<NPTS * 64 / 256, 256>>>(pos, c1W1, c1b1);
    edge_mma_kernel<6,8><<<NPTS/32, 256, EDGE_SMEM>>>(pos, c1W1 + 6*64,   c1b2, 0, h1);
    ab64_mma_kernel<<<NPTS/128, 256, ABM_SMEM>>>(h1, c2b1, 0, ab);
    edge_mma_kernel<4,4><<<NPTS/64, 256, EDGE_SMEM>>>(pos, c2W1 + 128*64, c2b2, 1, h2);
    ab64_mma_kernel<<<NPTS/128, 256, ABM_SMEM>>>(h2, c3b1, 1, ab);
    edge_mma_kernel<3,4><<<NPTS/64, 256, EDGE_SMEM>>>(pos, c3W1 + 128*64, c3b2, 2, h1);
    pool_kernel<<<BGRAPH, 256>>>(h1, regW, regb, out);
}

// round 9
// speedup vs baseline: 1.7821x; 1.0386x over previous
#include <cuda_runtime.h>
#include <cuda_bf16.h>
#include <float.h>
#include <stdint.h>

#define NPTS   65536
#define BGRAPH 64
#define PPG    1024

// ---------------- scratch (device globals; no allocation) ----------------
__device__ int    g_knn[NPTS * 8];            // 6 real + 2 pad (dup of nn0)
__device__ float  g_ab [NPTS * 128];          // layers 2/3: a (+b1) cols 0..63, b cols 64..127
__device__ float  g_h1 [NPTS * 64];
__device__ float  g_h2 [NPTS * 64];
__device__ float4 g_pos4[NPTS];               // packed positions (x,y,z,0)
__device__ __align__(16) __nv_bfloat16 g_w2s[3][2][4096];  // [layer][hi/lo] swizzled W2^T [n=64][k=64]
__device__ __align__(16) __nv_bfloat16 g_w1s[2][2][8192];  // [layer][hi/lo] swizzled W1ab^T [n=128][k=64]

// ---------------- helpers (base-ISA: ldmatrix + mma.sync, sm_80+) ----------------
__device__ __forceinline__ uint32_t smem_u32(const void* p) {
    uint32_t a;
    asm("{ .reg .u64 t; cvta.to.shared.u64 t, %1; cvt.u32.u64 %0, t; }" : "=r"(a) : "l"(p));
    return a;
}
__device__ __forceinline__ uint32_t sw128(uint32_t off) { return off ^ ((off >> 3) & 0x70); }
__device__ __forceinline__ uint32_t pack_bf(__nv_bfloat16 a, __nv_bfloat16 b) {
    uint16_t ua = __bfloat16_as_ushort(a), ub = __bfloat16_as_ushort(b);
    return (uint32_t)ua | ((uint32_t)ub << 16);
}
__device__ __forceinline__ void ldsm_x4(uint32_t* r, uint32_t addr) {
    asm volatile("ldmatrix.sync.aligned.m8n8.x4.shared.b16 {%0,%1,%2,%3}, [%4];"
                 : "=r"(r[0]), "=r"(r[1]), "=r"(r[2]), "=r"(r[3]) : "r"(addr));
}
__device__ __forceinline__ void mma_16816(float* d, const uint32_t* a, const uint32_t* b) {
    asm volatile("mma.sync.aligned.m16n8k16.row.col.f32.bf16.bf16.f32 "
                 "{%0,%1,%2,%3}, {%4,%5,%6,%7}, {%8,%9}, {%0,%1,%2,%3};"
                 : "+f"(d[0]), "+f"(d[1]), "+f"(d[2]), "+f"(d[3])
                 : "r"(a[0]), "r"(a[1]), "r"(a[2]), "r"(a[3]), "r"(b[0]), "r"(b[1]));
}
__device__ __forceinline__ void split_store(char* hiC, char* loC, uint32_t sw,
                                            float4 v0, float4 v1) {
    __nv_bfloat16 q0 = __float2bfloat16(v0.x), q1 = __float2bfloat16(v0.y);
    __nv_bfloat16 q2 = __float2bfloat16(v0.z), q3 = __float2bfloat16(v0.w);
    __nv_bfloat16 q4 = __float2bfloat16(v1.x), q5 = __float2bfloat16(v1.y);
    __nv_bfloat16 q6 = __float2bfloat16(v1.z), q7 = __float2bfloat16(v1.w);
    __nv_bfloat16 s0 = __float2bfloat16(v0.x - __bfloat162float(q0));
    __nv_bfloat16 s1 = __float2bfloat16(v0.y - __bfloat162float(q1));
    __nv_bfloat16 s2 = __float2bfloat16(v0.z - __bfloat162float(q2));
    __nv_bfloat16 s3 = __float2bfloat16(v0.w - __bfloat162float(q3));
    __nv_bfloat16 s4 = __float2bfloat16(v1.x - __bfloat162float(q4));
    __nv_bfloat16 s5 = __float2bfloat16(v1.y - __bfloat162float(q5));
    __nv_bfloat16 s6 = __float2bfloat16(v1.z - __bfloat162float(q6));
    __nv_bfloat16 s7 = __float2bfloat16(v1.w - __bfloat162float(q7));
    *(uint4*)(hiC + sw) = make_uint4(pack_bf(q0,q1), pack_bf(q2,q3), pack_bf(q4,q5), pack_bf(q6,q7));
    *(uint4*)(loC + sw) = make_uint4(pack_bf(s0,s1), pack_bf(s2,s3), pack_bf(s4,s5), pack_bf(s6,s7));
}

// ---------------- kNN (k=6, 2 queries/thread, 4 blocks/graph; matches jax top_k ties) ----------------
__global__ __launch_bounds__(128) void knn_kernel(const float* __restrict__ pos)
{
    __shared__ float4 cand[128];
    int graph = blockIdx.x >> 2;
    int q0 = graph * PPG + ((blockIdx.x & 3) << 8) + threadIdx.x;
    int q1 = q0 + 128;
    float ax = pos[3*q0], ay = pos[3*q0+1], az = pos[3*q0+2];
    float bx = pos[3*q1], by = pos[3*q1+1], bz = pos[3*q1+2];
    float as = ax*ax + ay*ay + az*az;
    float bs = bx*bx + by*by + bz*bz;
    g_pos4[q0] = make_float4(ax, ay, az, 0.f);
    g_pos4[q1] = make_float4(bx, by, bz, 0.f);
    float ad[6], bd[6]; int ai[6], bi[6];
#pragma unroll
    for (int t = 0; t < 6; t++) { ad[t] = FLT_MAX; ai[t] = 0; bd[t] = FLT_MAX; bi[t] = 0; }
    for (int tile = 0; tile < PPG; tile += 128) {
        int c = graph * PPG + tile + threadIdx.x;
        float cx = pos[3*c], cy = pos[3*c+1], cz = pos[3*c+2];
        cand[threadIdx.x] = make_float4(cx, cy, cz, cx*cx + cy*cy + cz*cz);
        __syncthreads();
#pragma unroll 4
        for (int u = 0; u < 128; u++) {
            float4 p = cand[u];
            int cidx = graph*PPG + tile + u;
            float d2a = as + p.w - 2.0f*(ax*p.x + ay*p.y + az*p.z);
            float d2b = bs + p.w - 2.0f*(bx*p.x + by*p.y + bz*p.z);
            if (d2a < ad[5]) {
                ad[5] = d2a; ai[5] = cidx;
#pragma unroll
                for (int t = 5; t > 0; t--)
                    if (ad[t] < ad[t-1]) {
                        float td = ad[t]; ad[t] = ad[t-1]; ad[t-1] = td;
                        int   ti = ai[t]; ai[t] = ai[t-1]; ai[t-1] = ti;
                    }
            }
            if (d2b < bd[5]) {
                bd[5] = d2b; bi[5] = cidx;
#pragma unroll
                for (int t = 5; t > 0; t--)
                    if (bd[t] < bd[t-1]) {
                        float td = bd[t]; bd[t] = bd[t-1]; bd[t-1] = td;
                        int   ti = bi[t]; bi[t] = bi[t-1]; bi[t-1] = ti;
                    }
            }
        }
        __syncthreads();
    }
#pragma unroll
    for (int t = 0; t < 6; t++) { g_knn[q0*8 + t] = ai[t]; g_knn[q1*8 + t] = bi[t]; }
    g_knn[q0*8 + 6] = ai[0]; g_knn[q0*8 + 7] = ai[0];
    g_knn[q1*8 + 6] = bi[0]; g_knn[q1*8 + 7] = bi[0];
}

// ---------------- W2^T bf16 split into swizzled B tiles (all 3 layers) ----------------
__global__ __launch_bounds__(128) void w2split_kernel(const float* __restrict__ W2a,
                                                      const float* __restrict__ W2b,
                                                      const float* __restrict__ W2c)
{
    int t = blockIdx.x * 128 + threadIdx.x;        // 3*4096 threads
    int l = t >> 12, nk = t & 4095;
    int n = nk >> 6, k = nk & 63;
    const float* W2 = (l == 0) ? W2a : ((l == 1) ? W2b : W2c);
    float v = W2[k*64 + n];                        // B^T[n][k] = W2[k][n]
    __nv_bfloat16 hi = __float2bfloat16(v);
    __nv_bfloat16 lo = __float2bfloat16(v - __bfloat162float(hi));
    uint32_t sw = sw128((uint32_t)(n*128 + k*2));
    g_w2s[l][0][sw >> 1] = hi;
    g_w2s[l][1][sw >> 1] = lo;
}

// ---------------- W1ab^T bf16 split, layers 2/3 (n=128 out cols, k=64 in ch) ----------------
__global__ __launch_bounds__(128) void w1split_kernel(const float* __restrict__ W1b,
                                                      const float* __restrict__ W1c)
{
    int t = blockIdx.x * 128 + threadIdx.x;        // 2*8192 threads
    int l = t >> 13, nk = t & 8191;
    int n = nk >> 6, k = nk & 63;
    const float* W1 = l ? W1c : W1b;
    float v = (n < 64) ? W1[k*64 + n] : W1[(64 + k)*64 + (n - 64)];
    __nv_bfloat16 hi = __float2bfloat16(v);
    __nv_bfloat16 lo = __float2bfloat16(v - __bfloat162float(hi));
    uint32_t sw = sw128((uint32_t)(n*128 + k*2));
    g_w1s[l][0][sw >> 1] = hi;
    g_w1s[l][1][sw >> 1] = lo;
}

// ---------------- ab projections, layers 2/3: MMA GEMM 128pts x 128cols x 64ch ----------------
#define ABM_SMEM (65536 + 256)
__global__ __launch_bounds__(256, 2) void ab64_mma_kernel(const float* __restrict__ h,
                                                          const float* __restrict__ b1,
                                                          int layer,
                                                          float* __restrict__ abot)
{
    extern __shared__ char smem_raw[];
    uint32_t su = smem_u32(smem_raw);
    uint32_t abase = (su + 127) & ~127u;
    char* base = smem_raw + (abase - su);
    char* AhiC = base;                        // 128 rows x 128B = 16KB
    char* AloC = base + 16384;
    uint32_t sAhi = abase, sAlo = abase + 16384;
    uint32_t sBhi = abase + 32768, sBlo = abase + 32768 + 16384;

    int tid = threadIdx.x, warp = tid >> 5, lane = tid & 31;
    int pbase = blockIdx.x * 128;

    {
        const uint4* sh = (const uint4*)g_w1s[layer][0];
        const uint4* sl = (const uint4*)g_w1s[layer][1];
        uint4* dh = (uint4*)(base + 32768);
        uint4* dl = (uint4*)(base + 32768 + 16384);
        for (int t = tid; t < 1024; t += 256) { dh[t] = sh[t]; dl[t] = sl[t]; }
    }

    {
        int row = tid >> 1, chb = (tid & 1) * 32;
        const float* hr = h + (size_t)(pbase + row) * 64 + chb;
#pragma unroll
        for (int g = 0; g < 4; g++) {
            float4 v0 = *(const float4*)(hr + g*8);
            float4 v1 = *(const float4*)(hr + g*8 + 4);
            uint32_t sw = sw128((uint32_t)(row*128 + (chb + g*8)*2));
            split_store(AhiC, AloC, sw, v0, v1);
        }
    }
    __syncthreads();

    const int rb = (warp >> 1) * 32;
    const int ch = (warp & 1) * 64;
    const int gn0 = (warp & 1) * 8;
    int acolb = (lane >> 4) * 16;
    uint32_t laddr = (uint32_t)((lane & 7)*128 + ((lane >> 4) & 1)*32 + ((lane >> 3) & 1)*16);

    uint32_t afr[2][4][4];
#pragma unroll
    for (int rt = 0; rt < 2; rt++) {
        uint32_t arow = (uint32_t)((rb + rt*16 + (lane & 15)) * 128);
#pragma unroll
        for (int k = 0; k < 4; k++)
            ldsm_x4(afr[rt][k], sAhi + sw128(arow + k*32 + acolb));
    }

    float d[2][8][4];
#pragma unroll
    for (int rt = 0; rt < 2; rt++)
#pragma unroll
        for (int nt = 0; nt < 8; nt++)
#pragma unroll
            for (int q = 0; q < 4; q++) d[rt][nt][q] = 0.f;

#pragma unroll
    for (int nt = 0; nt < 8; nt++) {
        uint32_t bh[4][2], bl[4][2];
#pragma unroll
        for (int kp = 0; kp < 4; kp += 2) {
            uint32_t bo = sw128((uint32_t)((gn0 + nt)*1024 + kp*32) + laddr);
            uint32_t r[4];
            ldsm_x4(r, sBhi + bo);
            bh[kp][0] = r[0]; bh[kp][1] = r[1]; bh[kp+1][0] = r[2]; bh[kp+1][1] = r[3];
            ldsm_x4(r, sBlo + bo);
            bl[kp][0] = r[0]; bl[kp][1] = r[1]; bl[kp+1][0] = r[2]; bl[kp+1][1] = r[3];
        }
#pragma unroll
        for (int rt = 0; rt < 2; rt++)
#pragma unroll
            for (int k = 0; k < 4; k++) mma_16816(d[rt][nt], afr[rt][k], bh[k]);
#pragma unroll
        for (int rt = 0; rt < 2; rt++)
#pragma unroll
            for (int k = 0; k < 4; k++) mma_16816(d[rt][nt], afr[rt][k], bl[k]);
    }
#pragma unroll
    for (int rt = 0; rt < 2; rt++) {
        uint32_t arow = (uint32_t)((rb + rt*16 + (lane & 15)) * 128);
#pragma unroll
        for (int k = 0; k < 4; k++)
            ldsm_x4(afr[rt][k], sAlo + sw128(arow + k*32 + acolb));
    }
#pragma unroll
    for (int nt = 0; nt < 8; nt++) {
        uint32_t bh[4][2];
#pragma unroll
        for (int kp = 0; kp < 4; kp += 2) {
            uint32_t bo = sw128((uint32_t)((gn0 + nt)*1024 + kp*32) + laddr);
            uint32_t r[4];
            ldsm_x4(r, sBhi + bo);
            bh[kp][0] = r[0]; bh[kp][1] = r[1]; bh[kp+1][0] = r[2]; bh[kp+1][1] = r[3];
        }
#pragma unroll
        for (int rt = 0; rt < 2; rt++)
#pragma unroll
            for (int k = 0; k < 4; k++) mma_16816(d[rt][nt], afr[rt][k], bh[k]);
    }

#pragma unroll
    for (int rt = 0; rt < 2; rt++) {
        int r0 = rb + rt*16 + (lane >> 2);
#pragma unroll
        for (int nt = 0; nt < 8; nt++) {
            int col = ch + nt*8 + (lane & 3)*2;
            float bx = 0.f, by = 0.f;
            if (col < 64) { bx = b1[col]; by = b1[col + 1]; }
            *(float2*)&abot[(size_t)(pbase + r0)*128 + col] =
                make_float2(d[rt][nt][0] + bx, d[rt][nt][1] + by);
            *(float2*)&abot[(size_t)(pbase + r0 + 8)*128 + col] =
                make_float2(d[rt][nt][2] + bx, d[rt][nt][3] + by);
        }
    }
}

// ---------------- shared phase-B + epilogue for edge kernels ----------------
template<int SLOTS>
__device__ __forceinline__ void edge_phaseB(
    uint32_t sAhi, uint32_t sAlo, uint32_t sBhi, uint32_t sBlo,
    const float* __restrict__ b2, float* __restrict__ hout,
    int warp, int lane, int PTS)
{
    const int rb = (warp >> 1) * 64;
    const int ch = (warp & 1) * 32;
    const int gn0 = (warp & 1) * 4;
    int acolb = (lane >> 4) * 16;

    uint32_t bh[4][4][2], bl[4][4][2];
    {
        uint32_t laddr = (uint32_t)((lane & 7)*128 + ((lane >> 4) & 1)*32 + ((lane >> 3) & 1)*16);
#pragma unroll
        for (int nt = 0; nt < 4; nt++)
#pragma unroll
            for (int kp = 0; kp < 4; kp += 2) {
                uint32_t boff = sw128((uint32_t)((gn0 + nt)*1024 + kp*32) + laddr);
                uint32_t r[4];
                ldsm_x4(r, sBhi + boff);
                bh[nt][kp][0] = r[0]; bh[nt][kp][1] = r[1];
                bh[nt][kp+1][0] = r[2]; bh[nt][kp+1][1] = r[3];
                ldsm_x4(r, sBlo + boff);
                bl[nt][kp][0] = r[0]; bl[nt][kp][1] = r[1];
                bl[nt][kp+1][0] = r[2]; bl[nt][kp+1][1] = r[3];
            }
    }

#pragma unroll
    for (int rt = 0; rt < 4; rt++) {
        float d[4][4];
#pragma unroll
        for (int nt = 0; nt < 4; nt++)
#pragma unroll
            for (int q = 0; q < 4; q++) d[nt][q] = 0.f;

        uint32_t afr[4][4];
        uint32_t arow_off = (uint32_t)((rb + rt*16 + (lane & 15)) * 128);
#pragma unroll
        for (int k = 0; k < 4; k++)
            ldsm_x4(afr[k], sAhi + sw128(arow_off + k*32 + acolb));

#pragma unroll
        for (int nt = 0; nt < 4; nt++)
#pragma unroll
            for (int k = 0; k < 4; k++) mma_16816(d[nt], afr[k], bh[nt][k]);
#pragma unroll
        for (int nt = 0; nt < 4; nt++)
#pragma unroll
            for (int k = 0; k < 4; k++) mma_16816(d[nt], afr[k], bl[nt][k]);
#pragma unroll
        for (int k = 0; k < 4; k++)
            ldsm_x4(afr[k], sAlo + sw128(arow_off + k*32 + acolb));
#pragma unroll
        for (int nt = 0; nt < 4; nt++)
#pragma unroll
            for (int k = 0; k < 4; k++) mma_16816(d[nt], afr[k], bh[nt][k]);

        if (SLOTS == 8) {
            int pA = blockIdx.x * PTS + (warp >> 1) * 8 + rt * 2;
#pragma unroll
            for (int nt = 0; nt < 4; nt++) {
                float m0 = d[nt][0], m1 = d[nt][1], m2 = d[nt][2], m3 = d[nt][3];
#pragma unroll
                for (int s = 4; s <= 16; s <<= 1) {
                    m0 = fmaxf(m0, __shfl_xor_sync(0xffffffffu, m0, s));
                    m1 = fmaxf(m1, __shfl_xor_sync(0xffffffffu, m1, s));
                    m2 = fmaxf(m2, __shfl_xor_sync(0xffffffffu, m2, s));
                    m3 = fmaxf(m3, __shfl_xor_sync(0xffffffffu, m3, s));
                }
                int col = ch + nt*8 + (lane & 3)*2;
                if (lane < 4) {
                    float2 o = make_float2(fmaxf(m0 + b2[col], 0.f), fmaxf(m1 + b2[col+1], 0.f));
                    *(float2*)&hout[(size_t)pA*64 + col] = o;
                } else if (lane < 8) {
                    float2 o = make_float2(fmaxf(m2 + b2[col], 0.f), fmaxf(m3 + b2[col+1], 0.f));
                    *(float2*)&hout[(size_t)(pA + 1)*64 + col] = o;
                }
            }
        } else {
            int pBse = blockIdx.x * PTS + (warp >> 1) * 16 + rt * 4;
#pragma unroll
            for (int nt = 0; nt < 4; nt++) {
                float m0 = d[nt][0], m1 = d[nt][1], m2 = d[nt][2], m3 = d[nt][3];
#pragma unroll
                for (int s = 4; s <= 8; s <<= 1) {
                    m0 = fmaxf(m0, __shfl_xor_sync(0xffffffffu, m0, s));
                    m1 = fmaxf(m1, __shfl_xor_sync(0xffffffffu, m1, s));
                    m2 = fmaxf(m2, __shfl_xor_sync(0xffffffffu, m2, s));
                    m3 = fmaxf(m3, __shfl_xor_sync(0xffffffffu, m3, s));
                }
                int col = ch + nt*8 + (lane & 3)*2;
                if ((lane & 15) < 4) {
                    int g = lane >> 4;
                    float2 o0 = make_float2(fmaxf(m0 + b2[col], 0.f), fmaxf(m1 + b2[col+1], 0.f));
                    float2 o1 = make_float2(fmaxf(m2 + b2[col], 0.f), fmaxf(m3 + b2[col+1], 0.f));
                    *(float2*)&hout[(size_t)(pBse + g)*64 + col]     = o0;
                    *(float2*)&hout[(size_t)(pBse + 2 + g)*64 + col] = o1;
                }
            }
        }
    }
}

// ---------------- edge layer 1: inline pos projections (no g_ab) ----------------
#define EDGE_SMEM (65536 + 16384 + 256)
__global__ __launch_bounds__(256, 2) void edge1_mma_kernel(
    const float* __restrict__ W1,      // [9][64]: rows 0-2 pos_i, 3-5 pos_j, 6-8 rel
    const float* __restrict__ b1,
    const float* __restrict__ b2,
    float* __restrict__ hout)
{
    constexpr int PTS = 32;            // SLOTS = 8
    extern __shared__ char smem_raw[];
    uint32_t su = smem_u32(smem_raw);
    uint32_t abase = (su + 127) & ~127u;
    char* base = smem_raw + (abase - su);
    char* AhiC = base;
    char* AloC = base + 32768;
    uint32_t sAhi = abase, sAlo = abase + 32768;
    uint32_t sBhi = abase + 65536, sBlo = abase + 65536 + 8192;

    int tid = threadIdx.x, warp = tid >> 5, lane = tid & 31;

    {
        const uint4* sh = (const uint4*)g_w2s[0][0];
        const uint4* sl = (const uint4*)g_w2s[0][1];
        uint4* dh = (uint4*)(base + 65536);
        uint4* dl = (uint4*)(base + 65536 + 8192);
        for (int t = tid; t < 512; t += 256) { dh[t] = sh[t]; dl[t] = sl[t]; }
    }

    // phase A: fully inline. lane -> channels (2*lane, 2*lane+1)
    {
        int lane2 = lane * 2;
        float wa0x=W1[lane2],       wa0y=W1[lane2+1];
        float wa1x=W1[64+lane2],    wa1y=W1[64+lane2+1];
        float wa2x=W1[128+lane2],   wa2y=W1[128+lane2+1];
        float wb0x=W1[192+lane2],   wb0y=W1[192+lane2+1];
        float wb1x=W1[256+lane2],   wb1y=W1[256+lane2+1];
        float wb2x=W1[320+lane2],   wb2y=W1[320+lane2+1];
        float wr0x=W1[384+lane2],   wr0y=W1[384+lane2+1];
        float wr1x=W1[448+lane2],   wr1y=W1[448+lane2+1];
        float wr2x=W1[512+lane2],   wr2y=W1[512+lane2+1];
        float b1x=b1[lane2], b1y=b1[lane2+1];
#pragma unroll
        for (int pp = 0; pp < 4; pp++) {         // PPW = 32/8
            int lp = warp * 4 + pp;
            int i = blockIdx.x * PTS + lp;
            float4 pi = g_pos4[i];
            float ax = fmaf(pi.x, wa0x, fmaf(pi.y, wa1x, fmaf(pi.z, wa2x, b1x)));
            float ay = fmaf(pi.x, wa0y, fmaf(pi.y, wa1y, fmaf(pi.z, wa2y, b1y)));
            int rowbase = lp * 8;
#pragma unroll
            for (int slot = 0; slot < 8; slot++) {   // pads already dup nn0
                int j = g_knn[i*8 + slot];
                float4 pj = g_pos4[j];
                float rx = pj.x - pi.x, ry = pj.y - pi.y, rz = pj.z - pi.z;
                float h0 = ax;
                h0 = fmaf(pj.x, wb0x, h0); h0 = fmaf(pj.y, wb1x, h0); h0 = fmaf(pj.z, wb2x, h0);
                h0 = fmaf(rx, wr0x, h0);   h0 = fmaf(ry, wr1x, h0);   h0 = fmaf(rz, wr2x, h0);
                float h1 = ay;
                h1 = fmaf(pj.x, wb0y, h1); h1 = fmaf(pj.y, wb1y, h1); h1 = fmaf(pj.z, wb2y, h1);
                h1 = fmaf(rx, wr0y, h1);   h1 = fmaf(ry, wr1y, h1);   h1 = fmaf(rz, wr2y, h1);
                h0 = fmaxf(h0, 0.f); h1 = fmaxf(h1, 0.f);
                __nv_bfloat16 q0 = __float2bfloat16(h0), q1 = __float2bfloat16(h1);
                __nv_bfloat16 s0 = __float2bfloat16(h0 - __bfloat162float(q0));
                __nv_bfloat16 s1 = __float2bfloat16(h1 - __bfloat162float(q1));
                uint32_t sw = sw128((uint32_t)((rowbase + slot)*128 + lane2*2));
                *(uint32_t*)(AhiC + sw) = pack_bf(q0, q1);
                *(uint32_t*)(AloC + sw) = pack_bf(s0, s1);
            }
        }
    }
    __syncthreads();
    edge_phaseB<8>(sAhi, sAlo, sBhi, sBlo, b2, hout, warp, lane, PTS);
}

// ---------------- edge layers 2/3: gather a/b from g_ab ----------------
template<int K, int SLOTS>
__global__ __launch_bounds__(256, 2) void edge_mma_kernel(
    const float* __restrict__ W1rel,
    const float* __restrict__ b2,
    int layer,
    float* __restrict__ hout)
{
    constexpr int PTS = 256 / SLOTS;
    constexpr int PPW = PTS / 8;
    extern __shared__ char smem_raw[];
    uint32_t su = smem_u32(smem_raw);
    uint32_t abase = (su + 127) & ~127u;
    char* base = smem_raw + (abase - su);
    char* AhiC = base;
    char* AloC = base + 32768;
    uint32_t sAhi = abase, sAlo = abase + 32768;
    uint32_t sBhi = abase + 65536, sBlo = abase + 65536 + 8192;

    int tid = threadIdx.x, warp = tid >> 5, lane = tid & 31;

    {
        const uint4* sh = (const uint4*)g_w2s[layer][0];
        const uint4* sl = (const uint4*)g_w2s[layer][1];
        uint4* dh = (uint4*)(base + 65536);
        uint4* dl = (uint4*)(base + 65536 + 8192);
        for (int t = tid; t < 512; t += 256) { dh[t] = sh[t]; dl[t] = sl[t]; }
    }

    {
        int lane2 = lane * 2;
        float u0x = W1rel[lane2],       u0y = W1rel[lane2 + 1];
        float u1x = W1rel[64 + lane2],  u1y = W1rel[64 + lane2 + 1];
        float u2x = W1rel[128 + lane2], u2y = W1rel[128 + lane2 + 1];
#pragma unroll
        for (int pp = 0; pp < PPW; pp++) {
            int lp = warp * PPW + pp;
            int i = blockIdx.x * PTS + lp;
            float2 a = *(const float2*)&g_ab[(size_t)i*128 + lane2];
            float4 pi = g_pos4[i];
            int rowbase = lp * SLOTS;
#pragma unroll
            for (int slot = 0; slot < SLOTS; slot++) {
                int j = g_knn[i*8 + (slot < K ? slot : 0)];
                float4 pj = g_pos4[j];
                float2 b = *(const float2*)&g_ab[(size_t)j*128 + 64 + lane2];
                float rx = pj.x - pi.x, ry = pj.y - pi.y, rz = pj.z - pi.z;
                float h0 = fmaxf(fmaf(rx, u0x, fmaf(ry, u1x, fmaf(rz, u2x, a.x + b.x))), 0.f);
                float h1 = fmaxf(fmaf(rx, u0y, fmaf(ry, u1y, fmaf(rz, u2y, a.y + b.y))), 0.f);
                __nv_bfloat16 q0 = __float2bfloat16(h0), q1 = __float2bfloat16(h1);
                __nv_bfloat16 s0 = __float2bfloat16(h0 - __bfloat162float(q0));
                __nv_bfloat16 s1 = __float2bfloat16(h1 - __bfloat162float(q1));
                uint32_t sw = sw128((uint32_t)((rowbase + slot)*128 + lane2*2));
                *(uint32_t*)(AhiC + sw) = pack_bf(q0, q1);
                *(uint32_t*)(AloC + sw) = pack_bf(s0, s1);
            }
        }
    }
    __syncthreads();
    edge_phaseB<SLOTS>(sAhi, sAlo, sBhi, sBlo, b2, hout, warp, lane, PTS);
}

// ---------------- global max pool + regression head ----------------
__global__ __launch_bounds__(256) void pool_kernel(const float* __restrict__ h,
                                                   const float* __restrict__ regW,
                                                   const float* __restrict__ regb,
                                                   float* __restrict__ out)
{
    __shared__ float red[4][64];
    int g = blockIdx.x;
    int c = threadIdx.x & 63, s = threadIdx.x >> 6;
    const float* hb = h + (size_t)g * PPG * 64;
    float m = -FLT_MAX;
    for (int p = s; p < PPG; p += 4) m = fmaxf(m, hb[p*64 + c]);
    red[s][c] = m;
    __syncthreads();
    if (threadIdx.x < 64)
        red[0][c] = fmaxf(fmaxf(red[0][c], red[1][c]), fmaxf(red[2][c], red[3][c]));
    __syncthreads();
    if (threadIdx.x < 6) {
        float acc = regb[threadIdx.x];
#pragma unroll
        for (int cc = 0; cc < 64; cc++)
            acc = fmaf(red[0][cc], regW[cc*6 + threadIdx.x], acc);
        out[g*6 + threadIdx.x] = acc;
    }
}

// ---------------- launch ----------------
extern "C" void kernel_launch(void* const* d_in, const int* in_sizes, int n_in,
                              void* d_out, int out_size)
{
    (void)in_sizes; (void)n_in; (void)out_size;
    const float* pos  = (const float*)d_in[1];
    const float* c1W1 = (const float*)d_in[3];
    const float* c1b1 = (const float*)d_in[4];
    const float* c1W2 = (const float*)d_in[5];
    const float* c1b2 = (const float*)d_in[6];
    const float* c2W1 = (const float*)d_in[7];
    const float* c2b1 = (const float*)d_in[8];
    const float* c2W2 = (const float*)d_in[9];
    const float* c2b2 = (const float*)d_in[10];
    const float* c3W1 = (const float*)d_in[11];
    const float* c3b1 = (const float*)d_in[12];
    const float* c3W2 = (const float*)d_in[13];
    const float* c3b2 = (const float*)d_in[14];
    const float* regW = (const float*)d_in[15];
    const float* regb = (const float*)d_in[16];
    float* out = (float*)d_out;

    float *h1, *h2, *ab;
    cudaGetSymbolAddress((void**)&h1, g_h1);
    cudaGetSymbolAddress((void**)&h2, g_h2);
    cudaGetSymbolAddress((void**)&ab, g_ab);
    cudaFuncSetAttribute((const void*)ab64_mma_kernel, cudaFuncAttributeMaxDynamicSharedMemorySize, ABM_SMEM);
    cudaFuncSetAttribute((const void*)edge1_mma_kernel, cudaFuncAttributeMaxDynamicSharedMemorySize, EDGE_SMEM);
    cudaFuncSetAttribute((const void*)edge_mma_kernel<4,4>, cudaFuncAttributeMaxDynamicSharedMemorySize, EDGE_SMEM);
    cudaFuncSetAttribute((const void*)edge_mma_kernel<3,4>, cudaFuncAttributeMaxDynamicSharedMemorySize, EDGE_SMEM);

    knn_kernel<<<BGRAPH * 4, 128>>>(pos);
    w2split_kernel<<<96, 128>>>(c1W2, c2W2, c3W2);
    w1split_kernel<<<128, 128>>>(c2W1, c3W1);
    edge1_mma_kernel<<<NPTS/32, 256, EDGE_SMEM>>>(c1W1, c1b1, c1b2, h1);
    ab64_mma_kernel<<<NPTS/128, 256, ABM_SMEM>>>(h1, c2b1, 0, ab);
    edge_mma_kernel<4,4><<<NPTS/64, 256, EDGE_SMEM>>>(c2W1 + 128*64, c2b2, 1, h2);
    ab64_mma_kernel<<<NPTS/128, 256, ABM_SMEM>>>(h2, c3b1, 1, ab);
    edge_mma_kernel<3,4><<<NPTS/64, 256, EDGE_SMEM>>>(c3W1 + 128*64, c3b2, 2, h1);
    pool_kernel<<<BGRAPH, 256>>>(h1, regW, regb, out);
}

// round 10
// speedup vs baseline: 2.2912x; 1.2857x over previous
#include <cuda_runtime.h>
#include <cuda_fp16.h>
#include <float.h>
#include <stdint.h>

#define NPTS   65536
#define BGRAPH 64
#define PPG    1024

// ---------------- scratch (device globals; no allocation) ----------------
__device__ int    g_knn[NPTS * 8];            // 6 real + 2 pad (dup of nn0)
__device__ float  g_ab [NPTS * 128];          // layers 2/3: a (+b1) cols 0..63, b cols 64..127
__device__ float  g_h1 [NPTS * 64];
__device__ float  g_h2 [NPTS * 64];
__device__ float4 g_pos4[NPTS];               // packed positions (x,y,z,0)
__device__ __align__(16) __half g_w2s[3][4096];  // [layer] swizzled fp16 W2^T [n=64][k=64]
__device__ __align__(16) __half g_w1s[2][8192];  // [layer] swizzled fp16 W1ab^T [n=128][k=64]

// ---------------- helpers (base-ISA: ldmatrix + mma.sync, sm_80+) ----------------
__device__ __forceinline__ uint32_t smem_u32(const void* p) {
    uint32_t a;
    asm("{ .reg .u64 t; cvta.to.shared.u64 t, %1; cvt.u32.u64 %0, t; }" : "=r"(a) : "l"(p));
    return a;
}
__device__ __forceinline__ uint32_t sw128(uint32_t off) { return off ^ ((off >> 3) & 0x70); }
__device__ __forceinline__ uint32_t pack_h2(float a, float b) {
    __half2 h = __floats2half2_rn(a, b);
    return *reinterpret_cast<uint32_t*>(&h);
}
__device__ __forceinline__ void ldsm_x4(uint32_t* r, uint32_t addr) {
    asm volatile("ldmatrix.sync.aligned.m8n8.x4.shared.b16 {%0,%1,%2,%3}, [%4];"
                 : "=r"(r[0]), "=r"(r[1]), "=r"(r[2]), "=r"(r[3]) : "r"(addr));
}
__device__ __forceinline__ void mma_16816(float* d, const uint32_t* a, const uint32_t* b) {
    asm volatile("mma.sync.aligned.m16n8k16.row.col.f32.f16.f16.f32 "
                 "{%0,%1,%2,%3}, {%4,%5,%6,%7}, {%8,%9}, {%0,%1,%2,%3};"
                 : "+f"(d[0]), "+f"(d[1]), "+f"(d[2]), "+f"(d[3])
                 : "r"(a[0]), "r"(a[1]), "r"(a[2]), "r"(a[3]), "r"(b[0]), "r"(b[1]));
}

// ---------------- kNN (k=6, 2 queries/thread, 4 blocks/graph; matches jax top_k ties) ----------------
__global__ __launch_bounds__(128) void knn_kernel(const float* __restrict__ pos)
{
    __shared__ float4 cand[128];
    int graph = blockIdx.x >> 2;
    int q0 = graph * PPG + ((blockIdx.x & 3) << 8) + threadIdx.x;
    int q1 = q0 + 128;
    float ax = pos[3*q0], ay = pos[3*q0+1], az = pos[3*q0+2];
    float bx = pos[3*q1], by = pos[3*q1+1], bz = pos[3*q1+2];
    float as = ax*ax + ay*ay + az*az;
    float bs = bx*bx + by*by + bz*bz;
    g_pos4[q0] = make_float4(ax, ay, az, 0.f);
    g_pos4[q1] = make_float4(bx, by, bz, 0.f);
    float ad[6], bd[6]; int ai[6], bi[6];
#pragma unroll
    for (int t = 0; t < 6; t++) { ad[t] = FLT_MAX; ai[t] = 0; bd[t] = FLT_MAX; bi[t] = 0; }
    for (int tile = 0; tile < PPG; tile += 128) {
        int c = graph * PPG + tile + threadIdx.x;
        float cx = pos[3*c], cy = pos[3*c+1], cz = pos[3*c+2];
        cand[threadIdx.x] = make_float4(cx, cy, cz, cx*cx + cy*cy + cz*cz);
        __syncthreads();
#pragma unroll 4
        for (int u = 0; u < 128; u++) {
            float4 p = cand[u];
            int cidx = graph*PPG + tile + u;
            float d2a = as + p.w - 2.0f*(ax*p.x + ay*p.y + az*p.z);
            float d2b = bs + p.w - 2.0f*(bx*p.x + by*p.y + bz*p.z);
            if (d2a < ad[5]) {
                ad[5] = d2a; ai[5] = cidx;
#pragma unroll
                for (int t = 5; t > 0; t--)
                    if (ad[t] < ad[t-1]) {
                        float td = ad[t]; ad[t] = ad[t-1]; ad[t-1] = td;
                        int   ti = ai[t]; ai[t] = ai[t-1]; ai[t-1] = ti;
                    }
            }
            if (d2b < bd[5]) {
                bd[5] = d2b; bi[5] = cidx;
#pragma unroll
                for (int t = 5; t > 0; t--)
                    if (bd[t] < bd[t-1]) {
                        float td = bd[t]; bd[t] = bd[t-1]; bd[t-1] = td;
                        int   ti = bi[t]; bi[t] = bi[t-1]; bi[t-1] = ti;
                    }
            }
        }
        __syncthreads();
    }
#pragma unroll
    for (int t = 0; t < 6; t++) { g_knn[q0*8 + t] = ai[t]; g_knn[q1*8 + t] = bi[t]; }
    g_knn[q0*8 + 6] = ai[0]; g_knn[q0*8 + 7] = ai[0];
    g_knn[q1*8 + 6] = bi[0]; g_knn[q1*8 + 7] = bi[0];
}

// ---------------- W2^T fp16 into swizzled B tiles (all 3 layers) ----------------
__global__ __launch_bounds__(128) void w2split_kernel(const float* __restrict__ W2a,
                                                      const float* __restrict__ W2b,
                                                      const float* __restrict__ W2c)
{
    int t = blockIdx.x * 128 + threadIdx.x;        // 3*4096 threads
    int l = t >> 12, nk = t & 4095;
    int n = nk >> 6, k = nk & 63;
    const float* W2 = (l == 0) ? W2a : ((l == 1) ? W2b : W2c);
    float v = W2[k*64 + n];                        // B^T[n][k] = W2[k][n]
    uint32_t sw = sw128((uint32_t)(n*128 + k*2));
    g_w2s[l][sw >> 1] = __float2half_rn(v);
}

// ---------------- W1ab^T fp16, layers 2/3 (n=128 out cols, k=64 in ch) ----------------
__global__ __launch_bounds__(128) void w1split_kernel(const float* __restrict__ W1b,
                                                      const float* __restrict__ W1c)
{
    int t = blockIdx.x * 128 + threadIdx.x;        // 2*8192 threads
    int l = t >> 13, nk = t & 8191;
    int n = nk >> 6, k = nk & 63;
    const float* W1 = l ? W1c : W1b;
    float v = (n < 64) ? W1[k*64 + n] : W1[(64 + k)*64 + (n - 64)];
    uint32_t sw = sw128((uint32_t)(n*128 + k*2));
    g_w1s[l][sw >> 1] = __float2half_rn(v);
}

// ---------------- ab projections, layers 2/3: fp16 MMA GEMM 128pts x 128cols x 64ch ----------------
#define ABM_SMEM (16384 + 16384 + 256)
__global__ __launch_bounds__(256, 2) void ab64_mma_kernel(const float* __restrict__ h,
                                                          const float* __restrict__ b1,
                                                          int layer,
                                                          float* __restrict__ abot)
{
    extern __shared__ char smem_raw[];
    uint32_t su = smem_u32(smem_raw);
    uint32_t abase = (su + 127) & ~127u;
    char* base = smem_raw + (abase - su);
    char* AC = base;                          // 128 rows x 128B = 16KB
    uint32_t sA = abase, sB = abase + 16384;

    int tid = threadIdx.x, warp = tid >> 5, lane = tid & 31;
    int pbase = blockIdx.x * 128;

    // stage B tile (16KB)
    {
        const uint4* sh = (const uint4*)g_w1s[layer];
        uint4* dh = (uint4*)(base + 16384);
        for (int t = tid; t < 1024; t += 256) dh[t] = sh[t];
    }

    // load + convert A: thread -> row tid>>1, channel half (tid&1)*32
    {
        int row = tid >> 1, chb = (tid & 1) * 32;
        const float* hr = h + (size_t)(pbase + row) * 64 + chb;
#pragma unroll
        for (int g = 0; g < 4; g++) {
            float4 v0 = *(const float4*)(hr + g*8);
            float4 v1 = *(const float4*)(hr + g*8 + 4);
            uint32_t sw = sw128((uint32_t)(row*128 + (chb + g*8)*2));
            *(uint4*)(AC + sw) = make_uint4(pack_h2(v0.x, v0.y), pack_h2(v0.z, v0.w),
                                            pack_h2(v1.x, v1.y), pack_h2(v1.z, v1.w));
        }
    }
    __syncthreads();

    const int rb = (warp >> 1) * 32;
    const int ch = (warp & 1) * 64;
    const int gn0 = (warp & 1) * 8;
    int acolb = (lane >> 4) * 16;
    uint32_t laddr = (uint32_t)((lane & 7)*128 + ((lane >> 4) & 1)*32 + ((lane >> 3) & 1)*16);

    uint32_t afr[2][4][4];
#pragma unroll
    for (int rt = 0; rt < 2; rt++) {
        uint32_t arow = (uint32_t)((rb + rt*16 + (lane & 15)) * 128);
#pragma unroll
        for (int k = 0; k < 4; k++)
            ldsm_x4(afr[rt][k], sA + sw128(arow + k*32 + acolb));
    }

    float d[2][8][4];
#pragma unroll
    for (int rt = 0; rt < 2; rt++)
#pragma unroll
        for (int nt = 0; nt < 8; nt++)
#pragma unroll
            for (int q = 0; q < 4; q++) d[rt][nt][q] = 0.f;

#pragma unroll
    for (int nt = 0; nt < 8; nt++) {
        uint32_t bh[4][2];
#pragma unroll
        for (int kp = 0; kp < 4; kp += 2) {
            uint32_t bo = sw128((uint32_t)((gn0 + nt)*1024 + kp*32) + laddr);
            uint32_t r[4];
            ldsm_x4(r, sB + bo);
            bh[kp][0] = r[0]; bh[kp][1] = r[1]; bh[kp+1][0] = r[2]; bh[kp+1][1] = r[3];
        }
#pragma unroll
        for (int rt = 0; rt < 2; rt++)
#pragma unroll
            for (int k = 0; k < 4; k++) mma_16816(d[rt][nt], afr[rt][k], bh[k]);
    }

    // epilogue: +b1 on cols 0..63 only, store fp32
#pragma unroll
    for (int rt = 0; rt < 2; rt++) {
        int r0 = rb + rt*16 + (lane >> 2);
#pragma unroll
        for (int nt = 0; nt < 8; nt++) {
            int col = ch + nt*8 + (lane & 3)*2;
            float bx = 0.f, by = 0.f;
            if (col < 64) { bx = b1[col]; by = b1[col + 1]; }
            *(float2*)&abot[(size_t)(pbase + r0)*128 + col] =
                make_float2(d[rt][nt][0] + bx, d[rt][nt][1] + by);
            *(float2*)&abot[(size_t)(pbase + r0 + 8)*128 + col] =
                make_float2(d[rt][nt][2] + bx, d[rt][nt][3] + by);
        }
    }
}

// ---------------- shared phase-B + epilogue for edge kernels (single fp16 pass) ----------------
template<int SLOTS>
__device__ __forceinline__ void edge_phaseB(
    uint32_t sA, uint32_t sB,
    const float* __restrict__ b2, float* __restrict__ hout,
    int warp, int lane, int PTS)
{
    const int rb = (warp >> 1) * 64;
    const int ch = (warp & 1) * 32;
    const int gn0 = (warp & 1) * 4;
    int acolb = (lane >> 4) * 16;

    uint32_t bh[4][4][2];
    {
        uint32_t laddr = (uint32_t)((lane & 7)*128 + ((lane >> 4) & 1)*32 + ((lane >> 3) & 1)*16);
#pragma unroll
        for (int nt = 0; nt < 4; nt++)
#pragma unroll
            for (int kp = 0; kp < 4; kp += 2) {
                uint32_t boff = sw128((uint32_t)((gn0 + nt)*1024 + kp*32) + laddr);
                uint32_t r[4];
                ldsm_x4(r, sB + boff);
                bh[nt][kp][0] = r[0]; bh[nt][kp][1] = r[1];
                bh[nt][kp+1][0] = r[2]; bh[nt][kp+1][1] = r[3];
            }
    }

#pragma unroll
    for (int rt = 0; rt < 4; rt++) {
        float d[4][4];
#pragma unroll
        for (int nt = 0; nt < 4; nt++)
#pragma unroll
            for (int q = 0; q < 4; q++) d[nt][q] = 0.f;

        uint32_t afr[4][4];
        uint32_t arow_off = (uint32_t)((rb + rt*16 + (lane & 15)) * 128);
#pragma unroll
        for (int k = 0; k < 4; k++)
            ldsm_x4(afr[k], sA + sw128(arow_off + k*32 + acolb));

#pragma unroll
        for (int nt = 0; nt < 4; nt++)
#pragma unroll
            for (int k = 0; k < 4; k++) mma_16816(d[nt], afr[k], bh[nt][k]);

        if (SLOTS == 8) {
            int pA = blockIdx.x * PTS + (warp >> 1) * 8 + rt * 2;
#pragma unroll
            for (int nt = 0; nt < 4; nt++) {
                float m0 = d[nt][0], m1 = d[nt][1], m2 = d[nt][2], m3 = d[nt][3];
#pragma unroll
                for (int s = 4; s <= 16; s <<= 1) {
                    m0 = fmaxf(m0, __shfl_xor_sync(0xffffffffu, m0, s));
                    m1 = fmaxf(m1, __shfl_xor_sync(0xffffffffu, m1, s));
                    m2 = fmaxf(m2, __shfl_xor_sync(0xffffffffu, m2, s));
                    m3 = fmaxf(m3, __shfl_xor_sync(0xffffffffu, m3, s));
                }
                int col = ch + nt*8 + (lane & 3)*2;
                if (lane < 4) {
                    float2 o = make_float2(fmaxf(m0 + b2[col], 0.f), fmaxf(m1 + b2[col+1], 0.f));
                    *(float2*)&hout[(size_t)pA*64 + col] = o;
                } else if (lane < 8) {
                    float2 o = make_float2(fmaxf(m2 + b2[col], 0.f), fmaxf(m3 + b2[col+1], 0.f));
                    *(float2*)&hout[(size_t)(pA + 1)*64 + col] = o;
                }
            }
        } else {
            int pBse = blockIdx.x * PTS + (warp >> 1) * 16 + rt * 4;
#pragma unroll
            for (int nt = 0; nt < 4; nt++) {
                float m0 = d[nt][0], m1 = d[nt][1], m2 = d[nt][2], m3 = d[nt][3];
#pragma unroll
                for (int s = 4; s <= 8; s <<= 1) {
                    m0 = fmaxf(m0, __shfl_xor_sync(0xffffffffu, m0, s));
                    m1 = fmaxf(m1, __shfl_xor_sync(0xffffffffu, m1, s));
                    m2 = fmaxf(m2, __shfl_xor_sync(0xffffffffu, m2, s));
                    m3 = fmaxf(m3, __shfl_xor_sync(0xffffffffu, m3, s));
                }
                int col = ch + nt*8 + (lane & 3)*2;
                if ((lane & 15) < 4) {
                    int g = lane >> 4;
                    float2 o0 = make_float2(fmaxf(m0 + b2[col], 0.f), fmaxf(m1 + b2[col+1], 0.f));
                    float2 o1 = make_float2(fmaxf(m2 + b2[col], 0.f), fmaxf(m3 + b2[col+1], 0.f));
                    *(float2*)&hout[(size_t)(pBse + g)*64 + col]     = o0;
                    *(float2*)&hout[(size_t)(pBse + 2 + g)*64 + col] = o1;
                }
            }
        }
    }
}

// ---------------- edge layer 1: inline pos projections (no g_ab) ----------------
#define EDGE_SMEM (32768 + 8192 + 256)
__global__ __launch_bounds__(256, 3) void edge1_mma_kernel(
    const float* __restrict__ W1,      // [9][64]: rows 0-2 pos_i, 3-5 pos_j, 6-8 rel
    const float* __restrict__ b1,
    const float* __restrict__ b2,
    float* __restrict__ hout)
{
    constexpr int PTS = 32;            // SLOTS = 8
    extern __shared__ char smem_raw[];
    uint32_t su = smem_u32(smem_raw);
    uint32_t abase = (su + 127) & ~127u;
    char* base = smem_raw + (abase - su);
    char* AC = base;
    uint32_t sA = abase, sB = abase + 32768;

    int tid = threadIdx.x, warp = tid >> 5, lane = tid & 31;

    {
        const uint4* sh = (const uint4*)g_w2s[0];
        uint4* dh = (uint4*)(base + 32768);
        for (int t = tid; t < 512; t += 256) dh[t] = sh[t];
    }

    // phase A: fully inline. lane -> channels (2*lane, 2*lane+1)
    {
        int lane2 = lane * 2;
        float wa0x=W1[lane2],       wa0y=W1[lane2+1];
        float wa1x=W1[64+lane2],    wa1y=W1[64+lane2+1];
        float wa2x=W1[128+lane2],   wa2y=W1[128+lane2+1];
        float wb0x=W1[192+lane2],   wb0y=W1[192+lane2+1];
        float wb1x=W1[256+lane2],   wb1y=W1[256+lane2+1];
        float wb2x=W1[320+lane2],   wb2y=W1[320+lane2+1];
        float wr0x=W1[384+lane2],   wr0y=W1[384+lane2+1];
        float wr1x=W1[448+lane2],   wr1y=W1[448+lane2+1];
        float wr2x=W1[512+lane2],   wr2y=W1[512+lane2+1];
        float b1x=b1[lane2], b1y=b1[lane2+1];
#pragma unroll
        for (int pp = 0; pp < 4; pp++) {
            int lp = warp * 4 + pp;
            int i = blockIdx.x * PTS + lp;
            float4 pi = g_pos4[i];
            float ax = fmaf(pi.x, wa0x, fmaf(pi.y, wa1x, fmaf(pi.z, wa2x, b1x)));
            float ay = fmaf(pi.x, wa0y, fmaf(pi.y, wa1y, fmaf(pi.z, wa2y, b1y)));
            int rowbase = lp * 8;
#pragma unroll
            for (int slot = 0; slot < 8; slot++) {
                int j = g_knn[i*8 + slot];
                float4 pj = g_pos4[j];
                float rx = pj.x - pi.x, ry = pj.y - pi.y, rz = pj.z - pi.z;
                float h0 = ax;
                h0 = fmaf(pj.x, wb0x, h0); h0 = fmaf(pj.y, wb1x, h0); h0 = fmaf(pj.z, wb2x, h0);
                h0 = fmaf(rx, wr0x, h0);   h0 = fmaf(ry, wr1x, h0);   h0 = fmaf(rz, wr2x, h0);
                float h1 = ay;
                h1 = fmaf(pj.x, wb0y, h1); h1 = fmaf(pj.y, wb1y, h1); h1 = fmaf(pj.z, wb2y, h1);
                h1 = fmaf(rx, wr0y, h1);   h1 = fmaf(ry, wr1y, h1);   h1 = fmaf(rz, wr2y, h1);
                h0 = fmaxf(h0, 0.f); h1 = fmaxf(h1, 0.f);
                uint32_t sw = sw128((uint32_t)((rowbase + slot)*128 + lane2*2));
                *(uint32_t*)(AC + sw) = pack_h2(h0, h1);
            }
        }
    }
    __syncthreads();
    edge_phaseB<8>(sA, sB, b2, hout, warp, lane, PTS);
}

// ---------------- edge layers 2/3: gather a/b from g_ab ----------------
template<int K, int SLOTS>
__global__ __launch_bounds__(256, 3) void edge_mma_kernel(
    const float* __restrict__ W1rel,
    const float* __restrict__ b2,
    int layer,
    float* __restrict__ hout)
{
    constexpr int PTS = 256 / SLOTS;
    constexpr int PPW = PTS / 8;
    extern __shared__ char smem_raw[];
    uint32_t su = smem_u32(smem_raw);
    uint32_t abase = (su + 127) & ~127u;
    char* base = smem_raw + (abase - su);
    char* AC = base;
    uint32_t sA = abase, sB = abase + 32768;

    int tid = threadIdx.x, warp = tid >> 5, lane = tid & 31;

    {
        const uint4* sh = (const uint4*)g_w2s[layer];
        uint4* dh = (uint4*)(base + 32768);
        for (int t = tid; t < 512; t += 256) dh[t] = sh[t];
    }

    {
        int lane2 = lane * 2;
        float u0x = W1rel[lane2],       u0y = W1rel[lane2 + 1];
        float u1x = W1rel[64 + lane2],  u1y = W1rel[64 + lane2 + 1];
        float u2x = W1rel[128 + lane2], u2y = W1rel[128 + lane2 + 1];
#pragma unroll
        for (int pp = 0; pp < PPW; pp++) {
            int lp = warp * PPW + pp;
            int i = blockIdx.x * PTS + lp;
            float2 a = *(const float2*)&g_ab[(size_t)i*128 + lane2];
            float4 pi = g_pos4[i];
            int rowbase = lp * SLOTS;
#pragma unroll
            for (int slot = 0; slot < SLOTS; slot++) {
                int j = g_knn[i*8 + (slot < K ? slot : 0)];
                float4 pj = g_pos4[j];
                float2 b = *(const float2*)&g_ab[(size_t)j*128 + 64 + lane2];
                float rx = pj.x - pi.x, ry = pj.y - pi.y, rz = pj.z - pi.z;
                float h0 = fmaxf(fmaf(rx, u0x, fmaf(ry, u1x, fmaf(rz, u2x, a.x + b.x))), 0.f);
                float h1 = fmaxf(fmaf(rx, u0y, fmaf(ry, u1y, fmaf(rz, u2y, a.y + b.y))), 0.f);
                uint32_t sw = sw128((uint32_t)((rowbase + slot)*128 + lane2*2));
                *(uint32_t*)(AC + sw) = pack_h2(h0, h1);
            }
        }
    }
    __syncthreads();
    edge_phaseB<SLOTS>(sA, sB, b2, hout, warp, lane, PTS);
}

// ---------------- global max pool + regression head ----------------
__global__ __launch_bounds__(256) void pool_kernel(const float* __restrict__ h,
                                                   const float* __restrict__ regW,
                                                   const float* __restrict__ regb,
                                                   float* __restrict__ out)
{
    __shared__ float red[4][64];
    int g = blockIdx.x;
    int c = threadIdx.x & 63, s = threadIdx.x >> 6;
    const float* hb = h + (size_t)g * PPG * 64;
    float m = -FLT_MAX;
    for (int p = s; p < PPG; p += 4) m = fmaxf(m, hb[p*64 + c]);
    red[s][c] = m;
    __syncthreads();
    if (threadIdx.x < 64)
        red[0][c] = fmaxf(fmaxf(red[0][c], red[1][c]), fmaxf(red[2][c], red[3][c]));
    __syncthreads();
    if (threadIdx.x < 6) {
        float acc = regb[threadIdx.x];
#pragma unroll
        for (int cc = 0; cc < 64; cc++)
            acc = fmaf(red[0][cc], regW[cc*6 + threadIdx.x], acc);
        out[g*6 + threadIdx.x] = acc;
    }
}

// ---------------- launch ----------------
extern "C" void kernel_launch(void* const* d_in, const int* in_sizes, int n_in,
                              void* d_out, int out_size)
{
    (void)in_sizes; (void)n_in; (void)out_size;
    const float* pos  = (const float*)d_in[1];
    const float* c1W1 = (const float*)d_in[3];
    const float* c1b1 = (const float*)d_in[4];
    const float* c1W2 = (const float*)d_in[5];
    const float* c1b2 = (const float*)d_in[6];
    const float* c2W1 = (const float*)d_in[7];
    const float* c2b1 = (const float*)d_in[8];
    const float* c2W2 = (const float*)d_in[9];
    const float* c2b2 = (const float*)d_in[10];
    const float* c3W1 = (const float*)d_in[11];
    const float* c3b1 = (const float*)d_in[12];
    const float* c3W2 = (const float*)d_in[13];
    const float* c3b2 = (const float*)d_in[14];
    const float* regW = (const float*)d_in[15];
    const float* regb = (const float*)d_in[16];
    float* out = (float*)d_out;

    float *h1, *h2, *ab;
    cudaGetSymbolAddress((void**)&h1, g_h1);
    cudaGetSymbolAddress((void**)&h2, g_h2);
    cudaGetSymbolAddress((void**)&ab, g_ab);
    cudaFuncSetAttribute((const void*)ab64_mma_kernel, cudaFuncAttributeMaxDynamicSharedMemorySize, ABM_SMEM);
    cudaFuncSetAttribute((const void*)edge1_mma_kernel, cudaFuncAttributeMaxDynamicSharedMemorySize, EDGE_SMEM);
    cudaFuncSetAttribute((const void*)edge_mma_kernel<4,4>, cudaFuncAttributeMaxDynamicSharedMemorySize, EDGE_SMEM);
    cudaFuncSetAttribute((const void*)edge_mma_kernel<3,4>, cudaFuncAttributeMaxDynamicSharedMemorySize, EDGE_SMEM);

    knn_kernel<<<BGRAPH * 4, 128>>>(pos);
    w2split_kernel<<<96, 128>>>(c1W2, c2W2, c3W2);
    w1split_kernel<<<128, 128>>>(c2W1, c3W1);
    edge1_mma_kernel<<<NPTS/32, 256, EDGE_SMEM>>>(c1W1, c1b1, c1b2, h1);
    ab64_mma_kernel<<<NPTS/128, 256, ABM_SMEM>>>(h1, c2b1, 0, ab);
    edge_mma_kernel<4,4><<<NPTS/64, 256, EDGE_SMEM>>>(c2W1 + 128*64, c2b2, 1, h2);
    ab64_mma_kernel<<<NPTS/128, 256, ABM_SMEM>>>(h2, c3b1, 1, ab);
    edge_mma_kernel<3,4><<<NPTS/64, 256, EDGE_SMEM>>>(c3W1 + 128*64, c3b2, 2, h1);
    pool_kernel<<<BGRAPH, 256>>>(h1, regW, regb, out);
}

// round 12
// speedup vs baseline: 2.3874x; 1.0420x over previous
#include <cuda_runtime.h>
#include <cuda_fp16.h>
#include <float.h>
#include <stdint.h>

#define NPTS   65536
#define BGRAPH 64
#define PPG    1024

// ---------------- scratch (device globals; no allocation) ----------------
__device__ int    g_knn[NPTS * 8];            // 6 real + 2 pad (dup of nn0)
__device__ float  g_abA[NPTS * 128];          // layer-2 input: a (+b1) cols 0..63, b cols 64..127
__device__ float  g_abB[NPTS * 128];          // layer-3 input (double buffer: fixes cross-block RAW race)
__device__ float  g_h1 [NPTS * 64];           // final layer h (for pool)
__device__ float4 g_pos4[NPTS];               // packed positions (x,y,z,0)
__device__ __align__(16) __half g_w2s[3][4096];  // [layer] swizzled fp16 W2^T [n=64][k=64]
__device__ __align__(16) __half g_w1s[2][8192];  // [layer] swizzled fp16 W1ab^T [n=128][k=64]

// ---------------- helpers (base-ISA: ldmatrix + mma.sync, sm_80+) ----------------
__device__ __forceinline__ uint32_t smem_u32(const void* p) {
    uint32_t a;
    asm("{ .reg .u64 t; cvta.to.shared.u64 t, %1; cvt.u32.u64 %0, t; }" : "=r"(a) : "l"(p));
    return a;
}
__device__ __forceinline__ uint32_t sw128(uint32_t off) { return off ^ ((off >> 3) & 0x70); }
__device__ __forceinline__ uint32_t pack_h2(float a, float b) {
    __half2 h = __floats2half2_rn(a, b);
    return *reinterpret_cast<uint32_t*>(&h);
}
__device__ __forceinline__ void ldsm_x4(uint32_t* r, uint32_t addr) {
    asm volatile("ldmatrix.sync.aligned.m8n8.x4.shared.b16 {%0,%1,%2,%3}, [%4];"
                 : "=r"(r[0]), "=r"(r[1]), "=r"(r[2]), "=r"(r[3]) : "r"(addr));
}
__device__ __forceinline__ void mma_16816(float* d, const uint32_t* a, const uint32_t* b) {
    asm volatile("mma.sync.aligned.m16n8k16.row.col.f32.f16.f16.f32 "
                 "{%0,%1,%2,%3}, {%4,%5,%6,%7}, {%8,%9}, {%0,%1,%2,%3};"
                 : "+f"(d[0]), "+f"(d[1]), "+f"(d[2]), "+f"(d[3])
                 : "r"(a[0]), "r"(a[1]), "r"(a[2]), "r"(a[3]), "r"(b[0]), "r"(b[1]));
}

// ---------------- kNN (k=6, 2 queries/thread, 4 blocks/graph; matches jax top_k ties) ----------------
__global__ __launch_bounds__(128) void knn_kernel(const float* __restrict__ pos)
{
    __shared__ float4 cand[128];
    int graph = blockIdx.x >> 2;
    int q0 = graph * PPG + ((blockIdx.x & 3) << 8) + threadIdx.x;
    int q1 = q0 + 128;
    float ax = pos[3*q0], ay = pos[3*q0+1], az = pos[3*q0+2];
    float bx = pos[3*q1], by = pos[3*q1+1], bz = pos[3*q1+2];
    float as = ax*ax + ay*ay + az*az;
    float bs = bx*bx + by*by + bz*bz;
    g_pos4[q0] = make_float4(ax, ay, az, 0.f);
    g_pos4[q1] = make_float4(bx, by, bz, 0.f);
    float ad[6], bd[6]; int ai[6], bi[6];
#pragma unroll
    for (int t = 0; t < 6; t++) { ad[t] = FLT_MAX; ai[t] = 0; bd[t] = FLT_MAX; bi[t] = 0; }
    for (int tile = 0; tile < PPG; tile += 128) {
        int c = graph * PPG + tile + threadIdx.x;
        float cx = pos[3*c], cy = pos[3*c+1], cz = pos[3*c+2];
        cand[threadIdx.x] = make_float4(cx, cy, cz, cx*cx + cy*cy + cz*cz);
        __syncthreads();
#pragma unroll 4
        for (int u = 0; u < 128; u++) {
            float4 p = cand[u];
            int cidx = graph*PPG + tile + u;
            float d2a = as + p.w - 2.0f*(ax*p.x + ay*p.y + az*p.z);
            float d2b = bs + p.w - 2.0f*(bx*p.x + by*p.y + bz*p.z);
            if (d2a < ad[5]) {
                ad[5] = d2a; ai[5] = cidx;
#pragma unroll
                for (int t = 5; t > 0; t--)
                    if (ad[t] < ad[t-1]) {
                        float td = ad[t]; ad[t] = ad[t-1]; ad[t-1] = td;
                        int   ti = ai[t]; ai[t] = ai[t-1]; ai[t-1] = ti;
                    }
            }
            if (d2b < bd[5]) {
                bd[5] = d2b; bi[5] = cidx;
#pragma unroll
                for (int t = 5; t > 0; t--)
                    if (bd[t] < bd[t-1]) {
                        float td = bd[t]; bd[t] = bd[t-1]; bd[t-1] = td;
                        int   ti = bi[t]; bi[t] = bi[t-1]; bi[t-1] = ti;
                    }
            }
        }
        __syncthreads();
    }
#pragma unroll
    for (int t = 0; t < 6; t++) { g_knn[q0*8 + t] = ai[t]; g_knn[q1*8 + t] = bi[t]; }
    g_knn[q0*8 + 6] = ai[0]; g_knn[q0*8 + 7] = ai[0];
    g_knn[q1*8 + 6] = bi[0]; g_knn[q1*8 + 7] = bi[0];
}

// ---------------- W2^T fp16 into swizzled B tiles (all 3 layers) ----------------
__global__ __launch_bounds__(128) void w2split_kernel(const float* __restrict__ W2a,
                                                      const float* __restrict__ W2b,
                                                      const float* __restrict__ W2c)
{
    int t = blockIdx.x * 128 + threadIdx.x;
    int l = t >> 12, nk = t & 4095;
    int n = nk >> 6, k = nk & 63;
    const float* W2 = (l == 0) ? W2a : ((l == 1) ? W2b : W2c);
    float v = W2[k*64 + n];
    uint32_t sw = sw128((uint32_t)(n*128 + k*2));
    g_w2s[l][sw >> 1] = __float2half_rn(v);
}

// ---------------- W1ab^T fp16, layers 2/3 (n=128 out cols, k=64 in ch) ----------------
__global__ __launch_bounds__(128) void w1split_kernel(const float* __restrict__ W1b,
                                                      const float* __restrict__ W1c)
{
    int t = blockIdx.x * 128 + threadIdx.x;
    int l = t >> 13, nk = t & 8191;
    int n = nk >> 6, k = nk & 63;
    const float* W1 = l ? W1c : W1b;
    float v = (n < 64) ? W1[k*64 + n] : W1[(64 + k)*64 + (n - 64)];
    uint32_t sw = sw128((uint32_t)(n*128 + k*2));
    g_w1s[l][sw >> 1] = __float2half_rn(v);
}

// ---------------- phase B: edge W2 GEMM + max over slots + relu; output to hout OR hC (fp16 smem) ----------------
template<int SLOTS, bool FUSE>
__device__ __forceinline__ void edge_phaseB(
    uint32_t sA, uint32_t sB,
    const float* __restrict__ b2, float* __restrict__ hout, char* hC,
    int warp, int lane, int PTS)
{
    const int rb = (warp >> 1) * 64;
    const int ch = (warp & 1) * 32;
    const int gn0 = (warp & 1) * 4;
    int acolb = (lane >> 4) * 16;

    uint32_t bh[4][4][2];
    {
        uint32_t laddr = (uint32_t)((lane & 7)*128 + ((lane >> 4) & 1)*32 + ((lane >> 3) & 1)*16);
#pragma unroll
        for (int nt = 0; nt < 4; nt++)
#pragma unroll
            for (int kp = 0; kp < 4; kp += 2) {
                uint32_t boff = sw128((uint32_t)((gn0 + nt)*1024 + kp*32) + laddr);
                uint32_t r[4];
                ldsm_x4(r, sB + boff);
                bh[nt][kp][0] = r[0]; bh[nt][kp][1] = r[1];
                bh[nt][kp+1][0] = r[2]; bh[nt][kp+1][1] = r[3];
            }
    }

#pragma unroll
    for (int rt = 0; rt < 4; rt++) {
        float d[4][4];
#pragma unroll
        for (int nt = 0; nt < 4; nt++)
#pragma unroll
            for (int q = 0; q < 4; q++) d[nt][q] = 0.f;

        uint32_t afr[4][4];
        uint32_t arow_off = (uint32_t)((rb + rt*16 + (lane & 15)) * 128);
#pragma unroll
        for (int k = 0; k < 4; k++)
            ldsm_x4(afr[k], sA + sw128(arow_off + k*32 + acolb));

#pragma unroll
        for (int nt = 0; nt < 4; nt++)
#pragma unroll
            for (int k = 0; k < 4; k++) mma_16816(d[nt], afr[k], bh[nt][k]);

        if (SLOTS == 8) {
            int pAl = (warp >> 1) * 8 + rt * 2;     // local point index
#pragma unroll
            for (int nt = 0; nt < 4; nt++) {
                float m0 = d[nt][0], m1 = d[nt][1], m2 = d[nt][2], m3 = d[nt][3];
#pragma unroll
                for (int s = 4; s <= 16; s <<= 1) {
                    m0 = fmaxf(m0, __shfl_xor_sync(0xffffffffu, m0, s));
                    m1 = fmaxf(m1, __shfl_xor_sync(0xffffffffu, m1, s));
                    m2 = fmaxf(m2, __shfl_xor_sync(0xffffffffu, m2, s));
                    m3 = fmaxf(m3, __shfl_xor_sync(0xffffffffu, m3, s));
                }
                int col = ch + nt*8 + (lane & 3)*2;
                if (lane < 8) {
                    int lp = pAl + (lane >> 2);
                    float v0 = (lane < 4) ? m0 : m2;
                    float v1 = (lane < 4) ? m1 : m3;
                    v0 = fmaxf(v0 + b2[col], 0.f);
                    v1 = fmaxf(v1 + b2[col+1], 0.f);
                    if (FUSE) {
                        *(uint32_t*)(hC + sw128((uint32_t)(lp*128 + col*2))) = pack_h2(v0, v1);
                    } else {
                        *(float2*)&hout[(size_t)(blockIdx.x*PTS + lp)*64 + col] = make_float2(v0, v1);
                    }
                }
            }
        } else {   // SLOTS == 4
            int lpb = (warp >> 1) * 16 + rt * 4;    // local point base
#pragma unroll
            for (int nt = 0; nt < 4; nt++) {
                float m0 = d[nt][0], m1 = d[nt][1], m2 = d[nt][2], m3 = d[nt][3];
#pragma unroll
                for (int s = 4; s <= 8; s <<= 1) {
                    m0 = fmaxf(m0, __shfl_xor_sync(0xffffffffu, m0, s));
                    m1 = fmaxf(m1, __shfl_xor_sync(0xffffffffu, m1, s));
                    m2 = fmaxf(m2, __shfl_xor_sync(0xffffffffu, m2, s));
                    m3 = fmaxf(m3, __shfl_xor_sync(0xffffffffu, m3, s));
                }
                int col = ch + nt*8 + (lane & 3)*2;
                if ((lane & 15) < 4) {
                    int g = lane >> 4;
                    float v0 = fmaxf(m0 + b2[col], 0.f), v1 = fmaxf(m1 + b2[col+1], 0.f);
                    float v2 = fmaxf(m2 + b2[col], 0.f), v3 = fmaxf(m3 + b2[col+1], 0.f);
                    if (FUSE) {
                        *(uint32_t*)(hC + sw128((uint32_t)((lpb + g)*128 + col*2)))     = pack_h2(v0, v1);
                        *(uint32_t*)(hC + sw128((uint32_t)((lpb + 2 + g)*128 + col*2))) = pack_h2(v2, v3);
                    } else {
                        *(float2*)&hout[(size_t)(blockIdx.x*PTS + lpb + g)*64 + col]     = make_float2(v0, v1);
                        *(float2*)&hout[(size_t)(blockIdx.x*PTS + lpb + 2 + g)*64 + col] = make_float2(v2, v3);
                    }
                }
            }
        }
    }
}

// ---------------- phase C: ab projection GEMM (h[PTS x 64] fp16 @ W1ab^T -> ab out fp32) ----------------
__device__ __forceinline__ void phaseC(
    uint32_t sH, uint32_t sW1, const float* __restrict__ b1n,
    float* __restrict__ abot, int warp, int lane, int PTS, int pbase)
{
    int ntile = (PTS / 16) * 4;
    uint32_t laddr = (uint32_t)((lane & 7)*128 + ((lane >> 4) & 1)*32 + ((lane >> 3) & 1)*16);
    uint32_t acolb = (uint32_t)((lane >> 4) * 16);
    for (int t = warp; t < ntile; t += 8) {
        int rt = t >> 2, cg = t & 3;
        uint32_t afr[4][4];
        uint32_t arow = (uint32_t)((rt*16 + (lane & 15)) * 128);
#pragma unroll
        for (int k = 0; k < 4; k++)
            ldsm_x4(afr[k], sH + sw128(arow + k*32 + acolb));
        float d[4][4];
#pragma unroll
        for (int nt = 0; nt < 4; nt++)
#pragma unroll
            for (int q = 0; q < 4; q++) d[nt][q] = 0.f;
#pragma unroll
        for (int nt = 0; nt < 4; nt++) {
            uint32_t bh[4][2];
#pragma unroll
            for (int kp = 0; kp < 4; kp += 2) {
                uint32_t bo = sw128((uint32_t)((cg*4 + nt)*1024 + kp*32) + laddr);
                uint32_t r[4];
                ldsm_x4(r, sW1 + bo);
                bh[kp][0] = r[0]; bh[kp][1] = r[1]; bh[kp+1][0] = r[2]; bh[kp+1][1] = r[3];
            }
#pragma unroll
            for (int k = 0; k < 4; k++) mma_16816(d[nt], afr[k], bh[k]);
        }
        int r0 = rt*16 + (lane >> 2);
#pragma unroll
        for (int nt = 0; nt < 4; nt++) {
            int col = cg*32 + nt*8 + (lane & 3)*2;
            float bx = 0.f, by = 0.f;
            if (col < 64) { bx = b1n[col]; by = b1n[col + 1]; }
            *(float2*)&abot[(size_t)(pbase + r0)*128 + col] =
                make_float2(d[nt][0] + bx, d[nt][1] + by);
            *(float2*)&abot[(size_t)(pbase + r0 + 8)*128 + col] =
                make_float2(d[nt][2] + bx, d[nt][3] + by);
        }
    }
}

// smem layout (fused): A 0..32K | W2 32K..40K | W1 40K..56K | hC 56K..64K
#define EDGE_SMEM_F  (65536 + 256)
#define EDGE_SMEM_NF (32768 + 8192 + 256)

// ---------------- edge layer 1 (fused ab): inline pos projections ----------------
__global__ __launch_bounds__(256, 3) void edge1_mma_kernel(
    const float* __restrict__ W1,      // [9][64]
    const float* __restrict__ b1,
    const float* __restrict__ b2,
    const float* __restrict__ b1n,     // next layer's b1 (for ab)
    float* __restrict__ abot)
{
    constexpr int PTS = 32;
    extern __shared__ char smem_raw[];
    uint32_t su = smem_u32(smem_raw);
    uint32_t abase = (su + 127) & ~127u;
    char* base = smem_raw + (abase - su);
    char* AC = base;
    char* hC = base + 57344;
    uint32_t sA = abase, sB = abase + 32768, sW1 = abase + 40960, sH = abase + 57344;

    int tid = threadIdx.x, warp = tid >> 5, lane = tid & 31;

    {
        const uint4* s2 = (const uint4*)g_w2s[0];
        uint4* d2p = (uint4*)(base + 32768);
        for (int t = tid; t < 512; t += 256) d2p[t] = s2[t];
        const uint4* s1 = (const uint4*)g_w1s[0];
        uint4* d1p = (uint4*)(base + 40960);
        for (int t = tid; t < 1024; t += 256) d1p[t] = s1[t];
    }

    // phase A: fully inline pos projections. lane -> channels (2*lane, 2*lane+1)
    {
        int lane2 = lane * 2;
        float wa0x=W1[lane2],       wa0y=W1[lane2+1];
        float wa1x=W1[64+lane2],    wa1y=W1[64+lane2+1];
        float wa2x=W1[128+lane2],   wa2y=W1[128+lane2+1];
        float wb0x=W1[192+lane2],   wb0y=W1[192+lane2+1];
        float wb1x=W1[256+lane2],   wb1y=W1[256+lane2+1];
        float wb2x=W1[320+lane2],   wb2y=W1[320+lane2+1];
        float wr0x=W1[384+lane2],   wr0y=W1[384+lane2+1];
        float wr1x=W1[448+lane2],   wr1y=W1[448+lane2+1];
        float wr2x=W1[512+lane2],   wr2y=W1[512+lane2+1];
        float b1x=b1[lane2], b1y=b1[lane2+1];
#pragma unroll
        for (int pp = 0; pp < 4; pp++) {
            int lp = warp * 4 + pp;
            int i = blockIdx.x * PTS + lp;
            float4 pi = g_pos4[i];
            float ax = fmaf(pi.x, wa0x, fmaf(pi.y, wa1x, fmaf(pi.z, wa2x, b1x)));
            float ay = fmaf(pi.x, wa0y, fmaf(pi.y, wa1y, fmaf(pi.z, wa2y, b1y)));
            int rowbase = lp * 8;
#pragma unroll
            for (int slot = 0; slot < 8; slot++) {
                int j = g_knn[i*8 + slot];
                float4 pj = g_pos4[j];
                float rx = pj.x - pi.x, ry = pj.y - pi.y, rz = pj.z - pi.z;
                float h0 = ax;
                h0 = fmaf(pj.x, wb0x, h0); h0 = fmaf(pj.y, wb1x, h0); h0 = fmaf(pj.z, wb2x, h0);
                h0 = fmaf(rx, wr0x, h0);   h0 = fmaf(ry, wr1x, h0);   h0 = fmaf(rz, wr2x, h0);
                float h1 = ay;
                h1 = fmaf(pj.x, wb0y, h1); h1 = fmaf(pj.y, wb1y, h1); h1 = fmaf(pj.z, wb2y, h1);
                h1 = fmaf(rx, wr0y, h1);   h1 = fmaf(ry, wr1y, h1);   h1 = fmaf(rz, wr2y, h1);
                h0 = fmaxf(h0, 0.f); h1 = fmaxf(h1, 0.f);
                uint32_t sw = sw128((uint32_t)((rowbase + slot)*128 + lane2*2));
                *(uint32_t*)(AC + sw) = pack_h2(h0, h1);
            }
        }
    }
    __syncthreads();
    edge_phaseB<8, true>(sA, sB, b2, nullptr, hC, warp, lane, PTS);
    __syncthreads();
    phaseC(sH, sW1, b1n, abot, warp, lane, PTS, blockIdx.x * PTS);
}

// ---------------- edge layers 2/3: gather a/b from abin; optional fused ab out ----------------
template<int K, int SLOTS, bool FUSE>
__global__ __launch_bounds__(256, 3) void edge_mma_kernel(
    const float* __restrict__ abin,     // this layer's a/b projections (read-only buffer)
    const float* __restrict__ W1rel,
    const float* __restrict__ b2,
    int layer,                          // W2 layer index
    int w1layer,                        // W1ab layer index (FUSE only)
    const float* __restrict__ b1n,      // next layer's b1 (FUSE only)
    float* __restrict__ abot,           // ab out, DIFFERENT buffer than abin (FUSE only)
    float* __restrict__ hout)           // h out (non-FUSE only)
{
    constexpr int PTS = 256 / SLOTS;
    constexpr int PPW = PTS / 8;
    extern __shared__ char smem_raw[];
    uint32_t su = smem_u32(smem_raw);
    uint32_t abase = (su + 127) & ~127u;
    char* base = smem_raw + (abase - su);
    char* AC = base;
    char* hC = base + 57344;
    uint32_t sA = abase, sB = abase + 32768, sW1 = abase + 40960, sH = abase + 57344;

    int tid = threadIdx.x, warp = tid >> 5, lane = tid & 31;

    {
        const uint4* s2 = (const uint4*)g_w2s[layer];
        uint4* d2p = (uint4*)(base + 32768);
        for (int t = tid; t < 512; t += 256) d2p[t] = s2[t];
        if (FUSE) {
            const uint4* s1 = (const uint4*)g_w1s[w1layer];
            uint4* d1p = (uint4*)(base + 40960);
            for (int t = tid; t < 1024; t += 256) d1p[t] = s1[t];
        }
    }

    {
        int lane2 = lane * 2;
        float u0x = W1rel[lane2],       u0y = W1rel[lane2 + 1];
        float u1x = W1rel[64 + lane2],  u1y = W1rel[64 + lane2 + 1];
        float u2x = W1rel[128 + lane2], u2y = W1rel[128 + lane2 + 1];
#pragma unroll
        for (int pp = 0; pp < PPW; pp++) {
            int lp = warp * PPW + pp;
            int i = blockIdx.x * PTS + lp;
            float2 a = *(const float2*)&abin[(size_t)i*128 + lane2];
            float4 pi = g_pos4[i];
            int rowbase = lp * SLOTS;
#pragma unroll
            for (int slot = 0; slot < SLOTS; slot++) {
                int j = g_knn[i*8 + (slot < K ? slot : 0)];
                float4 pj = g_pos4[j];
                float2 b = *(const float2*)&abin[(size_t)j*128 + 64 + lane2];
                float rx = pj.x - pi.x, ry = pj.y - pi.y, rz = pj.z - pi.z;
                float h0 = fmaxf(fmaf(rx, u0x, fmaf(ry, u1x, fmaf(rz, u2x, a.x + b.x))), 0.f);
                float h1 = fmaxf(fmaf(rx, u0y, fmaf(ry, u1y, fmaf(rz, u2y, a.y + b.y))), 0.f);
                uint32_t sw = sw128((uint32_t)((rowbase + slot)*128 + lane2*2));
                *(uint32_t*)(AC + sw) = pack_h2(h0, h1);
            }
        }
    }
    __syncthreads();
    edge_phaseB<SLOTS, FUSE>(sA, sB, b2, hout, hC, warp, lane, PTS);
    if (FUSE) {
        __syncthreads();
        phaseC(sH, sW1, b1n, abot, warp, lane, PTS, blockIdx.x * PTS);
    }
}

// ---------------- global max pool + regression head ----------------
__global__ __launch_bounds__(256) void pool_kernel(const float* __restrict__ h,
                                                   const float* __restrict__ regW,
                                                   const float* __restrict__ regb,
                                                   float* __restrict__ out)
{
    __shared__ float red[4][64];
    int g = blockIdx.x;
    int c = threadIdx.x & 63, s = threadIdx.x >> 6;
    const float* hb = h + (size_t)g * PPG * 64;
    float m = -FLT_MAX;
    for (int p = s; p < PPG; p += 4) m = fmaxf(m, hb[p*64 + c]);
    red[s][c] = m;
    __syncthreads();
    if (threadIdx.x < 64)
        red[0][c] = fmaxf(fmaxf(red[0][c], red[1][c]), fmaxf(red[2][c], red[3][c]));
    __syncthreads();
    if (threadIdx.x < 6) {
        float acc = regb[threadIdx.x];
#pragma unroll
        for (int cc = 0; cc < 64; cc++)
            acc = fmaf(red[0][cc], regW[cc*6 + threadIdx.x], acc);
        out[g*6 + threadIdx.x] = acc;
    }
}

// ---------------- launch ----------------
extern "C" void kernel_launch(void* const* d_in, const int* in_sizes, int n_in,
                              void* d_out, int out_size)
{
    (void)in_sizes; (void)n_in; (void)out_size;
    const float* pos  = (const float*)d_in[1];
    const float* c1W1 = (const float*)d_in[3];
    const float* c1b1 = (const float*)d_in[4];
    const float* c1W2 = (const float*)d_in[5];
    const float* c1b2 = (const float*)d_in[6];
    const float* c2W1 = (const float*)d_in[7];
    const float* c2b1 = (const float*)d_in[8];
    const float* c2W2 = (const float*)d_in[9];
    const float* c2b2 = (const float*)d_in[10];
    const float* c3W1 = (const float*)d_in[11];
    const float* c3b1 = (const float*)d_in[12];
    const float* c3W2 = (const float*)d_in[13];
    const float* c3b2 = (const float*)d_in[14];
    const float* regW = (const float*)d_in[15];
    const float* regb = (const float*)d_in[16];
    float* out = (float*)d_out;

    float *h1, *abA, *abB;
    cudaGetSymbolAddress((void**)&h1, g_h1);
    cudaGetSymbolAddress((void**)&abA, g_abA);
    cudaGetSymbolAddress((void**)&abB, g_abB);
    cudaFuncSetAttribute((const void*)edge1_mma_kernel, cudaFuncAttributeMaxDynamicSharedMemorySize, EDGE_SMEM_F);
    cudaFuncSetAttribute((const void*)edge_mma_kernel<4,4,true>,  cudaFuncAttributeMaxDynamicSharedMemorySize, EDGE_SMEM_F);
    cudaFuncSetAttribute((const void*)edge_mma_kernel<3,4,false>, cudaFuncAttributeMaxDynamicSharedMemorySize, EDGE_SMEM_NF);

    knn_kernel<<<BGRAPH * 4, 128>>>(pos);
    w2split_kernel<<<96, 128>>>(c1W2, c2W2, c3W2);
    w1split_kernel<<<128, 128>>>(c2W1, c3W1);
    // layer 1 (fused: writes abA for layer 2)
    edge1_mma_kernel<<<NPTS/32, 256, EDGE_SMEM_F>>>(c1W1, c1b1, c1b2, c2b1, abA);
    // layer 2 (fused: reads abA, writes abB for layer 3 — double buffer, no cross-block race)
    edge_mma_kernel<4,4,true><<<NPTS/64, 256, EDGE_SMEM_F>>>(abA, c2W1 + 128*64, c2b2, 1, 1, c3b1, abB, nullptr);
    // layer 3 (plain: reads abB, writes h for pool)
    edge_mma_kernel<3,4,false><<<NPTS/64, 256, EDGE_SMEM_NF>>>(abB, c3W1 + 128*64, c3b2, 2, 0, nullptr, nullptr, h1);
    pool_kernel<<<BGRAPH, 256>>>(h1, regW, regb, out);
}

// round 13
// speedup vs baseline: 2.4246x; 1.0156x over previous
#include <cuda_runtime.h>
#include <cuda_fp16.h>
#include <float.h>
#include <stdint.h>

#define NPTS   65536
#define BGRAPH 64
#define PPG    1024

// ---------------- scratch (device globals; no allocation) ----------------
__device__ int      g_knn[NPTS * 8];          // 6 real + 2 pad (dup of nn0)
__device__ float    g_abA[NPTS * 128];        // layer-2 input: a (+b1) cols 0..63, b cols 64..127
__device__ float    g_abB[NPTS * 128];        // layer-3 input (double buffer)
__device__ float4   g_pos4[NPTS];             // packed positions (x,y,z,0)
__device__ uint32_t g_pool[BGRAPH * 64];      // per-graph channel max (uint-ordered floats >= 0)
__device__ __align__(16) __half g_w2s[3][4096];  // [layer] swizzled fp16 W2^T [n=64][k=64]
__device__ __align__(16) __half g_w1s[2][8192];  // [layer] swizzled fp16 W1ab^T [n=128][k=64]

// ---------------- helpers (base-ISA: ldmatrix + mma.sync, sm_80+) ----------------
__device__ __forceinline__ uint32_t smem_u32(const void* p) {
    uint32_t a;
    asm("{ .reg .u64 t; cvta.to.shared.u64 t, %1; cvt.u32.u64 %0, t; }" : "=r"(a) : "l"(p));
    return a;
}
__device__ __forceinline__ uint32_t sw128(uint32_t off) { return off ^ ((off >> 3) & 0x70); }
__device__ __forceinline__ uint32_t pack_h2(float a, float b) {
    __half2 h = __floats2half2_rn(a, b);
    return *reinterpret_cast<uint32_t*>(&h);
}
__device__ __forceinline__ void ldsm_x4(uint32_t* r, uint32_t addr) {
    asm volatile("ldmatrix.sync.aligned.m8n8.x4.shared.b16 {%0,%1,%2,%3}, [%4];"
                 : "=r"(r[0]), "=r"(r[1]), "=r"(r[2]), "=r"(r[3]) : "r"(addr));
}
__device__ __forceinline__ void mma_16816(float* d, const uint32_t* a, const uint32_t* b) {
    asm volatile("mma.sync.aligned.m16n8k16.row.col.f32.f16.f16.f32 "
                 "{%0,%1,%2,%3}, {%4,%5,%6,%7}, {%8,%9}, {%0,%1,%2,%3};"
                 : "+f"(d[0]), "+f"(d[1]), "+f"(d[2]), "+f"(d[3])
                 : "r"(a[0]), "r"(a[1]), "r"(a[2]), "r"(a[3]), "r"(b[0]), "r"(b[1]));
}

// ---------------- kNN (k=6, 2 queries/thread, 4 blocks/graph; matches jax top_k ties) ----------------
__global__ __launch_bounds__(128) void knn_kernel(const float* __restrict__ pos)
{
    __shared__ float4 cand[128];
    int graph = blockIdx.x >> 2;
    int q0 = graph * PPG + ((blockIdx.x & 3) << 8) + threadIdx.x;
    int q1 = q0 + 128;
    float ax = pos[3*q0], ay = pos[3*q0+1], az = pos[3*q0+2];
    float bx = pos[3*q1], by = pos[3*q1+1], bz = pos[3*q1+2];
    float as = ax*ax + ay*ay + az*az;
    float bs = bx*bx + by*by + bz*bz;
    g_pos4[q0] = make_float4(ax, ay, az, 0.f);
    g_pos4[q1] = make_float4(bx, by, bz, 0.f);
    float ad[6], bd[6]; int ai[6], bi[6];
#pragma unroll
    for (int t = 0; t < 6; t++) { ad[t] = FLT_MAX; ai[t] = 0; bd[t] = FLT_MAX; bi[t] = 0; }
    for (int tile = 0; tile < PPG; tile += 128) {
        int c = graph * PPG + tile + threadIdx.x;
        float cx = pos[3*c], cy = pos[3*c+1], cz = pos[3*c+2];
        cand[threadIdx.x] = make_float4(cx, cy, cz, cx*cx + cy*cy + cz*cz);
        __syncthreads();
#pragma unroll 4
        for (int u = 0; u < 128; u++) {
            float4 p = cand[u];
            int cidx = graph*PPG + tile + u;
            float d2a = as + p.w - 2.0f*(ax*p.x + ay*p.y + az*p.z);
            float d2b = bs + p.w - 2.0f*(bx*p.x + by*p.y + bz*p.z);
            if (d2a < ad[5]) {
                ad[5] = d2a; ai[5] = cidx;
#pragma unroll
                for (int t = 5; t > 0; t--)
                    if (ad[t] < ad[t-1]) {
                        float td = ad[t]; ad[t] = ad[t-1]; ad[t-1] = td;
                        int   ti = ai[t]; ai[t] = ai[t-1]; ai[t-1] = ti;
                    }
            }
            if (d2b < bd[5]) {
                bd[5] = d2b; bi[5] = cidx;
#pragma unroll
                for (int t = 5; t > 0; t--)
                    if (bd[t] < bd[t-1]) {
                        float td = bd[t]; bd[t] = bd[t-1]; bd[t-1] = td;
                        int   ti = bi[t]; bi[t] = bi[t-1]; bi[t-1] = ti;
                    }
            }
        }
        __syncthreads();
    }
#pragma unroll
    for (int t = 0; t < 6; t++) { g_knn[q0*8 + t] = ai[t]; g_knn[q1*8 + t] = bi[t]; }
    g_knn[q0*8 + 6] = ai[0]; g_knn[q0*8 + 7] = ai[0];
    g_knn[q1*8 + 6] = bi[0]; g_knn[q1*8 + 7] = bi[0];
}

// ---------------- W2^T fp16 into swizzled B tiles (all 3 layers) + zero g_pool ----------------
__global__ __launch_bounds__(128) void w2split_kernel(const float* __restrict__ W2a,
                                                      const float* __restrict__ W2b,
                                                      const float* __restrict__ W2c)
{
    int t = blockIdx.x * 128 + threadIdx.x;
    if (t < BGRAPH * 64) g_pool[t] = 0u;      // re-zeroed every launch (graph-replay safe)
    int l = t >> 12, nk = t & 4095;
    int n = nk >> 6, k = nk & 63;
    const float* W2 = (l == 0) ? W2a : ((l == 1) ? W2b : W2c);
    float v = W2[k*64 + n];
    uint32_t sw = sw128((uint32_t)(n*128 + k*2));
    g_w2s[l][sw >> 1] = __float2half_rn(v);
}

// ---------------- W1ab^T fp16, layers 2/3 (n=128 out cols, k=64 in ch) ----------------
__global__ __launch_bounds__(128) void w1split_kernel(const float* __restrict__ W1b,
                                                      const float* __restrict__ W1c)
{
    int t = blockIdx.x * 128 + threadIdx.x;
    int l = t >> 13, nk = t & 8191;
    int n = nk >> 6, k = nk & 63;
    const float* W1 = l ? W1c : W1b;
    float v = (n < 64) ? W1[k*64 + n] : W1[(64 + k)*64 + (n - 64)];
    uint32_t sw = sw128((uint32_t)(n*128 + k*2));
    g_w1s[l][sw >> 1] = __float2half_rn(v);
}

// ---------------- phase B: edge W2 GEMM + max over slots + relu ----------------
// MODE: 0 = (unused), 1 = FUSE (write fp16 hC), 2 = POOL (write fp32 poolC [64][66])
template<int SLOTS, int MODE>
__device__ __forceinline__ void edge_phaseB(
    uint32_t sA, uint32_t sB,
    const float* __restrict__ b2, char* hC, float* poolC,
    int warp, int lane)
{
    const int rb = (warp >> 1) * 64;
    const int ch = (warp & 1) * 32;
    const int gn0 = (warp & 1) * 4;
    int acolb = (lane >> 4) * 16;

    uint32_t bh[4][4][2];
    {
        uint32_t laddr = (uint32_t)((lane & 7)*128 + ((lane >> 4) & 1)*32 + ((lane >> 3) & 1)*16);
#pragma unroll
        for (int nt = 0; nt < 4; nt++)
#pragma unroll
            for (int kp = 0; kp < 4; kp += 2) {
                uint32_t boff = sw128((uint32_t)((gn0 + nt)*1024 + kp*32) + laddr);
                uint32_t r[4];
                ldsm_x4(r, sB + boff);
                bh[nt][kp][0] = r[0]; bh[nt][kp][1] = r[1];
                bh[nt][kp+1][0] = r[2]; bh[nt][kp+1][1] = r[3];
            }
    }

#pragma unroll
    for (int rt = 0; rt < 4; rt++) {
        float d[4][4];
#pragma unroll
        for (int nt = 0; nt < 4; nt++)
#pragma unroll
            for (int q = 0; q < 4; q++) d[nt][q] = 0.f;

        uint32_t afr[4][4];
        uint32_t arow_off = (uint32_t)((rb + rt*16 + (lane & 15)) * 128);
#pragma unroll
        for (int k = 0; k < 4; k++)
            ldsm_x4(afr[k], sA + sw128(arow_off + k*32 + acolb));

#pragma unroll
        for (int nt = 0; nt < 4; nt++)
#pragma unroll
            for (int k = 0; k < 4; k++) mma_16816(d[nt], afr[k], bh[nt][k]);

        if (SLOTS == 8) {
            int pAl = (warp >> 1) * 8 + rt * 2;
#pragma unroll
            for (int nt = 0; nt < 4; nt++) {
                float m0 = d[nt][0], m1 = d[nt][1], m2 = d[nt][2], m3 = d[nt][3];
#pragma unroll
                for (int s = 4; s <= 16; s <<= 1) {
                    m0 = fmaxf(m0, __shfl_xor_sync(0xffffffffu, m0, s));
                    m1 = fmaxf(m1, __shfl_xor_sync(0xffffffffu, m1, s));
                    m2 = fmaxf(m2, __shfl_xor_sync(0xffffffffu, m2, s));
                    m3 = fmaxf(m3, __shfl_xor_sync(0xffffffffu, m3, s));
                }
                int col = ch + nt*8 + (lane & 3)*2;
                if (lane < 8) {
                    int lp = pAl + (lane >> 2);
                    float v0 = (lane < 4) ? m0 : m2;
                    float v1 = (lane < 4) ? m1 : m3;
                    v0 = fmaxf(v0 + b2[col], 0.f);
                    v1 = fmaxf(v1 + b2[col+1], 0.f);
                    *(uint32_t*)(hC + sw128((uint32_t)(lp*128 + col*2))) = pack_h2(v0, v1);
                }
            }
        } else {   // SLOTS == 4
            int lpb = (warp >> 1) * 16 + rt * 4;
#pragma unroll
            for (int nt = 0; nt < 4; nt++) {
                float m0 = d[nt][0], m1 = d[nt][1], m2 = d[nt][2], m3 = d[nt][3];
#pragma unroll
                for (int s = 4; s <= 8; s <<= 1) {
                    m0 = fmaxf(m0, __shfl_xor_sync(0xffffffffu, m0, s));
                    m1 = fmaxf(m1, __shfl_xor_sync(0xffffffffu, m1, s));
                    m2 = fmaxf(m2, __shfl_xor_sync(0xffffffffu, m2, s));
                    m3 = fmaxf(m3, __shfl_xor_sync(0xffffffffu, m3, s));
                }
                int col = ch + nt*8 + (lane & 3)*2;
                if ((lane & 15) < 4) {
                    int g = lane >> 4;
                    float v0 = fmaxf(m0 + b2[col], 0.f), v1 = fmaxf(m1 + b2[col+1], 0.f);
                    float v2 = fmaxf(m2 + b2[col], 0.f), v3 = fmaxf(m3 + b2[col+1], 0.f);
                    if (MODE == 1) {
                        *(uint32_t*)(hC + sw128((uint32_t)((lpb + g)*128 + col*2)))     = pack_h2(v0, v1);
                        *(uint32_t*)(hC + sw128((uint32_t)((lpb + 2 + g)*128 + col*2))) = pack_h2(v2, v3);
                    } else {   // MODE == 2: fp32 pool staging
                        *(float2*)&poolC[(lpb + g)*66 + col]     = make_float2(v0, v1);
                        *(float2*)&poolC[(lpb + 2 + g)*66 + col] = make_float2(v2, v3);
                    }
                }
            }
        }
    }
}

// ---------------- phase C: ab projection GEMM (h[PTS x 64] fp16 @ W1ab^T -> ab out fp32) ----------------
__device__ __forceinline__ void phaseC(
    uint32_t sH, uint32_t sW1, const float* __restrict__ b1n,
    float* __restrict__ abot, int warp, int lane, int PTS, int pbase)
{
    int ntile = (PTS / 16) * 4;
    uint32_t laddr = (uint32_t)((lane & 7)*128 + ((lane >> 4) & 1)*32 + ((lane >> 3) & 1)*16);
    uint32_t acolb = (uint32_t)((lane >> 4) * 16);
    for (int t = warp; t < ntile; t += 8) {
        int rt = t >> 2, cg = t & 3;
        uint32_t afr[4][4];
        uint32_t arow = (uint32_t)((rt*16 + (lane & 15)) * 128);
#pragma unroll
        for (int k = 0; k < 4; k++)
            ldsm_x4(afr[k], sH + sw128(arow + k*32 + acolb));
        float d[4][4];
#pragma unroll
        for (int nt = 0; nt < 4; nt++)
#pragma unroll
            for (int q = 0; q < 4; q++) d[nt][q] = 0.f;
#pragma unroll
        for (int nt = 0; nt < 4; nt++) {
            uint32_t bh[4][2];
#pragma unroll
            for (int kp = 0; kp < 4; kp += 2) {
                uint32_t bo = sw128((uint32_t)((cg*4 + nt)*1024 + kp*32) + laddr);
                uint32_t r[4];
                ldsm_x4(r, sW1 + bo);
                bh[kp][0] = r[0]; bh[kp][1] = r[1]; bh[kp+1][0] = r[2]; bh[kp+1][1] = r[3];
            }
#pragma unroll
            for (int k = 0; k < 4; k++) mma_16816(d[nt], afr[k], bh[k]);
        }
        int r0 = rt*16 + (lane >> 2);
#pragma unroll
        for (int nt = 0; nt < 4; nt++) {
            int col = cg*32 + nt*8 + (lane & 3)*2;
            float bx = 0.f, by = 0.f;
            if (col < 64) { bx = b1n[col]; by = b1n[col + 1]; }
            *(float2*)&abot[(size_t)(pbase + r0)*128 + col] =
                make_float2(d[nt][0] + bx, d[nt][1] + by);
            *(float2*)&abot[(size_t)(pbase + r0 + 8)*128 + col] =
                make_float2(d[nt][2] + bx, d[nt][3] + by);
        }
    }
}

// smem layouts:
//   FUSE:  A 0..32K | W2 32K..40K | W1 40K..56K | hC 56K..64K
//   POOL:  A 0..32K | W2 32K..40K | poolC 40K..40K+16896 (reduce scratch reuses A)
#define EDGE_SMEM_F (65536 + 256)
#define EDGE_SMEM_P (40960 + 64*66*4 + 256)

// ---------------- edge layer 1 (fused ab): inline pos projections; pad slots copied, not recomputed ----------------
__global__ __launch_bounds__(256, 3) void edge1_mma_kernel(
    const float* __restrict__ W1,      // [9][64]
    const float* __restrict__ b1,
    const float* __restrict__ b2,
    const float* __restrict__ b1n,
    float* __restrict__ abot)
{
    constexpr int PTS = 32;
    extern __shared__ char smem_raw[];
    uint32_t su = smem_u32(smem_raw);
    uint32_t abase = (su + 127) & ~127u;
    char* base = smem_raw + (abase - su);
    char* AC = base;
    char* hC = base + 57344;
    uint32_t sA = abase, sB = abase + 32768, sW1 = abase + 40960, sH = abase + 57344;

    int tid = threadIdx.x, warp = tid >> 5, lane = tid & 31;

    {
        const uint4* s2 = (const uint4*)g_w2s[0];
        uint4* d2p = (uint4*)(base + 32768);
        for (int t = tid; t < 512; t += 256) d2p[t] = s2[t];
        const uint4* s1 = (const uint4*)g_w1s[0];
        uint4* d1p = (uint4*)(base + 40960);
        for (int t = tid; t < 1024; t += 256) d1p[t] = s1[t];
    }

    {
        int lane2 = lane * 2;
        float wa0x=W1[lane2],       wa0y=W1[lane2+1];
        float wa1x=W1[64+lane2],    wa1y=W1[64+lane2+1];
        float wa2x=W1[128+lane2],   wa2y=W1[128+lane2+1];
        float wb0x=W1[192+lane2],   wb0y=W1[192+lane2+1];
        float wb1x=W1[256+lane2],   wb1y=W1[256+lane2+1];
        float wb2x=W1[320+lane2],   wb2y=W1[320+lane2+1];
        float wr0x=W1[384+lane2],   wr0y=W1[384+lane2+1];
        float wr1x=W1[448+lane2],   wr1y=W1[448+lane2+1];
        float wr2x=W1[512+lane2],   wr2y=W1[512+lane2+1];
        float b1x=b1[lane2], b1y=b1[lane2+1];
#pragma unroll
        for (int pp = 0; pp < 4; pp++) {
            int lp = warp * 4 + pp;
            int i = blockIdx.x * PTS + lp;
            float4 pi = g_pos4[i];
            float ax = fmaf(pi.x, wa0x, fmaf(pi.y, wa1x, fmaf(pi.z, wa2x, b1x)));
            float ay = fmaf(pi.x, wa0y, fmaf(pi.y, wa1y, fmaf(pi.z, wa2y, b1y)));
            int rowbase = lp * 8;
#pragma unroll
            for (int slot = 0; slot < 6; slot++) {     // 6 real slots only
                int j = g_knn[i*8 + slot];
                float4 pj = g_pos4[j];
                float rx = pj.x - pi.x, ry = pj.y - pi.y, rz = pj.z - pi.z;
                float h0 = ax;
                h0 = fmaf(pj.x, wb0x, h0); h0 = fmaf(pj.y, wb1x, h0); h0 = fmaf(pj.z, wb2x, h0);
                h0 = fmaf(rx, wr0x, h0);   h0 = fmaf(ry, wr1x, h0);   h0 = fmaf(rz, wr2x, h0);
                float h1 = ay;
                h1 = fmaf(pj.x, wb0y, h1); h1 = fmaf(pj.y, wb1y, h1); h1 = fmaf(pj.z, wb2y, h1);
                h1 = fmaf(rx, wr0y, h1);   h1 = fmaf(ry, wr1y, h1);   h1 = fmaf(rz, wr2y, h1);
                h0 = fmaxf(h0, 0.f); h1 = fmaxf(h1, 0.f);
                uint32_t pk = pack_h2(h0, h1);
                *(uint32_t*)(AC + sw128((uint32_t)((rowbase + slot)*128 + lane2*2))) = pk;
                if (slot == 0) {                       // pad rows 6,7 duplicate slot 0
                    *(uint32_t*)(AC + sw128((uint32_t)((rowbase + 6)*128 + lane2*2))) = pk;
                    *(uint32_t*)(AC + sw128((uint32_t)((rowbase + 7)*128 + lane2*2))) = pk;
                }
            }
        }
    }
    __syncthreads();
    edge_phaseB<8, 1>(sA, sB, b2, hC, nullptr, warp, lane);
    __syncthreads();
    phaseC(sH, sW1, b1n, abot, warp, lane, PTS, blockIdx.x * PTS);
}

// ---------------- edge layers 2/3: gather a/b from abin; MODE 1=fused ab out, 2=pool ----------------
template<int K, int SLOTS, int MODE>
__global__ __launch_bounds__(256, 3) void edge_mma_kernel(
    const float* __restrict__ abin,
    const float* __restrict__ W1rel,
    const float* __restrict__ b2,
    int layer,
    int w1layer,
    const float* __restrict__ b1n,
    float* __restrict__ abot)
{
    constexpr int PTS = 256 / SLOTS;
    constexpr int PPW = PTS / 8;
    extern __shared__ char smem_raw[];
    uint32_t su = smem_u32(smem_raw);
    uint32_t abase = (su + 127) & ~127u;
    char* base = smem_raw + (abase - su);
    char* AC = base;
    char* hC = base + 57344;
    float* poolC = (float*)(base + 40960);
    uint32_t sA = abase, sB = abase + 32768, sW1 = abase + 40960, sH = abase + 57344;

    int tid = threadIdx.x, warp = tid >> 5, lane = tid & 31;

    {
        const uint4* s2 = (const uint4*)g_w2s[layer];
        uint4* d2p = (uint4*)(base + 32768);
        for (int t = tid; t < 512; t += 256) d2p[t] = s2[t];
        if (MODE == 1) {
            const uint4* s1 = (const uint4*)g_w1s[w1layer];
            uint4* d1p = (uint4*)(base + 40960);
            for (int t = tid; t < 1024; t += 256) d1p[t] = s1[t];
        }
    }

    {
        int lane2 = lane * 2;
        float u0x = W1rel[lane2],       u0y = W1rel[lane2 + 1];
        float u1x = W1rel[64 + lane2],  u1y = W1rel[64 + lane2 + 1];
        float u2x = W1rel[128 + lane2], u2y = W1rel[128 + lane2 + 1];
#pragma unroll
        for (int pp = 0; pp < PPW; pp++) {
            int lp = warp * PPW + pp;
            int i = blockIdx.x * PTS + lp;
            float2 a = *(const float2*)&abin[(size_t)i*128 + lane2];
            float4 pi = g_pos4[i];
            int rowbase = lp * SLOTS;
#pragma unroll
            for (int slot = 0; slot < K; slot++) {
                int j = g_knn[i*8 + slot];
                float4 pj = g_pos4[j];
                float2 b = *(const float2*)&abin[(size_t)j*128 + 64 + lane2];
                float rx = pj.x - pi.x, ry = pj.y - pi.y, rz = pj.z - pi.z;
                float h0 = fmaxf(fmaf(rx, u0x, fmaf(ry, u1x, fmaf(rz, u2x, a.x + b.x))), 0.f);
                float h1 = fmaxf(fmaf(rx, u0y, fmaf(ry, u1y, fmaf(rz, u2y, a.y + b.y))), 0.f);
                uint32_t pk = pack_h2(h0, h1);
                *(uint32_t*)(AC + sw128((uint32_t)((rowbase + slot)*128 + lane2*2))) = pk;
                if (slot == 0) {
#pragma unroll
                    for (int e = K; e < SLOTS; e++)    // pad rows duplicate slot 0
                        *(uint32_t*)(AC + sw128((uint32_t)((rowbase + e)*128 + lane2*2))) = pk;
                }
            }
        }
    }
    __syncthreads();
    edge_phaseB<SLOTS, MODE>(sA, sB, b2, hC, poolC, warp, lane);
    if (MODE == 1) {
        __syncthreads();
        phaseC(sH, sW1, b1n, abot, warp, lane, PTS, blockIdx.x * PTS);
    }
    if (MODE == 2) {
        __syncthreads();
        // block covers 64 points of one graph -> block max per channel, then atomicMax
        float* red = (float*)AC;          // A tile no longer needed
        int col = tid & 63, grp = tid >> 6;
        float m = 0.f;                    // post-relu values >= 0
        for (int r = grp; r < 64; r += 4) m = fmaxf(m, poolC[r*66 + col]);
        red[grp*64 + col] = m;
        __syncthreads();
        if (grp == 0) {
            m = fmaxf(fmaxf(red[col], red[64 + col]), fmaxf(red[128 + col], red[192 + col]));
            int graph = blockIdx.x >> 4;  // 16 blocks (of 64 pts) per graph
            atomicMax(&g_pool[graph*64 + col], __float_as_uint(m));
        }
    }
}

// ---------------- regression head: out = pool @ regW + regb ----------------
__global__ __launch_bounds__(64) void head_kernel(const float* __restrict__ regW,
                                                  const float* __restrict__ regb,
                                                  float* __restrict__ out)
{
    __shared__ float hv[64];
    int g = blockIdx.x, tid = threadIdx.x;
    hv[tid] = __uint_as_float(g_pool[g*64 + tid]);
    __syncthreads();
    if (tid < 6) {
        float acc = regb[tid];
#pragma unroll
        for (int c = 0; c < 64; c++)
            acc = fmaf(hv[c], regW[c*6 + tid], acc);
        out[g*6 + tid] = acc;
    }
}

// ---------------- launch ----------------
extern "C" void kernel_launch(void* const* d_in, const int* in_sizes, int n_in,
                              void* d_out, int out_size)
{
    (void)in_sizes; (void)n_in; (void)out_size;
    const float* pos  = (const float*)d_in[1];
    const float* c1W1 = (const float*)d_in[3];
    const float* c1b1 = (const float*)d_in[4];
    const float* c1W2 = (const float*)d_in[5];
    const float* c1b2 = (const float*)d_in[6];
    const float* c2W1 = (const float*)d_in[7];
    const float* c2b1 = (const float*)d_in[8];
    const float* c2W2 = (const float*)d_in[9];
    const float* c2b2 = (const float*)d_in[10];
    const float* c3W1 = (const float*)d_in[11];
    const float* c3b1 = (const float*)d_in[12];
    const float* c3W2 = (const float*)d_in[13];
    const float* c3b2 = (const float*)d_in[14];
    const float* regW = (const float*)d_in[15];
    const float* regb = (const float*)d_in[16];
    float* out = (float*)d_out;

    float *abA, *abB;
    cudaGetSymbolAddress((void**)&abA, g_abA);
    cudaGetSymbolAddress((void**)&abB, g_abB);
    cudaFuncSetAttribute((const void*)edge1_mma_kernel, cudaFuncAttributeMaxDynamicSharedMemorySize, EDGE_SMEM_F);
    cudaFuncSetAttribute((const void*)edge_mma_kernel<4,4,1>, cudaFuncAttributeMaxDynamicSharedMemorySize, EDGE_SMEM_F);
    cudaFuncSetAttribute((const void*)edge_mma_kernel<3,4,2>, cudaFuncAttributeMaxDynamicSharedMemorySize, EDGE_SMEM_P);

    knn_kernel<<<BGRAPH * 4, 128>>>(pos);
    w2split_kernel<<<96, 128>>>(c1W2, c2W2, c3W2);   // also zeroes g_pool each call
    w1split_kernel<<<128, 128>>>(c2W1, c3W1);
    // layer 1 (fused: writes abA)
    edge1_mma_kernel<<<NPTS/32, 256, EDGE_SMEM_F>>>(c1W1, c1b1, c1b2, c2b1, abA);
    // layer 2 (fused: reads abA, writes abB)
    edge_mma_kernel<4,4,1><<<NPTS/64, 256, EDGE_SMEM_F>>>(abA, c2W1 + 128*64, c2b2, 1, 1, c3b1, abB);
    // layer 3 (pool: reads abB, block-max + atomicMax into g_pool)
    edge_mma_kernel<3,4,2><<<NPTS/64, 256, EDGE_SMEM_P>>>(abB, c3W1 + 128*64, c3b2, 2, 0, nullptr, nullptr);
    head_kernel<<<BGRAPH, 64>>>(regW, regb, out);
}

// round 14
// speedup vs baseline: 2.4508x; 1.0108x over previous
#include <cuda_runtime.h>
#include <cuda_fp16.h>
#include <float.h>
#include <stdint.h>

#define NPTS   65536
#define BGRAPH 64
#define PPG    1024

// ---------------- scratch (device globals; no allocation) ----------------
__device__ int      g_knn[NPTS * 8];          // 6 real + 2 pad (dup of nn0)
__device__ float    g_abA[NPTS * 128];        // layer-2 input: a (+b1) cols 0..63, b cols 64..127
__device__ float    g_abB[NPTS * 128];        // layer-3 input (double buffer)
__device__ float4   g_pos4[NPTS];             // packed positions (x,y,z,0)
__device__ uint32_t g_pool[BGRAPH * 64];      // per-graph channel max (uint-ordered floats >= 0)
__device__ __align__(16) __half g_w2s[3][4096];  // [layer] swizzled fp16 W2^T [n=64][k=64]
__device__ __align__(16) __half g_w1s[2][8192];  // [layer] swizzled fp16 W1ab^T [n=128][k=64]

// ---------------- helpers (base-ISA: ldmatrix + mma.sync, sm_80+) ----------------
__device__ __forceinline__ uint32_t smem_u32(const void* p) {
    uint32_t a;
    asm("{ .reg .u64 t; cvta.to.shared.u64 t, %1; cvt.u32.u64 %0, t; }" : "=r"(a) : "l"(p));
    return a;
}
__device__ __forceinline__ uint32_t sw128(uint32_t off) { return off ^ ((off >> 3) & 0x70); }
__device__ __forceinline__ uint32_t pack_h2(float a, float b) {
    __half2 h = __floats2half2_rn(a, b);
    return *reinterpret_cast<uint32_t*>(&h);
}
__device__ __forceinline__ void ldsm_x4(uint32_t* r, uint32_t addr) {
    asm volatile("ldmatrix.sync.aligned.m8n8.x4.shared.b16 {%0,%1,%2,%3}, [%4];"
                 : "=r"(r[0]), "=r"(r[1]), "=r"(r[2]), "=r"(r[3]) : "r"(addr));
}
__device__ __forceinline__ void mma_16816(float* d, const uint32_t* a, const uint32_t* b) {
    asm volatile("mma.sync.aligned.m16n8k16.row.col.f32.f16.f16.f32 "
                 "{%0,%1,%2,%3}, {%4,%5,%6,%7}, {%8,%9}, {%0,%1,%2,%3};"
                 : "+f"(d[0]), "+f"(d[1]), "+f"(d[2]), "+f"(d[3])
                 : "r"(a[0]), "r"(a[1]), "r"(a[2]), "r"(a[3]), "r"(b[0]), "r"(b[1]));
}

// ---------------- kNN (k=6, 2 queries/thread, 4 blocks/graph; matches jax top_k ties) ----------------
__global__ __launch_bounds__(128) void knn_kernel(const float* __restrict__ pos)
{
    __shared__ float4 cand[128];
    int graph = blockIdx.x >> 2;
    int q0 = graph * PPG + ((blockIdx.x & 3) << 8) + threadIdx.x;
    int q1 = q0 + 128;
    float ax = pos[3*q0], ay = pos[3*q0+1], az = pos[3*q0+2];
    float bx = pos[3*q1], by = pos[3*q1+1], bz = pos[3*q1+2];
    float as = ax*ax + ay*ay + az*az;
    float bs = bx*bx + by*by + bz*bz;
    g_pos4[q0] = make_float4(ax, ay, az, 0.f);
    g_pos4[q1] = make_float4(bx, by, bz, 0.f);
    float ad[6], bd[6]; int ai[6], bi[6];
#pragma unroll
    for (int t = 0; t < 6; t++) { ad[t] = FLT_MAX; ai[t] = 0; bd[t] = FLT_MAX; bi[t] = 0; }
    for (int tile = 0; tile < PPG; tile += 128) {
        int c = graph * PPG + tile + threadIdx.x;
        float cx = pos[3*c], cy = pos[3*c+1], cz = pos[3*c+2];
        cand[threadIdx.x] = make_float4(cx, cy, cz, cx*cx + cy*cy + cz*cz);
        __syncthreads();
#pragma unroll 4
        for (int u = 0; u < 128; u++) {
            float4 p = cand[u];
            int cidx = graph*PPG + tile + u;
            float d2a = as + p.w - 2.0f*(ax*p.x + ay*p.y + az*p.z);
            float d2b = bs + p.w - 2.0f*(bx*p.x + by*p.y + bz*p.z);
            if (d2a < ad[5]) {
                ad[5] = d2a; ai[5] = cidx;
#pragma unroll
                for (int t = 5; t > 0; t--)
                    if (ad[t] < ad[t-1]) {
                        float td = ad[t]; ad[t] = ad[t-1]; ad[t-1] = td;
                        int   ti = ai[t]; ai[t] = ai[t-1]; ai[t-1] = ti;
                    }
            }
            if (d2b < bd[5]) {
                bd[5] = d2b; bi[5] = cidx;
#pragma unroll
                for (int t = 5; t > 0; t--)
                    if (bd[t] < bd[t-1]) {
                        float td = bd[t]; bd[t] = bd[t-1]; bd[t-1] = td;
                        int   ti = bi[t]; bi[t] = bi[t-1]; bi[t-1] = ti;
                    }
            }
        }
        __syncthreads();
    }
#pragma unroll
    for (int t = 0; t < 6; t++) { g_knn[q0*8 + t] = ai[t]; g_knn[q1*8 + t] = bi[t]; }
    g_knn[q0*8 + 6] = ai[0]; g_knn[q0*8 + 7] = ai[0];
    g_knn[q1*8 + 6] = bi[0]; g_knn[q1*8 + 7] = bi[0];
}

// ---------------- merged weight split (W2 all layers + W1 layers 2/3) + zero g_pool ----------------
__global__ __launch_bounds__(128) void wsplit_kernel(const float* __restrict__ W2a,
                                                     const float* __restrict__ W2b,
                                                     const float* __restrict__ W2c,
                                                     const float* __restrict__ W1b,
                                                     const float* __restrict__ W1c)
{
    int t = blockIdx.x * 128 + threadIdx.x;        // 224 blocks: 12288 (W2) + 16384 (W1)
    if (t < BGRAPH * 64) g_pool[t] = 0u;           // re-zeroed every launch (graph-replay safe)
    if (t < 12288) {
        int l = t >> 12, nk = t & 4095;
        int n = nk >> 6, k = nk & 63;
        const float* W2 = (l == 0) ? W2a : ((l == 1) ? W2b : W2c);
        g_w2s[l][sw128((uint32_t)(n*128 + k*2)) >> 1] = __float2half_rn(W2[k*64 + n]);
    } else {
        int u = t - 12288;
        int l = u >> 13, nk = u & 8191;
        int n = nk >> 6, k = nk & 63;
        const float* W1 = l ? W1c : W1b;
        float v = (n < 64) ? W1[k*64 + n] : W1[(64 + k)*64 + (n - 64)];
        g_w1s[l][sw128((uint32_t)(n*128 + k*2)) >> 1] = __float2half_rn(v);
    }
}

// ---------------- phase B: W2 GEMM + max over slots + relu (epilogue per nt: d shrinks to 4 regs) ----------
// MODE 1 = FUSE (hC fp16, ALIASED onto W2 region -> sync after bh loads); MODE 2 = POOL (fp32 poolC)
template<int SLOTS, int MODE>
__device__ __forceinline__ void edge_phaseB(
    uint32_t sA, uint32_t sB,
    const float* __restrict__ b2, char* hC, float* poolC,
    int warp, int lane)
{
    const int rb = (warp >> 1) * 64;
    const int ch = (warp & 1) * 32;
    const int gn0 = (warp & 1) * 4;
    int acolb = (lane >> 4) * 16;

    uint32_t bh[4][4][2];
    {
        uint32_t laddr = (uint32_t)((lane & 7)*128 + ((lane >> 4) & 1)*32 + ((lane >> 3) & 1)*16);
#pragma unroll
        for (int nt = 0; nt < 4; nt++)
#pragma unroll
            for (int kp = 0; kp < 4; kp += 2) {
                uint32_t boff = sw128((uint32_t)((gn0 + nt)*1024 + kp*32) + laddr);
                uint32_t r[4];
                ldsm_x4(r, sB + boff);
                bh[nt][kp][0] = r[0]; bh[nt][kp][1] = r[1];
                bh[nt][kp+1][0] = r[2]; bh[nt][kp+1][1] = r[3];
            }
    }
    if (MODE == 1) __syncthreads();    // hC aliases W2 smem: all warps' bh must be in regs first

#pragma unroll
    for (int rt = 0; rt < 4; rt++) {
        uint32_t afr[4][4];
        uint32_t arow_off = (uint32_t)((rb + rt*16 + (lane & 15)) * 128);
#pragma unroll
        for (int k = 0; k < 4; k++)
            ldsm_x4(afr[k], sA + sw128(arow_off + k*32 + acolb));

#pragma unroll
        for (int nt = 0; nt < 4; nt++) {
            float d[4] = {0.f, 0.f, 0.f, 0.f};
#pragma unroll
            for (int k = 0; k < 4; k++) mma_16816(d, afr[k], bh[nt][k]);

            float m0 = d[0], m1 = d[1], m2 = d[2], m3 = d[3];
            if (SLOTS == 8) {
#pragma unroll
                for (int s = 4; s <= 16; s <<= 1) {
                    m0 = fmaxf(m0, __shfl_xor_sync(0xffffffffu, m0, s));
                    m1 = fmaxf(m1, __shfl_xor_sync(0xffffffffu, m1, s));
                    m2 = fmaxf(m2, __shfl_xor_sync(0xffffffffu, m2, s));
                    m3 = fmaxf(m3, __shfl_xor_sync(0xffffffffu, m3, s));
                }
                int col = ch + nt*8 + (lane & 3)*2;
                if (lane < 8) {
                    int lp = (warp >> 1) * 8 + rt * 2 + (lane >> 2);
                    float v0 = (lane < 4) ? m0 : m2;
                    float v1 = (lane < 4) ? m1 : m3;
                    v0 = fmaxf(v0 + b2[col], 0.f);
                    v1 = fmaxf(v1 + b2[col+1], 0.f);
                    *(uint32_t*)(hC + sw128((uint32_t)(lp*128 + col*2))) = pack_h2(v0, v1);
                }
            } else {   // SLOTS == 4
#pragma unroll
                for (int s = 4; s <= 8; s <<= 1) {
                    m0 = fmaxf(m0, __shfl_xor_sync(0xffffffffu, m0, s));
                    m1 = fmaxf(m1, __shfl_xor_sync(0xffffffffu, m1, s));
                    m2 = fmaxf(m2, __shfl_xor_sync(0xffffffffu, m2, s));
                    m3 = fmaxf(m3, __shfl_xor_sync(0xffffffffu, m3, s));
                }
                int col = ch + nt*8 + (lane & 3)*2;
                if ((lane & 15) < 4) {
                    int lpb = (warp >> 1) * 16 + rt * 4;
                    int g = lane >> 4;
                    float v0 = fmaxf(m0 + b2[col], 0.f), v1 = fmaxf(m1 + b2[col+1], 0.f);
                    float v2 = fmaxf(m2 + b2[col], 0.f), v3 = fmaxf(m3 + b2[col+1], 0.f);
                    if (MODE == 1) {
                        *(uint32_t*)(hC + sw128((uint32_t)((lpb + g)*128 + col*2)))     = pack_h2(v0, v1);
                        *(uint32_t*)(hC + sw128((uint32_t)((lpb + 2 + g)*128 + col*2))) = pack_h2(v2, v3);
                    } else {
                        *(float2*)&poolC[(lpb + g)*66 + col]     = make_float2(v0, v1);
                        *(float2*)&poolC[(lpb + 2 + g)*66 + col] = make_float2(v2, v3);
                    }
                }
            }
        }
    }
}

// ---------------- phase C: ab projection GEMM (h[PTS x 64] fp16 @ W1ab^T -> ab out fp32) ----------------
__device__ __forceinline__ void phaseC(
    uint32_t sH, uint32_t sW1, const float* __restrict__ b1n,
    float* __restrict__ abot, int warp, int lane, int PTS, int pbase)
{
    int ntile = (PTS / 16) * 4;
    uint32_t laddr = (uint32_t)((lane & 7)*128 + ((lane >> 4) & 1)*32 + ((lane >> 3) & 1)*16);
    uint32_t acolb = (uint32_t)((lane >> 4) * 16);
    for (int t = warp; t < ntile; t += 8) {
        int rt = t >> 2, cg = t & 3;
        uint32_t afr[4][4];
        uint32_t arow = (uint32_t)((rt*16 + (lane & 15)) * 128);
#pragma unroll
        for (int k = 0; k < 4; k++)
            ldsm_x4(afr[k], sH + sw128(arow + k*32 + acolb));
#pragma unroll
        for (int nt = 0; nt < 4; nt++) {
            uint32_t bh[4][2];
#pragma unroll
            for (int kp = 0; kp < 4; kp += 2) {
                uint32_t bo = sw128((uint32_t)((cg*4 + nt)*1024 + kp*32) + laddr);
                uint32_t r[4];
                ldsm_x4(r, sW1 + bo);
                bh[kp][0] = r[0]; bh[kp][1] = r[1]; bh[kp+1][0] = r[2]; bh[kp+1][1] = r[3];
            }
            float d[4] = {0.f, 0.f, 0.f, 0.f};
#pragma unroll
            for (int k = 0; k < 4; k++) mma_16816(d, afr[k], bh[k]);
            int r0 = rt*16 + (lane >> 2);
            int col = cg*32 + nt*8 + (lane & 3)*2;
            float bx = 0.f, by = 0.f;
            if (col < 64) { bx = b1n[col]; by = b1n[col + 1]; }
            *(float2*)&abot[(size_t)(pbase + r0)*128 + col]     = make_float2(d[0] + bx, d[1] + by);
            *(float2*)&abot[(size_t)(pbase + r0 + 8)*128 + col] = make_float2(d[2] + bx, d[3] + by);
        }
    }
}

// smem layouts:
//   FUSE:  A 0..32K | W2->hC 32K..40K (aliased after bh load) | W1 40K..56K        = 56.25KB -> 4 CTAs
//   POOL:  A 0..32K | W2 32K..40K | poolC 40K..40K+16896 (reduce scratch reuses A) = 56.75KB -> 3 CTAs
#define EDGE_SMEM_F (32768 + 8192 + 16384 + 256)
#define EDGE_SMEM_P (32768 + 8192 + 64*66*4 + 256)

// ---------------- edge layer 1 (fused ab): inline pos projections ----------------
__global__ __launch_bounds__(256, 4) void edge1_mma_kernel(
    const float* __restrict__ W1,      // [9][64]
    const float* __restrict__ b1,
    const float* __restrict__ b2,
    const float* __restrict__ b1n,
    float* __restrict__ abot)
{
    constexpr int PTS = 32;
    extern __shared__ char smem_raw[];
    uint32_t su = smem_u32(smem_raw);
    uint32_t abase = (su + 127) & ~127u;
    char* base = smem_raw + (abase - su);
    char* AC = base;
    char* hC = base + 32768;               // aliases W2 region after bh loads
    uint32_t sA = abase, sB = abase + 32768, sW1 = abase + 40960, sH = abase + 32768;

    int tid = threadIdx.x, warp = tid >> 5, lane = tid & 31;

    {
        const uint4* s2 = (const uint4*)g_w2s[0];
        uint4* d2p = (uint4*)(base + 32768);
        for (int t = tid; t < 512; t += 256) d2p[t] = s2[t];
        const uint4* s1 = (const uint4*)g_w1s[0];
        uint4* d1p = (uint4*)(base + 40960);
        for (int t = tid; t < 1024; t += 256) d1p[t] = s1[t];
    }

    {
        int lane2 = lane * 2;
        float wa0x=W1[lane2],       wa0y=W1[lane2+1];
        float wa1x=W1[64+lane2],    wa1y=W1[64+lane2+1];
        float wa2x=W1[128+lane2],   wa2y=W1[128+lane2+1];
        float wb0x=W1[192+lane2],   wb0y=W1[192+lane2+1];
        float wb1x=W1[256+lane2],   wb1y=W1[256+lane2+1];
        float wb2x=W1[320+lane2],   wb2y=W1[320+lane2+1];
        float wr0x=W1[384+lane2],   wr0y=W1[384+lane2+1];
        float wr1x=W1[448+lane2],   wr1y=W1[448+lane2+1];
        float wr2x=W1[512+lane2],   wr2y=W1[512+lane2+1];
        float b1x=b1[lane2], b1y=b1[lane2+1];
#pragma unroll
        for (int pp = 0; pp < 4; pp++) {
            int lp = warp * 4 + pp;
            int i = blockIdx.x * PTS + lp;
            float4 pi = g_pos4[i];
            float ax = fmaf(pi.x, wa0x, fmaf(pi.y, wa1x, fmaf(pi.z, wa2x, b1x)));
            float ay = fmaf(pi.x, wa0y, fmaf(pi.y, wa1y, fmaf(pi.z, wa2y, b1y)));
            int rowbase = lp * 8;
#pragma unroll
            for (int slot = 0; slot < 6; slot++) {
                int j = g_knn[i*8 + slot];
                float4 pj = g_pos4[j];
                float rx = pj.x - pi.x, ry = pj.y - pi.y, rz = pj.z - pi.z;
                float h0 = ax;
                h0 = fmaf(pj.x, wb0x, h0); h0 = fmaf(pj.y, wb1x, h0); h0 = fmaf(pj.z, wb2x, h0);
                h0 = fmaf(rx, wr0x, h0);   h0 = fmaf(ry, wr1x, h0);   h0 = fmaf(rz, wr2x, h0);
                float h1 = ay;
                h1 = fmaf(pj.x, wb0y, h1); h1 = fmaf(pj.y, wb1y, h1); h1 = fmaf(pj.z, wb2y, h1);
                h1 = fmaf(rx, wr0y, h1);   h1 = fmaf(ry, wr1y, h1);   h1 = fmaf(rz, wr2y, h1);
                h0 = fmaxf(h0, 0.f); h1 = fmaxf(h1, 0.f);
                uint32_t pk = pack_h2(h0, h1);
                *(uint32_t*)(AC + sw128((uint32_t)((rowbase + slot)*128 + lane2*2))) = pk;
                if (slot == 0) {
                    *(uint32_t*)(AC + sw128((uint32_t)((rowbase + 6)*128 + lane2*2))) = pk;
                    *(uint32_t*)(AC + sw128((uint32_t)((rowbase + 7)*128 + lane2*2))) = pk;
                }
            }
        }
    }
    __syncthreads();
    edge_phaseB<8, 1>(sA, sB, b2, hC, nullptr, warp, lane);
    __syncthreads();
    phaseC(sH, sW1, b1n, abot, warp, lane, PTS, blockIdx.x * PTS);
}

// ---------------- edge layers 2/3: gather a/b from abin; MODE 1=fused ab out, 2=pool ----------------
template<int K, int SLOTS, int MODE>
__global__ __launch_bounds__(256, (MODE == 2 ? 3 : 4)) void edge_mma_kernel(
    const float* __restrict__ abin,
    const float* __restrict__ W1rel,
    const float* __restrict__ b2,
    int layer,
    int w1layer,
    const float* __restrict__ b1n,
    float* __restrict__ abot)
{
    constexpr int PTS = 256 / SLOTS;
    constexpr int PPW = PTS / 8;
    extern __shared__ char smem_raw[];
    uint32_t su = smem_u32(smem_raw);
    uint32_t abase = (su + 127) & ~127u;
    char* base = smem_raw + (abase - su);
    char* AC = base;
    char* hC = base + 32768;                 // MODE 1: aliases W2 region
    float* poolC = (float*)(base + 40960);   // MODE 2
    uint32_t sA = abase, sB = abase + 32768, sW1 = abase + 40960, sH = abase + 32768;

    int tid = threadIdx.x, warp = tid >> 5, lane = tid & 31;

    {
        const uint4* s2 = (const uint4*)g_w2s[layer];
        uint4* d2p = (uint4*)(base + 32768);
        for (int t = tid; t < 512; t += 256) d2p[t] = s2[t];
        if (MODE == 1) {
            const uint4* s1 = (const uint4*)g_w1s[w1layer];
            uint4* d1p = (uint4*)(base + 40960);
            for (int t = tid; t < 1024; t += 256) d1p[t] = s1[t];
        }
    }

    {
        int lane2 = lane * 2;
        float u0x = W1rel[lane2],       u0y = W1rel[lane2 + 1];
        float u1x = W1rel[64 + lane2],  u1y = W1rel[64 + lane2 + 1];
        float u2x = W1rel[128 + lane2], u2y = W1rel[128 + lane2 + 1];
#pragma unroll
        for (int pp = 0; pp < PPW; pp++) {
            int lp = warp * PPW + pp;
            int i = blockIdx.x * PTS + lp;
            float2 a = *(const float2*)&abin[(size_t)i*128 + lane2];
            float4 pi = g_pos4[i];
            int rowbase = lp * SLOTS;
#pragma unroll
            for (int slot = 0; slot < K; slot++) {
                int j = g_knn[i*8 + slot];
                float4 pj = g_pos4[j];
                float2 b = *(const float2*)&abin[(size_t)j*128 + 64 + lane2];
                float rx = pj.x - pi.x, ry = pj.y - pi.y, rz = pj.z - pi.z;
                float h0 = fmaxf(fmaf(rx, u0x, fmaf(ry, u1x, fmaf(rz, u2x, a.x + b.x))), 0.f);
                float h1 = fmaxf(fmaf(rx, u0y, fmaf(ry, u1y, fmaf(rz, u2y, a.y + b.y))), 0.f);
                uint32_t pk = pack_h2(h0, h1);
                *(uint32_t*)(AC + sw128((uint32_t)((rowbase + slot)*128 + lane2*2))) = pk;
                if (slot == 0) {
#pragma unroll
                    for (int e = K; e < SLOTS; e++)
                        *(uint32_t*)(AC + sw128((uint32_t)((rowbase + e)*128 + lane2*2))) = pk;
                }
            }
        }
    }
    __syncthreads();
    edge_phaseB<SLOTS, MODE>(sA, sB, b2, hC, poolC, warp, lane);
    if (MODE == 1) {
        __syncthreads();
        phaseC(sH, sW1, b1n, abot, warp, lane, PTS, blockIdx.x * PTS);
    }
    if (MODE == 2) {
        __syncthreads();
        float* red = (float*)AC;
        int col = tid & 63, grp = tid >> 6;
        float m = 0.f;
        for (int r = grp; r < 64; r += 4) m = fmaxf(m, poolC[r*66 + col]);
        red[grp*64 + col] = m;
        __syncthreads();
        if (grp == 0) {
            m = fmaxf(fmaxf(red[col], red[64 + col]), fmaxf(red[128 + col], red[192 + col]));
            int graph = blockIdx.x >> 4;
            atomicMax(&g_pool[graph*64 + col], __float_as_uint(m));
        }
    }
}

// ---------------- regression head: out = pool @ regW + regb ----------------
__global__ __launch_bounds__(64) void head_kernel(const float* __restrict__ regW,
                                                  const float* __restrict__ regb,
                                                  float* __restrict__ out)
{
    __shared__ float hv[64];
    int g = blockIdx.x, tid = threadIdx.x;
    hv[tid] = __uint_as_float(g_pool[g*64 + tid]);
    __syncthreads();
    if (tid < 6) {
        float acc = regb[tid];
#pragma unroll
        for (int c = 0; c < 64; c++)
            acc = fmaf(hv[c], regW[c*6 + tid], acc);
        out[g*6 + tid] = acc;
    }
}

// ---------------- launch ----------------
extern "C" void kernel_launch(void* const* d_in, const int* in_sizes, int n_in,
                              void* d_out, int out_size)
{
    (void)in_sizes; (void)n_in; (void)out_size;
    const float* pos  = (const float*)d_in[1];
    const float* c1W1 = (const float*)d_in[3];
    const float* c1b1 = (const float*)d_in[4];
    const float* c1W2 = (const float*)d_in[5];
    const float* c1b2 = (const float*)d_in[6];
    const float* c2W1 = (const float*)d_in[7];
    const float* c2b1 = (const float*)d_in[8];
    const float* c2W2 = (const float*)d_in[9];
    const float* c2b2 = (const float*)d_in[10];
    const float* c3W1 = (const float*)d_in[11];
    const float* c3b1 = (const float*)d_in[12];
    const float* c3W2 = (const float*)d_in[13];
    const float* c3b2 = (const float*)d_in[14];
    const float* regW = (const float*)d_in[15];
    const float* regb = (const float*)d_in[16];
    float* out = (float*)d_out;

    float *abA, *abB;
    cudaGetSymbolAddress((void**)&abA, g_abA);
    cudaGetSymbolAddress((void**)&abB, g_abB);
    cudaFuncSetAttribute((const void*)edge1_mma_kernel, cudaFuncAttributeMaxDynamicSharedMemorySize, EDGE_SMEM_F);
    cudaFuncSetAttribute((const void*)edge_mma_kernel<4,4,1>, cudaFuncAttributeMaxDynamicSharedMemorySize, EDGE_SMEM_F);
    cudaFuncSetAttribute((const void*)edge_mma_kernel<3,4,2>, cudaFuncAttributeMaxDynamicSharedMemorySize, EDGE_SMEM_P);

    knn_kernel<<<BGRAPH * 4, 128>>>(pos);
    wsplit_kernel<<<224, 128>>>(c1W2, c2W2, c3W2, c2W1, c3W1);   // also zeroes g_pool
    edge1_mma_kernel<<<NPTS/32, 256, EDGE_SMEM_F>>>(c1W1, c1b1, c1b2, c2b1, abA);
    edge_mma_kernel<4,4,1><<<NPTS/64, 256, EDGE_SMEM_F>>>(abA, c2W1 + 128*64, c2b2, 1, 1, c3b1, abB);
    edge_mma_kernel<3,4,2><<<NPTS/64, 256, EDGE_SMEM_P>>>(abB, c3W1 + 128*64, c3b2, 2, 0, nullptr, nullptr);
    head_kernel<<<BGRAPH, 64>>>(regW, regb, out);
}

// round 15
// speedup vs baseline: 2.4659x; 1.0062x over previous
#include <cuda_runtime.h>
#include <cuda_fp16.h>
#include <float.h>
#include <stdint.h>

#define NPTS   65536
#define BGRAPH 64
#define PPG    1024

// ---------------- scratch (device globals; no allocation) ----------------
__device__ int      g_knn[NPTS * 8];          // 6 real + 2 pad (dup of nn0)
__device__ __half   g_abA[NPTS * 128];        // fp16: a (+b1) cols 0..63, b cols 64..127
__device__ __half   g_abB[NPTS * 128];        // fp16 double buffer (layer-3 input)
__device__ float4   g_pos4[NPTS];             // packed positions (x,y,z,0)
__device__ uint32_t g_pool[BGRAPH * 64];      // per-graph channel max (uint-ordered floats >= 0)
__device__ __align__(16) __half g_w2s[3][4096];  // [layer] swizzled fp16 W2^T [n=64][k=64]
__device__ __align__(16) __half g_w1s[2][8192];  // [layer] swizzled fp16 W1ab^T [n=128][k=64]

// ---------------- helpers (base-ISA: ldmatrix + mma.sync, sm_80+) ----------------
__device__ __forceinline__ uint32_t smem_u32(const void* p) {
    uint32_t a;
    asm("{ .reg .u64 t; cvta.to.shared.u64 t, %1; cvt.u32.u64 %0, t; }" : "=r"(a) : "l"(p));
    return a;
}
__device__ __forceinline__ uint32_t sw128(uint32_t off) { return off ^ ((off >> 3) & 0x70); }
__device__ __forceinline__ uint32_t pack_h2(float a, float b) {
    __half2 h = __floats2half2_rn(a, b);
    return *reinterpret_cast<uint32_t*>(&h);
}
__device__ __forceinline__ void ldsm_x4(uint32_t* r, uint32_t addr) {
    asm volatile("ldmatrix.sync.aligned.m8n8.x4.shared.b16 {%0,%1,%2,%3}, [%4];"
                 : "=r"(r[0]), "=r"(r[1]), "=r"(r[2]), "=r"(r[3]) : "r"(addr));
}
__device__ __forceinline__ void mma_16816(float* d, const uint32_t* a, const uint32_t* b) {
    asm volatile("mma.sync.aligned.m16n8k16.row.col.f32.f16.f16.f32 "
                 "{%0,%1,%2,%3}, {%4,%5,%6,%7}, {%8,%9}, {%0,%1,%2,%3};"
                 : "+f"(d[0]), "+f"(d[1]), "+f"(d[2]), "+f"(d[3])
                 : "r"(a[0]), "r"(a[1]), "r"(a[2]), "r"(a[3]), "r"(b[0]), "r"(b[1]));
}

// ---------------- kNN (k=6, 2 queries/thread, 4 blocks/graph; matches jax top_k ties) ----------------
__global__ __launch_bounds__(128) void knn_kernel(const float* __restrict__ pos)
{
    __shared__ float4 cand[128];
    int graph = blockIdx.x >> 2;
    int q0 = graph * PPG + ((blockIdx.x & 3) << 8) + threadIdx.x;
    int q1 = q0 + 128;
    float ax = pos[3*q0], ay = pos[3*q0+1], az = pos[3*q0+2];
    float bx = pos[3*q1], by = pos[3*q1+1], bz = pos[3*q1+2];
    float as = ax*ax + ay*ay + az*az;
    float bs = bx*bx + by*by + bz*bz;
    g_pos4[q0] = make_float4(ax, ay, az, 0.f);
    g_pos4[q1] = make_float4(bx, by, bz, 0.f);
    float ad[6], bd[6]; int ai[6], bi[6];
#pragma unroll
    for (int t = 0; t < 6; t++) { ad[t] = FLT_MAX; ai[t] = 0; bd[t] = FLT_MAX; bi[t] = 0; }
    for (int tile = 0; tile < PPG; tile += 128) {
        int c = graph * PPG + tile + threadIdx.x;
        float cx = pos[3*c], cy = pos[3*c+1], cz = pos[3*c+2];
        cand[threadIdx.x] = make_float4(cx, cy, cz, cx*cx + cy*cy + cz*cz);
        __syncthreads();
#pragma unroll 4
        for (int u = 0; u < 128; u++) {
            float4 p = cand[u];
            int cidx = graph*PPG + tile + u;
            float d2a = as + p.w - 2.0f*(ax*p.x + ay*p.y + az*p.z);
            float d2b = bs + p.w - 2.0f*(bx*p.x + by*p.y + bz*p.z);
            if (d2a < ad[5]) {
                ad[5] = d2a; ai[5] = cidx;
#pragma unroll
                for (int t = 5; t > 0; t--)
                    if (ad[t] < ad[t-1]) {
                        float td = ad[t]; ad[t] = ad[t-1]; ad[t-1] = td;
                        int   ti = ai[t]; ai[t] = ai[t-1]; ai[t-1] = ti;
                    }
            }
            if (d2b < bd[5]) {
                bd[5] = d2b; bi[5] = cidx;
#pragma unroll
                for (int t = 5; t > 0; t--)
                    if (bd[t] < bd[t-1]) {
                        float td = bd[t]; bd[t] = bd[t-1]; bd[t-1] = td;
                        int   ti = bi[t]; bi[t] = bi[t-1]; bi[t-1] = ti;
                    }
            }
        }
        __syncthreads();
    }
#pragma unroll
    for (int t = 0; t < 6; t++) { g_knn[q0*8 + t] = ai[t]; g_knn[q1*8 + t] = bi[t]; }
    g_knn[q0*8 + 6] = ai[0]; g_knn[q0*8 + 7] = ai[0];
    g_knn[q1*8 + 6] = bi[0]; g_knn[q1*8 + 7] = bi[0];
}

// ---------------- merged weight split (W2 all layers + W1 layers 2/3) + zero g_pool ----------------
__global__ __launch_bounds__(128) void wsplit_kernel(const float* __restrict__ W2a,
                                                     const float* __restrict__ W2b,
                                                     const float* __restrict__ W2c,
                                                     const float* __restrict__ W1b,
                                                     const float* __restrict__ W1c)
{
    int t = blockIdx.x * 128 + threadIdx.x;        // 224 blocks: 12288 (W2) + 16384 (W1)
    if (t < BGRAPH * 64) g_pool[t] = 0u;           // re-zeroed every launch (graph-replay safe)
    if (t < 12288) {
        int l = t >> 12, nk = t & 4095;
        int n = nk >> 6, k = nk & 63;
        const float* W2 = (l == 0) ? W2a : ((l == 1) ? W2b : W2c);
        g_w2s[l][sw128((uint32_t)(n*128 + k*2)) >> 1] = __float2half_rn(W2[k*64 + n]);
    } else {
        int u = t - 12288;
        int l = u >> 13, nk = u & 8191;
        int n = nk >> 6, k = nk & 63;
        const float* W1 = l ? W1c : W1b;
        float v = (n < 64) ? W1[k*64 + n] : W1[(64 + k)*64 + (n - 64)];
        g_w1s[l][sw128((uint32_t)(n*128 + k*2)) >> 1] = __float2half_rn(v);
    }
}

// ---------------- phase B: W2 GEMM + max over slots + relu ----------------
// MODE 1 = FUSE (hC fp16, ALIASED onto W2 region -> sync after bh loads); MODE 2 = POOL (fp32 poolC)
template<int SLOTS, int MODE>
__device__ __forceinline__ void edge_phaseB(
    uint32_t sA, uint32_t sB,
    const float* __restrict__ b2, char* hC, float* poolC,
    int warp, int lane)
{
    const int rb = (warp >> 1) * 64;
    const int ch = (warp & 1) * 32;
    const int gn0 = (warp & 1) * 4;
    int acolb = (lane >> 4) * 16;

    uint32_t bh[4][4][2];
    {
        uint32_t laddr = (uint32_t)((lane & 7)*128 + ((lane >> 4) & 1)*32 + ((lane >> 3) & 1)*16);
#pragma unroll
        for (int nt = 0; nt < 4; nt++)
#pragma unroll
            for (int kp = 0; kp < 4; kp += 2) {
                uint32_t boff = sw128((uint32_t)((gn0 + nt)*1024 + kp*32) + laddr);
                uint32_t r[4];
                ldsm_x4(r, sB + boff);
                bh[nt][kp][0] = r[0]; bh[nt][kp][1] = r[1];
                bh[nt][kp+1][0] = r[2]; bh[nt][kp+1][1] = r[3];
            }
    }
    if (MODE == 1) __syncthreads();    // hC aliases W2 smem: all warps' bh must be in regs first

#pragma unroll
    for (int rt = 0; rt < 4; rt++) {
        uint32_t afr[4][4];
        uint32_t arow_off = (uint32_t)((rb + rt*16 + (lane & 15)) * 128);
#pragma unroll
        for (int k = 0; k < 4; k++)
            ldsm_x4(afr[k], sA + sw128(arow_off + k*32 + acolb));

#pragma unroll
        for (int nt = 0; nt < 4; nt++) {
            float d[4] = {0.f, 0.f, 0.f, 0.f};
#pragma unroll
            for (int k = 0; k < 4; k++) mma_16816(d, afr[k], bh[nt][k]);

            float m0 = d[0], m1 = d[1], m2 = d[2], m3 = d[3];
            if (SLOTS == 8) {
#pragma unroll
                for (int s = 4; s <= 16; s <<= 1) {
                    m0 = fmaxf(m0, __shfl_xor_sync(0xffffffffu, m0, s));
                    m1 = fmaxf(m1, __shfl_xor_sync(0xffffffffu, m1, s));
                    m2 = fmaxf(m2, __shfl_xor_sync(0xffffffffu, m2, s));
                    m3 = fmaxf(m3, __shfl_xor_sync(0xffffffffu, m3, s));
                }
                int col = ch + nt*8 + (lane & 3)*2;
                if (lane < 8) {
                    int lp = (warp >> 1) * 8 + rt * 2 + (lane >> 2);
                    float v0 = (lane < 4) ? m0 : m2;
                    float v1 = (lane < 4) ? m1 : m3;
                    v0 = fmaxf(v0 + b2[col], 0.f);
                    v1 = fmaxf(v1 + b2[col+1], 0.f);
                    *(uint32_t*)(hC + sw128((uint32_t)(lp*128 + col*2))) = pack_h2(v0, v1);
                }
            } else {   // SLOTS == 4
#pragma unroll
                for (int s = 4; s <= 8; s <<= 1) {
                    m0 = fmaxf(m0, __shfl_xor_sync(0xffffffffu, m0, s));
                    m1 = fmaxf(m1, __shfl_xor_sync(0xffffffffu, m1, s));
                    m2 = fmaxf(m2, __shfl_xor_sync(0xffffffffu, m2, s));
                    m3 = fmaxf(m3, __shfl_xor_sync(0xffffffffu, m3, s));
                }
                int col = ch + nt*8 + (lane & 3)*2;
                if ((lane & 15) < 4) {
                    int lpb = (warp >> 1) * 16 + rt * 4;
                    int g = lane >> 4;
                    float v0 = fmaxf(m0 + b2[col], 0.f), v1 = fmaxf(m1 + b2[col+1], 0.f);
                    float v2 = fmaxf(m2 + b2[col], 0.f), v3 = fmaxf(m3 + b2[col+1], 0.f);
                    if (MODE == 1) {
                        *(uint32_t*)(hC + sw128((uint32_t)((lpb + g)*128 + col*2)))     = pack_h2(v0, v1);
                        *(uint32_t*)(hC + sw128((uint32_t)((lpb + 2 + g)*128 + col*2))) = pack_h2(v2, v3);
                    } else {
                        *(float2*)&poolC[(lpb + g)*66 + col]     = make_float2(v0, v1);
                        *(float2*)&poolC[(lpb + 2 + g)*66 + col] = make_float2(v2, v3);
                    }
                }
            }
        }
    }
}

// ---------------- phase C: ab projection GEMM (h fp16 @ W1ab^T -> ab out FP16) ----------------
__device__ __forceinline__ void phaseC(
    uint32_t sH, uint32_t sW1, const float* __restrict__ b1n,
    __half* __restrict__ abot, int warp, int lane, int PTS, int pbase)
{
    int ntile = (PTS / 16) * 4;
    uint32_t laddr = (uint32_t)((lane & 7)*128 + ((lane >> 4) & 1)*32 + ((lane >> 3) & 1)*16);
    uint32_t acolb = (uint32_t)((lane >> 4) * 16);
    for (int t = warp; t < ntile; t += 8) {
        int rt = t >> 2, cg = t & 3;
        uint32_t afr[4][4];
        uint32_t arow = (uint32_t)((rt*16 + (lane & 15)) * 128);
#pragma unroll
        for (int k = 0; k < 4; k++)
            ldsm_x4(afr[k], sH + sw128(arow + k*32 + acolb));
#pragma unroll
        for (int nt = 0; nt < 4; nt++) {
            uint32_t bh[4][2];
#pragma unroll
            for (int kp = 0; kp < 4; kp += 2) {
                uint32_t bo = sw128((uint32_t)((cg*4 + nt)*1024 + kp*32) + laddr);
                uint32_t r[4];
                ldsm_x4(r, sW1 + bo);
                bh[kp][0] = r[0]; bh[kp][1] = r[1]; bh[kp+1][0] = r[2]; bh[kp+1][1] = r[3];
            }
            float d[4] = {0.f, 0.f, 0.f, 0.f};
#pragma unroll
            for (int k = 0; k < 4; k++) mma_16816(d, afr[k], bh[k]);
            int r0 = rt*16 + (lane >> 2);
            int col = cg*32 + nt*8 + (lane & 3)*2;
            float bx = 0.f, by = 0.f;
            if (col < 64) { bx = b1n[col]; by = b1n[col + 1]; }
            *(uint32_t*)&abot[(size_t)(pbase + r0)*128 + col]     = pack_h2(d[0] + bx, d[1] + by);
            *(uint32_t*)&abot[(size_t)(pbase + r0 + 8)*128 + col] = pack_h2(d[2] + bx, d[3] + by);
        }
    }
}

// smem layouts:
//   FUSE:  A 0..32K | W2->hC 32K..40K (aliased after bh load) | W1 40K..56K        -> 4 CTAs
//   POOL:  A 0..32K | W2 32K..40K | poolC 40K..40K+16896 (reduce scratch reuses A) -> 3 CTAs
#define EDGE_SMEM_F (32768 + 8192 + 16384 + 256)
#define EDGE_SMEM_P (32768 + 8192 + 64*66*4 + 256)

// ---------------- edge layer 1 (fused ab): inline pos projections ----------------
__global__ __launch_bounds__(256, 4) void edge1_mma_kernel(
    const float* __restrict__ W1,      // [9][64]
    const float* __restrict__ b1,
    const float* __restrict__ b2,
    const float* __restrict__ b1n,
    __half* __restrict__ abot)
{
    constexpr int PTS = 32;
    extern __shared__ char smem_raw[];
    uint32_t su = smem_u32(smem_raw);
    uint32_t abase = (su + 127) & ~127u;
    char* base = smem_raw + (abase - su);
    char* AC = base;
    char* hC = base + 32768;               // aliases W2 region after bh loads
    uint32_t sA = abase, sB = abase + 32768, sW1 = abase + 40960, sH = abase + 32768;

    int tid = threadIdx.x, warp = tid >> 5, lane = tid & 31;

    {
        const uint4* s2 = (const uint4*)g_w2s[0];
        uint4* d2p = (uint4*)(base + 32768);
        for (int t = tid; t < 512; t += 256) d2p[t] = s2[t];
        const uint4* s1 = (const uint4*)g_w1s[0];
        uint4* d1p = (uint4*)(base + 40960);
        for (int t = tid; t < 1024; t += 256) d1p[t] = s1[t];
    }

    {
        int lane2 = lane * 2;
        float wa0x=W1[lane2],       wa0y=W1[lane2+1];
        float wa1x=W1[64+lane2],    wa1y=W1[64+lane2+1];
        float wa2x=W1[128+lane2],   wa2y=W1[128+lane2+1];
        float wb0x=W1[192+lane2],   wb0y=W1[192+lane2+1];
        float wb1x=W1[256+lane2],   wb1y=W1[256+lane2+1];
        float wb2x=W1[320+lane2],   wb2y=W1[320+lane2+1];
        float wr0x=W1[384+lane2],   wr0y=W1[384+lane2+1];
        float wr1x=W1[448+lane2],   wr1y=W1[448+lane2+1];
        float wr2x=W1[512+lane2],   wr2y=W1[512+lane2+1];
        float b1x=b1[lane2], b1y=b1[lane2+1];
#pragma unroll
        for (int pp = 0; pp < 4; pp++) {
            int lp = warp * 4 + pp;
            int i = blockIdx.x * PTS + lp;
            float4 pi = g_pos4[i];
            float ax = fmaf(pi.x, wa0x, fmaf(pi.y, wa1x, fmaf(pi.z, wa2x, b1x)));
            float ay = fmaf(pi.x, wa0y, fmaf(pi.y, wa1y, fmaf(pi.z, wa2y, b1y)));
            int rowbase = lp * 8;
#pragma unroll
            for (int slot = 0; slot < 6; slot++) {
                int j = g_knn[i*8 + slot];
                float4 pj = g_pos4[j];
                float rx = pj.x - pi.x, ry = pj.y - pi.y, rz = pj.z - pi.z;
                float h0 = ax;
                h0 = fmaf(pj.x, wb0x, h0); h0 = fmaf(pj.y, wb1x, h0); h0 = fmaf(pj.z, wb2x, h0);
                h0 = fmaf(rx, wr0x, h0);   h0 = fmaf(ry, wr1x, h0);   h0 = fmaf(rz, wr2x, h0);
                float h1 = ay;
                h1 = fmaf(pj.x, wb0y, h1); h1 = fmaf(pj.y, wb1y, h1); h1 = fmaf(pj.z, wb2y, h1);
                h1 = fmaf(rx, wr0y, h1);   h1 = fmaf(ry, wr1y, h1);   h1 = fmaf(rz, wr2y, h1);
                h0 = fmaxf(h0, 0.f); h1 = fmaxf(h1, 0.f);
                uint32_t pk = pack_h2(h0, h1);
                *(uint32_t*)(AC + sw128((uint32_t)((rowbase + slot)*128 + lane2*2))) = pk;
                if (slot == 0) {
                    *(uint32_t*)(AC + sw128((uint32_t)((rowbase + 6)*128 + lane2*2))) = pk;
                    *(uint32_t*)(AC + sw128((uint32_t)((rowbase + 7)*128 + lane2*2))) = pk;
                }
            }
        }
    }
    __syncthreads();
    edge_phaseB<8, 1>(sA, sB, b2, hC, nullptr, warp, lane);
    __syncthreads();
    phaseC(sH, sW1, b1n, abot, warp, lane, PTS, blockIdx.x * PTS);
}

// ---------------- edge layers 2/3: gather fp16 a/b from abin; MODE 1=fused ab out, 2=pool ----------------
template<int K, int SLOTS, int MODE>
__global__ __launch_bounds__(256, (MODE == 2 ? 3 : 4)) void edge_mma_kernel(
    const __half* __restrict__ abin,
    const float* __restrict__ W1rel,
    const float* __restrict__ b2,
    int layer,
    int w1layer,
    const float* __restrict__ b1n,
    __half* __restrict__ abot)
{
    constexpr int PTS = 256 / SLOTS;
    constexpr int PPW = PTS / 8;
    extern __shared__ char smem_raw[];
    uint32_t su = smem_u32(smem_raw);
    uint32_t abase = (su + 127) & ~127u;
    char* base = smem_raw + (abase - su);
    char* AC = base;
    char* hC = base + 32768;                 // MODE 1: aliases W2 region
    float* poolC = (float*)(base + 40960);   // MODE 2
    uint32_t sA = abase, sB = abase + 32768, sW1 = abase + 40960, sH = abase + 32768;

    int tid = threadIdx.x, warp = tid >> 5, lane = tid & 31;

    {
        const uint4* s2 = (const uint4*)g_w2s[layer];
        uint4* d2p = (uint4*)(base + 32768);
        for (int t = tid; t < 512; t += 256) d2p[t] = s2[t];
        if (MODE == 1) {
            const uint4* s1 = (const uint4*)g_w1s[w1layer];
            uint4* d1p = (uint4*)(base + 40960);
            for (int t = tid; t < 1024; t += 256) d1p[t] = s1[t];
        }
    }

    {
        int lane2 = lane * 2;
        float u0x = W1rel[lane2],       u0y = W1rel[lane2 + 1];
        float u1x = W1rel[64 + lane2],  u1y = W1rel[64 + lane2 + 1];
        float u2x = W1rel[128 + lane2], u2y = W1rel[128 + lane2 + 1];
#pragma unroll
        for (int pp = 0; pp < PPW; pp++) {
            int lp = warp * PPW + pp;
            int i = blockIdx.x * PTS + lp;
            float2 a = __half22float2(*(const __half2*)&abin[(size_t)i*128 + lane2]);
            float4 pi = g_pos4[i];
            int rowbase = lp * SLOTS;
#pragma unroll
            for (int slot = 0; slot < K; slot++) {
                int j = g_knn[i*8 + slot];
                float4 pj = g_pos4[j];
                float2 b = __half22float2(*(const __half2*)&abin[(size_t)j*128 + 64 + lane2]);
                float rx = pj.x - pi.x, ry = pj.y - pi.y, rz = pj.z - pi.z;
                float h0 = fmaxf(fmaf(rx, u0x, fmaf(ry, u1x, fmaf(rz, u2x, a.x + b.x))), 0.f);
                float h1 = fmaxf(fmaf(rx, u0y, fmaf(ry, u1y, fmaf(rz, u2y, a.y + b.y))), 0.f);
                uint32_t pk = pack_h2(h0, h1);
                *(uint32_t*)(AC + sw128((uint32_t)((rowbase + slot)*128 + lane2*2))) = pk;
                if (slot == 0) {
#pragma unroll
                    for (int e = K; e < SLOTS; e++)
                        *(uint32_t*)(AC + sw128((uint32_t)((rowbase + e)*128 + lane2*2))) = pk;
                }
            }
        }
    }
    __syncthreads();
    edge_phaseB<SLOTS, MODE>(sA, sB, b2, hC, poolC, warp, lane);
    if (MODE == 1) {
        __syncthreads();
        phaseC(sH, sW1, b1n, abot, warp, lane, PTS, blockIdx.x * PTS);
    }
    if (MODE == 2) {
        __syncthreads();
        float* red = (float*)AC;
        int col = tid & 63, grp = tid >> 6;
        float m = 0.f;
        for (int r = grp; r < 64; r += 4) m = fmaxf(m, poolC[r*66 + col]);
        red[grp*64 + col] = m;
        __syncthreads();
        if (grp == 0) {
            m = fmaxf(fmaxf(red[col], red[64 + col]), fmaxf(red[128 + col], red[192 + col]));
            int graph = blockIdx.x >> 4;
            atomicMax(&g_pool[graph*64 + col], __float_as_uint(m));
        }
    }
}

// ---------------- regression head: out = pool @ regW + regb ----------------
__global__ __launch_bounds__(64) void head_kernel(const float* __restrict__ regW,
                                                  const float* __restrict__ regb,
                                                  float* __restrict__ out)
{
    __shared__ float hv[64];
    int g = blockIdx.x, tid = threadIdx.x;
    hv[tid] = __uint_as_float(g_pool[g*64 + tid]);
    __syncthreads();
    if (tid < 6) {
        float acc = regb[tid];
#pragma unroll
        for (int c = 0; c < 64; c++)
            acc = fmaf(hv[c], regW[c*6 + tid], acc);
        out[g*6 + tid] = acc;
    }
}

// ---------------- launch ----------------
extern "C" void kernel_launch(void* const* d_in, const int* in_sizes, int n_in,
                              void* d_out, int out_size)
{
    (void)in_sizes; (void)n_in; (void)out_size;
    const float* pos  = (const float*)d_in[1];
    const float* c1W1 = (const float*)d_in[3];
    const float* c1b1 = (const float*)d_in[4];
    const float* c1W2 = (const float*)d_in[5];
    const float* c1b2 = (const float*)d_in[6];
    const float* c2W1 = (const float*)d_in[7];
    const float* c2b1 = (const float*)d_in[8];
    const float* c2W2 = (const float*)d_in[9];
    const float* c2b2 = (const float*)d_in[10];
    const float* c3W1 = (const float*)d_in[11];
    const float* c3b1 = (const float*)d_in[12];
    const float* c3W2 = (const float*)d_in[13];
    const float* c3b2 = (const float*)d_in[14];
    const float* regW = (const float*)d_in[15];
    const float* regb = (const float*)d_in[16];
    float* out = (float*)d_out;

    __half *abA, *abB;
    cudaGetSymbolAddress((void**)&abA, g_abA);
    cudaGetSymbolAddress((void**)&abB, g_abB);
    cudaFuncSetAttribute((const void*)edge1_mma_kernel, cudaFuncAttributeMaxDynamicSharedMemorySize, EDGE_SMEM_F);
    cudaFuncSetAttribute((const void*)edge_mma_kernel<4,4,1>, cudaFuncAttributeMaxDynamicSharedMemorySize, EDGE_SMEM_F);
    cudaFuncSetAttribute((const void*)edge_mma_kernel<3,4,2>, cudaFuncAttributeMaxDynamicSharedMemorySize, EDGE_SMEM_P);

    knn_kernel<<<BGRAPH * 4, 128>>>(pos);
    wsplit_kernel<<<224, 128>>>(c1W2, c2W2, c3W2, c2W1, c3W1);   // also zeroes g_pool
    edge1_mma_kernel<<<NPTS/32, 256, EDGE_SMEM_F>>>(c1W1, c1b1, c1b2, c2b1, abA);
    edge_mma_kernel<4,4,1><<<NPTS/64, 256, EDGE_SMEM_F>>>(abA, c2W1 + 128*64, c2b2, 1, 1, c3b1, abB);
    edge_mma_kernel<3,4,2><<<NPTS/64, 256, EDGE_SMEM_P>>>(abB, c3W1 + 128*64, c3b2, 2, 0, nullptr, nullptr);
    head_kernel<<<BGRAPH, 64>>>(regW, regb, out);
}